// round 9
// baseline (speedup 1.0000x reference)
#include <cuda_runtime.h>
#include <cuda_bf16.h>
#include <cuda_fp16.h>
#include <cstdint>

// Problem constants
#define VB 4
#define PP 2048
#define DD 1280
#define HH 16
#define HD 80
#define M_ROWS (VB * PP)     // 8192
#define N_QKV  (3 * DD)      // 3840
#define QK_SCALE 0.111803398874989484f

// ---------------------------------------------------------------------------
// Scratch (static device globals — allocation-guard safe)
// ---------------------------------------------------------------------------
__device__ float g_qkv[M_ROWS * N_QKV];               // [8192, 3840] fp32
__device__ __nv_bfloat16 g_ahi[M_ROWS * DD];          // split A (hs, then attn out)
__device__ __nv_bfloat16 g_alo[M_ROWS * DD];
__device__ __nv_bfloat16 g_bhi[N_QKV * DD];           // split W^T [N,K]
__device__ __nv_bfloat16 g_blo[N_QKV * DD];
// fp16 attention operands
__device__ __align__(16) __half g_qhi2[VB * HH * PP * HD];  // [v][h][p][d], scaled
__device__ __align__(16) __half g_qlo2[VB * HH * PP * HD];
__device__ __align__(16) __half g_khi2[VB * HH * PP * HD];
__device__ __align__(16) __half g_klo2[VB * HH * PP * HD];
__device__ __align__(16) __half g_vt[VB * HH * HD * PP];    // [v][h][d][p]

// ---------------------------------------------------------------------------
// Helpers
// ---------------------------------------------------------------------------
__device__ __forceinline__ uint32_t smem_u32(const void* p) {
    uint32_t a;
    asm("{ .reg .u64 t; cvta.to.shared.u64 t, %1; cvt.u32.u64 %0, t; }" : "=r"(a) : "l"(p));
    return a;
}

#define CP_ASYNC16(dst, src) \
    asm volatile("cp.async.cg.shared.global [%0], [%1], 16;" :: "r"(dst), "l"(src))
#define CP_COMMIT() asm volatile("cp.async.commit_group;" ::: "memory")
#define CP_WAIT(n)  asm volatile("cp.async.wait_group %0;" :: "n"(n) : "memory")

__device__ __forceinline__ void ldsm_x4(uint32_t& r0, uint32_t& r1, uint32_t& r2, uint32_t& r3,
                                        uint32_t addr) {
    asm volatile("ldmatrix.sync.aligned.m8n8.x4.shared.b16 {%0,%1,%2,%3}, [%4];"
                 : "=r"(r0), "=r"(r1), "=r"(r2), "=r"(r3) : "r"(addr));
}
__device__ __forceinline__ void ldsm_x2(uint32_t& r0, uint32_t& r1, uint32_t addr) {
    asm volatile("ldmatrix.sync.aligned.m8n8.x2.shared.b16 {%0,%1}, [%2];"
                 : "=r"(r0), "=r"(r1) : "r"(addr));
}
__device__ __forceinline__ void mma16816bf(float* c, const uint32_t* a, const uint32_t* b) {
    asm volatile("mma.sync.aligned.m16n8k16.row.col.f32.bf16.bf16.f32 "
                 "{%0,%1,%2,%3}, {%4,%5,%6,%7}, {%8,%9}, {%0,%1,%2,%3};"
                 : "+f"(c[0]), "+f"(c[1]), "+f"(c[2]), "+f"(c[3])
                 : "r"(a[0]), "r"(a[1]), "r"(a[2]), "r"(a[3]), "r"(b[0]), "r"(b[1]));
}
__device__ __forceinline__ void mma16816h(float* c, const uint32_t* a, const uint32_t* b) {
    asm volatile("mma.sync.aligned.m16n8k16.row.col.f32.f16.f16.f32 "
                 "{%0,%1,%2,%3}, {%4,%5,%6,%7}, {%8,%9}, {%0,%1,%2,%3};"
                 : "+f"(c[0]), "+f"(c[1]), "+f"(c[2]), "+f"(c[3])
                 : "r"(a[0]), "r"(a[1]), "r"(a[2]), "r"(a[3]), "r"(b[0]), "r"(b[1]));
}

__device__ __forceinline__ uint32_t swz(uint32_t x)   { return x ^ ((x >> 3) & 0x70u); }
__device__ __forceinline__ uint32_t swz64(uint32_t x) { return x ^ ((x >> 2) & 0x30u); }

// ---------------------------------------------------------------------------
// Split fp32 -> hi/lo bf16
// ---------------------------------------------------------------------------
__global__ __launch_bounds__(256) void split_kernel(
    const float* __restrict__ x, __nv_bfloat16* __restrict__ hi,
    __nv_bfloat16* __restrict__ lo, int n)
{
    int i = (blockIdx.x * 256 + threadIdx.x) * 4;
    if (i >= n) return;
    float4 v = *(const float4*)(x + i);
    __nv_bfloat16 h0 = __float2bfloat16(v.x);
    __nv_bfloat16 h1 = __float2bfloat16(v.y);
    __nv_bfloat16 h2 = __float2bfloat16(v.z);
    __nv_bfloat16 h3 = __float2bfloat16(v.w);
    ((__nv_bfloat162*)(hi + i))[0] = __nv_bfloat162(h0, h1);
    ((__nv_bfloat162*)(hi + i))[1] = __nv_bfloat162(h2, h3);
    __nv_bfloat16 l0 = __float2bfloat16(v.x - __bfloat162float(h0));
    __nv_bfloat16 l1 = __float2bfloat16(v.y - __bfloat162float(h1));
    __nv_bfloat16 l2 = __float2bfloat16(v.z - __bfloat162float(h2));
    __nv_bfloat16 l3 = __float2bfloat16(v.w - __bfloat162float(h3));
    ((__nv_bfloat162*)(lo + i))[0] = __nv_bfloat162(l0, l1);
    ((__nv_bfloat162*)(lo + i))[1] = __nv_bfloat162(l2, l3);
}

// ---------------------------------------------------------------------------
// Transpose + split: w [K,N] fp32 -> thi/tlo [N,K] bf16
// ---------------------------------------------------------------------------
__global__ __launch_bounds__(256) void transpose_split(
    const float* __restrict__ w, __nv_bfloat16* __restrict__ thi,
    __nv_bfloat16* __restrict__ tlo, int K, int N)
{
    __shared__ float t[32][33];
    int n0 = blockIdx.x * 32, k0 = blockIdx.y * 32;
    int tx = threadIdx.x & 31, ty = threadIdx.x >> 5;
    #pragma unroll
    for (int r = ty; r < 32; r += 8)
        t[r][tx] = w[(size_t)(k0 + r) * N + n0 + tx];
    __syncthreads();
    #pragma unroll
    for (int r = ty; r < 32; r += 8) {
        float v = t[tx][r];
        __nv_bfloat16 h = __float2bfloat16(v);
        size_t o = (size_t)(n0 + r) * K + k0 + tx;
        thi[o] = h;
        tlo[o] = __float2bfloat16(v - __bfloat162float(h));
    }
}

// ---------------------------------------------------------------------------
// mma.sync split-bf16 GEMM: C = A @ B^T + bias
// CTA 128x128, K-chunk 32 (64B rows, SW64), double-buffered, 2 CTAs/SM.
// ---------------------------------------------------------------------------
#define GTM 128
#define GTN 128
#define GKC 32
#define MAT_B 8192u              // 128 rows * 64 bytes
#define STAGE_B (4u * MAT_B)     // Ahi | Alo | Bhi | Blo = 32 KB
#define GEMM_SMEM (2 * STAGE_B)  // 65536 bytes

__device__ __forceinline__ void load_chunk4(
    uint32_t sb, int buf,
    const __nv_bfloat16* a0, const __nv_bfloat16* a1,
    const __nv_bfloat16* b0, const __nv_bfloat16* b1,
    int k0, int tid, int K)
{
    const __nv_bfloat16* srcs[4] = {a0 + k0, a1 + k0, b0 + k0, b1 + k0};
    uint32_t stage = sb + (uint32_t)buf * STAGE_B;
    #pragma unroll
    for (int mat = 0; mat < 4; mat++) {
        uint32_t tbase = stage + (uint32_t)mat * MAT_B;
        const __nv_bfloat16* s = srcs[mat];
        #pragma unroll
        for (int i = 0; i < 2; i++) {
            int g = tid + i * 256;          // granule 0..511
            int row = g >> 2;
            int c16 = g & 3;
            uint32_t boff = (uint32_t)(row * 64 + c16 * 16);
            CP_ASYNC16(tbase + swz64(boff), s + (size_t)row * K + c16 * 8);
        }
    }
}

__global__ __launch_bounds__(256, 2) void gemm_mma_bf16x3(
    const __nv_bfloat16* __restrict__ Ahi, const __nv_bfloat16* __restrict__ Alo,
    const __nv_bfloat16* __restrict__ Bhi, const __nv_bfloat16* __restrict__ Blo,
    const float* __restrict__ bias, float* __restrict__ C, int K, int N)
{
    extern __shared__ char smem[];
    uint32_t sb = smem_u32(smem);
    const int tid = threadIdx.x;
    const int lane = tid & 31;
    const int wid = tid >> 5;
    const int wm = wid >> 2;
    const int wn = wid & 3;
    const int m0 = blockIdx.y * GTM;
    const int n0 = blockIdx.x * GTN;

    const __nv_bfloat16* a0 = Ahi + (size_t)m0 * K;
    const __nv_bfloat16* a1 = Alo + (size_t)m0 * K;
    const __nv_bfloat16* b0 = Bhi + (size_t)n0 * K;
    const __nv_bfloat16* b1 = Blo + (size_t)n0 * K;

    float acc[4][4][4];
    #pragma unroll
    for (int i = 0; i < 4; i++)
        #pragma unroll
        for (int j = 0; j < 4; j++)
            #pragma unroll
            for (int t = 0; t < 4; t++) acc[i][j][t] = 0.f;

    const int a_row_l = (lane & 7) + ((lane >> 3) & 1) * 8;
    const int a_c16_l = (lane >> 4);
    const int b_row_l = (lane & 7);
    const int b_c16_l = ((lane >> 3) & 1);

    const int nch = K / GKC;   // 40

    load_chunk4(sb, 0, a0, a1, b0, b1, 0, tid, K);
    CP_COMMIT();

    for (int it = 0; it < nch; it++) {
        const int b = it & 1;
        if (it + 1 < nch) {
            load_chunk4(sb, b ^ 1, a0, a1, b0, b1, (it + 1) * GKC, tid, K);
            CP_COMMIT();
            CP_WAIT(1);
        } else {
            CP_WAIT(0);
        }
        __syncthreads();

        uint32_t stage = sb + (uint32_t)b * STAGE_B;
        uint32_t sAhi = stage;
        uint32_t sAlo = stage + MAT_B;
        uint32_t sBhi = stage + 2 * MAT_B;
        uint32_t sBlo = stage + 3 * MAT_B;

        #pragma unroll
        for (int ks = 0; ks < 2; ks++) {   // 2 x k16 per 32-chunk
            // B fragments first (16 regs live)
            uint32_t bhi[4][2], blo[4][2];
            #pragma unroll
            for (int nt = 0; nt < 4; nt++) {
                uint32_t boff = (uint32_t)((wn * 32 + nt * 8 + b_row_l) * 64 +
                                           (ks * 2 + b_c16_l) * 16);
                uint32_t so = swz64(boff);
                ldsm_x2(bhi[nt][0], bhi[nt][1], sBhi + so);
                ldsm_x2(blo[nt][0], blo[nt][1], sBlo + so);
            }
            // A fragments per-mt (8 regs live at a time)
            #pragma unroll
            for (int mt = 0; mt < 4; mt++) {
                uint32_t boff = (uint32_t)((wm * 64 + mt * 16 + a_row_l) * 64 +
                                           (ks * 2 + a_c16_l) * 16);
                uint32_t so = swz64(boff);
                uint32_t ahi[4], alo[4];
                ldsm_x4(ahi[0], ahi[1], ahi[2], ahi[3], sAhi + so);
                ldsm_x4(alo[0], alo[1], alo[2], alo[3], sAlo + so);
                #pragma unroll
                for (int nt = 0; nt < 4; nt++) {
                    mma16816bf(acc[mt][nt], ahi, bhi[nt]);
                    mma16816bf(acc[mt][nt], ahi, blo[nt]);
                    mma16816bf(acc[mt][nt], alo, bhi[nt]);
                }
            }
        }
        __syncthreads();
    }

    const int r_base = m0 + wm * 64 + (lane >> 2);
    const int c_base = n0 + wn * 32 + (lane & 3) * 2;
    #pragma unroll
    for (int mt = 0; mt < 4; mt++) {
        #pragma unroll
        for (int nt = 0; nt < 4; nt++) {
            int col = c_base + nt * 8;
            float bx = bias[col], by = bias[col + 1];
            int r0 = r_base + mt * 16;
            float2 v0 = {acc[mt][nt][0] + bx, acc[mt][nt][1] + by};
            float2 v1 = {acc[mt][nt][2] + bx, acc[mt][nt][3] + by};
            *(float2*)(C + (size_t)r0 * N + col) = v0;
            *(float2*)(C + (size_t)(r0 + 8) * N + col) = v1;
        }
    }
}

// ---------------------------------------------------------------------------
// RoPE + split-fp16 scatter for Q (scaled) and K: [v][h][p][d]
// ---------------------------------------------------------------------------
__global__ __launch_bounds__(256) void rope_scatter(
    const float* __restrict__ qkv, const float* __restrict__ rope)
{
    int idx = blockIdx.x * 256 + threadIdx.x;
    if (idx >= VB * PP * HH * 40) return;
    int d = idx % 40;
    int h = (idx / 40) % HH;
    int p = (idx / (40 * HH)) % PP;
    int v = idx / (40 * HH * PP);

    size_t row = (size_t)v * PP + p;
    const float* qr = qkv + row * N_QKV + h * HD;
    const float* kr = qr + DD;
    const float* rp = rope + row * (2 * HD);

    float c0 = rp[d],      c1 = rp[d + 40];
    float s0 = rp[HD + d], s1 = rp[HD + d + 40];
    float q0 = qr[d], q1 = qr[d + 40];
    float k0 = kr[d], k1 = kr[d + 40];

    float qa = (q0 * c0 - q1 * s0) * QK_SCALE;
    float qb = (q1 * c1 + q0 * s1) * QK_SCALE;
    float ka = k0 * c0 - k1 * s0;
    float kb = k1 * c1 + k0 * s1;

    size_t ob = (((size_t)v * HH + h) * PP + p) * HD;
    __half hqa = __float2half_rn(qa);
    __half hqb = __float2half_rn(qb);
    __half hka = __float2half_rn(ka);
    __half hkb = __float2half_rn(kb);
    g_qhi2[ob + d]      = hqa;
    g_qhi2[ob + d + 40] = hqb;
    g_qlo2[ob + d]      = __float2half_rn(qa - __half2float(hqa));
    g_qlo2[ob + d + 40] = __float2half_rn(qb - __half2float(hqb));
    g_khi2[ob + d]      = hka;
    g_khi2[ob + d + 40] = hkb;
    g_klo2[ob + d]      = __float2half_rn(ka - __half2float(hka));
    g_klo2[ob + d + 40] = __float2half_rn(kb - __half2float(hkb));
}

// ---------------------------------------------------------------------------
// V transpose: g_qkv V-part [v][p][h*80+d] -> g_vt [v][h][d][p] fp16
// ---------------------------------------------------------------------------
__global__ __launch_bounds__(256) void v_transpose(const float* __restrict__ qkv)
{
    __shared__ float t[32][33];
    int vh = blockIdx.z;
    int v = vh >> 4, h = vh & 15;
    int p0 = blockIdx.x * 32;
    int d0 = blockIdx.y * 32;
    int tx = threadIdx.x & 31, ty = threadIdx.x >> 5;
    #pragma unroll
    for (int r = ty; r < 32; r += 8) {
        int d = d0 + tx;
        if (d < HD)
            t[r][tx] = qkv[((size_t)v * PP + p0 + r) * N_QKV + 2 * DD + h * HD + d];
    }
    __syncthreads();
    #pragma unroll
    for (int r = ty; r < 32; r += 8) {
        int d = d0 + r;
        if (d < HD)
            g_vt[((size_t)vh * HD + d) * PP + p0 + tx] = __float2half_rn(t[tx][r]);
    }
}

// ---------------------------------------------------------------------------
// Tensor-core flash attention (epilogue now writes split-bf16 directly)
// ---------------------------------------------------------------------------
#define SQ 88
#define SV 72
#define ATTN_SMEM 113152

__global__ __launch_bounds__(256) void attn_mma(const int* __restrict__ valid_lens)
{
    extern __shared__ char smem[];
    uint32_t sb = smem_u32(smem);
    const int tid = threadIdx.x;
    const int lane = tid & 31;
    const int wq = tid >> 5;
    const int q0 = blockIdx.x * 128;
    const int h = blockIdx.y;
    const int v = blockIdx.z;
    int L = valid_lens[v];
    if (L < 1) L = 1;

    const size_t hb = ((size_t)(v * HH + h)) * PP * HD;
    const __half* qhi = g_qhi2 + hb + (size_t)q0 * HD;
    const __half* qlo = g_qlo2 + hb + (size_t)q0 * HD;
    const __half* khi = g_khi2 + hb;
    const __half* klo = g_klo2 + hb;
    const __half* vtp = g_vt + hb;   // [80][2048]

    const uint32_t bQHI = sb;
    const uint32_t bQLO = sb + 22528u;
    const uint32_t bKHI = sb + 45056u;
    const uint32_t bKLO = sb + 67584u;
    const uint32_t bVT  = sb + 90112u;

    for (int i = tid; i < 1280; i += 256) {
        int r = i / 10, g = i % 10;
        uint32_t off = (uint32_t)(r * SQ + g * 8) * 2;
        CP_ASYNC16(bQHI + off, qhi + (size_t)r * HD + g * 8);
        CP_ASYNC16(bQLO + off, qlo + (size_t)r * HD + g * 8);
    }
    {
        for (int i = tid; i < 640; i += 256) {
            int r = i / 10, g = i % 10;
            uint32_t off = (uint32_t)(r * SQ + g * 8) * 2;
            CP_ASYNC16(bKHI + off, khi + (size_t)r * HD + g * 8);
            CP_ASYNC16(bKLO + off, klo + (size_t)r * HD + g * 8);
        }
        for (int i = tid; i < 640; i += 256) {
            int d = i / 8, g = i % 8;
            CP_ASYNC16(bVT + (uint32_t)(d * SV + g * 8) * 2, vtp + (size_t)d * PP + g * 8);
        }
    }
    CP_COMMIT();

    float m_lo = -1e30f, m_hi = -1e30f, l_lo = 0.f, l_hi = 0.f;
    float o[10][4];
    #pragma unroll
    for (int i = 0; i < 10; i++)
        #pragma unroll
        for (int j = 0; j < 4; j++) o[i][j] = 0.f;

    const int a_row = wq * 16 + (lane & 7) + ((lane >> 3) & 1) * 8;
    const int a_c16 = (lane >> 4);
    const int b_row = (lane & 7);
    const int b_c16 = (lane >> 3) & 1;
    const int gc = lane & 3;

    const int nkt = (L + 63) >> 6;
    for (int kt = 0; kt < nkt; kt++) {
        const int b = kt & 1;
        if (kt + 1 < nkt) {
            const int kn = (kt + 1) * 64;
            const uint32_t kh = bKHI + (uint32_t)(b ^ 1) * 11264u;
            const uint32_t kl = bKLO + (uint32_t)(b ^ 1) * 11264u;
            const uint32_t vb = bVT + (uint32_t)(b ^ 1) * 11520u;
            for (int i = tid; i < 640; i += 256) {
                int r = i / 10, g = i % 10;
                uint32_t off = (uint32_t)(r * SQ + g * 8) * 2;
                CP_ASYNC16(kh + off, khi + (size_t)(kn + r) * HD + g * 8);
                CP_ASYNC16(kl + off, klo + (size_t)(kn + r) * HD + g * 8);
            }
            for (int i = tid; i < 640; i += 256) {
                int d = i / 8, g = i % 8;
                CP_ASYNC16(vb + (uint32_t)(d * SV + g * 8) * 2,
                           vtp + (size_t)d * PP + kn + g * 8);
            }
            CP_COMMIT();
            CP_WAIT(1);
        } else {
            CP_WAIT(0);
        }
        __syncthreads();

        const uint32_t khb = bKHI + (uint32_t)b * 11264u;
        const uint32_t klb = bKLO + (uint32_t)b * 11264u;
        const uint32_t vtb = bVT + (uint32_t)b * 11520u;

        float s[8][4];
        #pragma unroll
        for (int nt = 0; nt < 8; nt++)
            #pragma unroll
            for (int j = 0; j < 4; j++) s[nt][j] = 0.f;

        #pragma unroll
        for (int kc = 0; kc < 5; kc++) {
            uint32_t qh[4], ql[4];
            uint32_t qoff = (uint32_t)(a_row * SQ + kc * 16 + a_c16 * 8) * 2;
            ldsm_x4(qh[0], qh[1], qh[2], qh[3], bQHI + qoff);
            ldsm_x4(ql[0], ql[1], ql[2], ql[3], bQLO + qoff);
            #pragma unroll
            for (int nt = 0; nt < 8; nt++) {
                uint32_t koff = (uint32_t)((nt * 8 + b_row) * SQ + kc * 16 + b_c16 * 8) * 2;
                uint32_t kh[2], kl[2];
                ldsm_x2(kh[0], kh[1], khb + koff);
                ldsm_x2(kl[0], kl[1], klb + koff);
                mma16816h(s[nt], qh, kh);
                mma16816h(s[nt], qh, kl);
                mma16816h(s[nt], ql, kh);
            }
        }

        const int k0 = kt * 64;
        if (k0 + 64 > L) {
            #pragma unroll
            for (int nt = 0; nt < 8; nt++) {
                int kb0 = k0 + nt * 8 + gc * 2;
                if (kb0 >= L)     { s[nt][0] = -1e30f; s[nt][2] = -1e30f; }
                if (kb0 + 1 >= L) { s[nt][1] = -1e30f; s[nt][3] = -1e30f; }
            }
        }

        float mt_lo = -1e30f, mt_hi = -1e30f;
        #pragma unroll
        for (int nt = 0; nt < 8; nt++) {
            mt_lo = fmaxf(mt_lo, fmaxf(s[nt][0], s[nt][1]));
            mt_hi = fmaxf(mt_hi, fmaxf(s[nt][2], s[nt][3]));
        }
        mt_lo = fmaxf(mt_lo, __shfl_xor_sync(0xffffffffu, mt_lo, 1));
        mt_lo = fmaxf(mt_lo, __shfl_xor_sync(0xffffffffu, mt_lo, 2));
        mt_hi = fmaxf(mt_hi, __shfl_xor_sync(0xffffffffu, mt_hi, 1));
        mt_hi = fmaxf(mt_hi, __shfl_xor_sync(0xffffffffu, mt_hi, 2));

        float mn_lo = fmaxf(m_lo, mt_lo), mn_hi = fmaxf(m_hi, mt_hi);
        float al = __expf(m_lo - mn_lo), ah = __expf(m_hi - mn_hi);
        m_lo = mn_lo; m_hi = mn_hi;

        float sum_lo = 0.f, sum_hi = 0.f;
        #pragma unroll
        for (int nt = 0; nt < 8; nt++) {
            s[nt][0] = __expf(s[nt][0] - mn_lo);
            s[nt][1] = __expf(s[nt][1] - mn_lo);
            s[nt][2] = __expf(s[nt][2] - mn_hi);
            s[nt][3] = __expf(s[nt][3] - mn_hi);
            sum_lo += s[nt][0] + s[nt][1];
            sum_hi += s[nt][2] + s[nt][3];
        }
        sum_lo += __shfl_xor_sync(0xffffffffu, sum_lo, 1);
        sum_lo += __shfl_xor_sync(0xffffffffu, sum_lo, 2);
        sum_hi += __shfl_xor_sync(0xffffffffu, sum_hi, 1);
        sum_hi += __shfl_xor_sync(0xffffffffu, sum_hi, 2);
        l_lo = l_lo * al + sum_lo;
        l_hi = l_hi * ah + sum_hi;

        #pragma unroll
        for (int nt = 0; nt < 10; nt++) {
            o[nt][0] *= al; o[nt][1] *= al;
            o[nt][2] *= ah; o[nt][3] *= ah;
        }

        uint32_t pa[4][4];
        #pragma unroll
        for (int kc = 0; kc < 4; kc++) {
            __half2 t0 = __floats2half2_rn(s[2 * kc][0], s[2 * kc][1]);
            __half2 t1 = __floats2half2_rn(s[2 * kc][2], s[2 * kc][3]);
            __half2 t2 = __floats2half2_rn(s[2 * kc + 1][0], s[2 * kc + 1][1]);
            __half2 t3 = __floats2half2_rn(s[2 * kc + 1][2], s[2 * kc + 1][3]);
            pa[kc][0] = *(uint32_t*)&t0;
            pa[kc][1] = *(uint32_t*)&t1;
            pa[kc][2] = *(uint32_t*)&t2;
            pa[kc][3] = *(uint32_t*)&t3;
        }

        #pragma unroll
        for (int nt = 0; nt < 10; nt++) {
            #pragma unroll
            for (int kc = 0; kc < 4; kc++) {
                uint32_t voff = (uint32_t)((nt * 8 + b_row) * SV + kc * 16 + b_c16 * 8) * 2;
                uint32_t vv[2];
                ldsm_x2(vv[0], vv[1], vtb + voff);
                mma16816h(o[nt], pa[kc], vv);
            }
        }
        __syncthreads();
    }

    // Epilogue: write split bf16 hi/lo directly (fused split for proj GEMM)
    float inv_lo = 1.f / l_lo, inv_hi = 1.f / l_hi;
    int row_lo = q0 + wq * 16 + (lane >> 2);
    #pragma unroll
    for (int nt = 0; nt < 10; nt++) {
        int col = h * HD + nt * 8 + gc * 2;
        size_t off0 = ((size_t)v * PP + row_lo) * DD + col;
        size_t off1 = ((size_t)v * PP + row_lo + 8) * DD + col;
        float v00 = o[nt][0] * inv_lo, v01 = o[nt][1] * inv_lo;
        float v10 = o[nt][2] * inv_hi, v11 = o[nt][3] * inv_hi;
        __nv_bfloat16 h00 = __float2bfloat16(v00);
        __nv_bfloat16 h01 = __float2bfloat16(v01);
        __nv_bfloat16 h10 = __float2bfloat16(v10);
        __nv_bfloat16 h11 = __float2bfloat16(v11);
        *(__nv_bfloat162*)(g_ahi + off0) = __nv_bfloat162(h00, h01);
        *(__nv_bfloat162*)(g_ahi + off1) = __nv_bfloat162(h10, h11);
        *(__nv_bfloat162*)(g_alo + off0) = __nv_bfloat162(
            __float2bfloat16(v00 - __bfloat162float(h00)),
            __float2bfloat16(v01 - __bfloat162float(h01)));
        *(__nv_bfloat162*)(g_alo + off1) = __nv_bfloat162(
            __float2bfloat16(v10 - __bfloat162float(h10)),
            __float2bfloat16(v11 - __bfloat162float(h11)));
    }
}

// ---------------------------------------------------------------------------
// Launch
// ---------------------------------------------------------------------------
extern "C" void kernel_launch(void* const* d_in, const int* in_sizes, int n_in,
                              void* d_out, int out_size)
{
    const float* hs    = (const float*)d_in[0];
    const float* rope  = (const float*)d_in[1];
    const int*   vlens = (const int*)d_in[2];
    const float* wqkv  = (const float*)d_in[3];
    const float* bqkv  = (const float*)d_in[4];
    const float* wproj = (const float*)d_in[5];
    const float* bproj = (const float*)d_in[6];
    float* out = (float*)d_out;

    float* p_qkv;
    __nv_bfloat16 *p_ahi, *p_alo, *p_bhi, *p_blo;
    cudaGetSymbolAddress((void**)&p_qkv, g_qkv);
    cudaGetSymbolAddress((void**)&p_ahi, g_ahi);
    cudaGetSymbolAddress((void**)&p_alo, g_alo);
    cudaGetSymbolAddress((void**)&p_bhi, g_bhi);
    cudaGetSymbolAddress((void**)&p_blo, g_blo);

    cudaFuncSetAttribute(gemm_mma_bf16x3,
                         cudaFuncAttributeMaxDynamicSharedMemorySize, GEMM_SMEM);
    cudaFuncSetAttribute(attn_mma,
                         cudaFuncAttributeMaxDynamicSharedMemorySize, ATTN_SMEM);

    // 1) Split hidden states, transpose+split W_qkv
    {
        int n = M_ROWS * DD;
        split_kernel<<<(n / 4 + 255) / 256, 256>>>(hs, p_ahi, p_alo, n);
        transpose_split<<<dim3(N_QKV / 32, DD / 32), 256>>>(wqkv, p_bhi, p_blo, DD, N_QKV);
    }

    // 2) QKV GEMM
    gemm_mma_bf16x3<<<dim3(N_QKV / GTN, M_ROWS / GTM), 256, GEMM_SMEM>>>(
        p_ahi, p_alo, p_bhi, p_blo, bqkv, p_qkv, DD, N_QKV);

    // 3) RoPE (split fp16 Q/K) + V transpose (fp16)
    {
        int total = VB * PP * HH * 40;
        rope_scatter<<<(total + 255) / 256, 256>>>(p_qkv, rope);
        v_transpose<<<dim3(PP / 32, 3, VB * HH), 256>>>(p_qkv);
    }

    // 4) Tensor-core flash attention (writes split bf16 directly)
    attn_mma<<<dim3(PP / 128, HH, VB), 256, ATTN_SMEM>>>(vlens);

    // 5) Transpose+split W_proj (g_bhi/g_blo free after QKV GEMM)
    transpose_split<<<dim3(DD / 32, DD / 32), 256>>>(wproj, p_bhi, p_blo, DD, DD);

    // 6) Output projection
    gemm_mma_bf16x3<<<dim3(DD / GTN, M_ROWS / GTM), 256, GEMM_SMEM>>>(
        p_ahi, p_alo, p_bhi, p_blo, bproj, out, DD, DD);
}

// round 10
// speedup vs baseline: 1.0618x; 1.0618x over previous
#include <cuda_runtime.h>
#include <cuda_bf16.h>
#include <cuda_fp16.h>
#include <cstdint>

// Problem constants
#define VB 4
#define PP 2048
#define DD 1280
#define HH 16
#define HD 80
#define M_ROWS (VB * PP)     // 8192
#define N_QKV  (3 * DD)      // 3840
#define QK_SCALE 0.111803398874989484f

// ---------------------------------------------------------------------------
// Scratch (static device globals — allocation-guard safe)
// ---------------------------------------------------------------------------
__device__ float g_qkv[M_ROWS * N_QKV];               // [8192, 3840] fp32
__device__ __nv_bfloat16 g_ahi[M_ROWS * DD];          // split A (hs, then attn out)
__device__ __nv_bfloat16 g_alo[M_ROWS * DD];
__device__ __nv_bfloat16 g_bhi[N_QKV * DD];           // split W^T [N,K]
__device__ __nv_bfloat16 g_blo[N_QKV * DD];
// fp16 attention operands
__device__ __align__(16) __half g_qhi2[VB * HH * PP * HD];  // [v][h][p][d], scaled
__device__ __align__(16) __half g_qlo2[VB * HH * PP * HD];
__device__ __align__(16) __half g_khi2[VB * HH * PP * HD];
__device__ __align__(16) __half g_klo2[VB * HH * PP * HD];
__device__ __align__(16) __half g_vt[VB * HH * HD * PP];    // [v][h][d][p]

// ---------------------------------------------------------------------------
// Helpers
// ---------------------------------------------------------------------------
__device__ __forceinline__ uint32_t smem_u32(const void* p) {
    uint32_t a;
    asm("{ .reg .u64 t; cvta.to.shared.u64 t, %1; cvt.u32.u64 %0, t; }" : "=r"(a) : "l"(p));
    return a;
}

#define CP_ASYNC16(dst, src) \
    asm volatile("cp.async.cg.shared.global [%0], [%1], 16;" :: "r"(dst), "l"(src))
#define CP_COMMIT() asm volatile("cp.async.commit_group;" ::: "memory")
#define CP_WAIT(n)  asm volatile("cp.async.wait_group %0;" :: "n"(n) : "memory")

__device__ __forceinline__ void ldsm_x4(uint32_t& r0, uint32_t& r1, uint32_t& r2, uint32_t& r3,
                                        uint32_t addr) {
    asm volatile("ldmatrix.sync.aligned.m8n8.x4.shared.b16 {%0,%1,%2,%3}, [%4];"
                 : "=r"(r0), "=r"(r1), "=r"(r2), "=r"(r3) : "r"(addr));
}
__device__ __forceinline__ void ldsm_x2(uint32_t& r0, uint32_t& r1, uint32_t addr) {
    asm volatile("ldmatrix.sync.aligned.m8n8.x2.shared.b16 {%0,%1}, [%2];"
                 : "=r"(r0), "=r"(r1) : "r"(addr));
}
__device__ __forceinline__ void mma16816bf(float* c, const uint32_t* a, const uint32_t* b) {
    asm volatile("mma.sync.aligned.m16n8k16.row.col.f32.bf16.bf16.f32 "
                 "{%0,%1,%2,%3}, {%4,%5,%6,%7}, {%8,%9}, {%0,%1,%2,%3};"
                 : "+f"(c[0]), "+f"(c[1]), "+f"(c[2]), "+f"(c[3])
                 : "r"(a[0]), "r"(a[1]), "r"(a[2]), "r"(a[3]), "r"(b[0]), "r"(b[1]));
}
__device__ __forceinline__ void mma16816h(float* c, const uint32_t* a, const uint32_t* b) {
    asm volatile("mma.sync.aligned.m16n8k16.row.col.f32.f16.f16.f32 "
                 "{%0,%1,%2,%3}, {%4,%5,%6,%7}, {%8,%9}, {%0,%1,%2,%3};"
                 : "+f"(c[0]), "+f"(c[1]), "+f"(c[2]), "+f"(c[3])
                 : "r"(a[0]), "r"(a[1]), "r"(a[2]), "r"(a[3]), "r"(b[0]), "r"(b[1]));
}

__device__ __forceinline__ uint32_t swz(uint32_t x) { return x ^ ((x >> 3) & 0x70u); }

// ---------------------------------------------------------------------------
// Split fp32 -> hi/lo bf16
// ---------------------------------------------------------------------------
__global__ __launch_bounds__(256) void split_kernel(
    const float* __restrict__ x, __nv_bfloat16* __restrict__ hi,
    __nv_bfloat16* __restrict__ lo, int n)
{
    int i = (blockIdx.x * 256 + threadIdx.x) * 4;
    if (i >= n) return;
    float4 v = *(const float4*)(x + i);
    __nv_bfloat16 h0 = __float2bfloat16(v.x);
    __nv_bfloat16 h1 = __float2bfloat16(v.y);
    __nv_bfloat16 h2 = __float2bfloat16(v.z);
    __nv_bfloat16 h3 = __float2bfloat16(v.w);
    ((__nv_bfloat162*)(hi + i))[0] = __nv_bfloat162(h0, h1);
    ((__nv_bfloat162*)(hi + i))[1] = __nv_bfloat162(h2, h3);
    __nv_bfloat16 l0 = __float2bfloat16(v.x - __bfloat162float(h0));
    __nv_bfloat16 l1 = __float2bfloat16(v.y - __bfloat162float(h1));
    __nv_bfloat16 l2 = __float2bfloat16(v.z - __bfloat162float(h2));
    __nv_bfloat16 l3 = __float2bfloat16(v.w - __bfloat162float(h3));
    ((__nv_bfloat162*)(lo + i))[0] = __nv_bfloat162(l0, l1);
    ((__nv_bfloat162*)(lo + i))[1] = __nv_bfloat162(l2, l3);
}

// ---------------------------------------------------------------------------
// Transpose + split: w [K,N] fp32 -> thi/tlo [N,K] bf16
// ---------------------------------------------------------------------------
__global__ __launch_bounds__(256) void transpose_split(
    const float* __restrict__ w, __nv_bfloat16* __restrict__ thi,
    __nv_bfloat16* __restrict__ tlo, int K, int N)
{
    __shared__ float t[32][33];
    int n0 = blockIdx.x * 32, k0 = blockIdx.y * 32;
    int tx = threadIdx.x & 31, ty = threadIdx.x >> 5;
    #pragma unroll
    for (int r = ty; r < 32; r += 8)
        t[r][tx] = w[(size_t)(k0 + r) * N + n0 + tx];
    __syncthreads();
    #pragma unroll
    for (int r = ty; r < 32; r += 8) {
        float v = t[tx][r];
        __nv_bfloat16 h = __float2bfloat16(v);
        size_t o = (size_t)(n0 + r) * K + k0 + tx;
        thi[o] = h;
        tlo[o] = __float2bfloat16(v - __bfloat162float(h));
    }
}

// ---------------------------------------------------------------------------
// mma.sync split-bf16 GEMM: C = A @ B^T + bias
// CTA 128x128, K-chunk 64 (SW128), 3-stage cp.async pipeline.
// ---------------------------------------------------------------------------
#define GTM 128
#define GTN 128
#define GKC 64
#define MAT_B 16384u
#define STAGE_B (4u * MAT_B)      // 64 KB
#define GEMM_SMEM (3 * STAGE_B)   // 196608 bytes (3 stages)

__device__ __forceinline__ void load_chunk4(
    uint32_t sb, int buf,
    const __nv_bfloat16* a0, const __nv_bfloat16* a1,
    const __nv_bfloat16* b0, const __nv_bfloat16* b1,
    int k0, int tid, int K)
{
    const __nv_bfloat16* srcs[4] = {a0 + k0, a1 + k0, b0 + k0, b1 + k0};
    uint32_t stage = sb + (uint32_t)buf * STAGE_B;
    #pragma unroll
    for (int mat = 0; mat < 4; mat++) {
        uint32_t tbase = stage + (uint32_t)mat * MAT_B;
        const __nv_bfloat16* s = srcs[mat];
        #pragma unroll
        for (int i = 0; i < 4; i++) {
            int g = tid + i * 256;
            int row = g >> 3;
            int c16 = g & 7;
            uint32_t boff = (uint32_t)(row * 128 + c16 * 16);
            CP_ASYNC16(tbase + swz(boff), s + (size_t)row * K + c16 * 8);
        }
    }
}

__global__ __launch_bounds__(256) void gemm_mma_bf16x3(
    const __nv_bfloat16* __restrict__ Ahi, const __nv_bfloat16* __restrict__ Alo,
    const __nv_bfloat16* __restrict__ Bhi, const __nv_bfloat16* __restrict__ Blo,
    const float* __restrict__ bias, float* __restrict__ C, int K, int N)
{
    extern __shared__ char smem[];
    uint32_t sb = smem_u32(smem);
    const int tid = threadIdx.x;
    const int lane = tid & 31;
    const int wid = tid >> 5;
    const int wm = wid >> 2;
    const int wn = wid & 3;
    const int m0 = blockIdx.y * GTM;
    const int n0 = blockIdx.x * GTN;

    const __nv_bfloat16* a0 = Ahi + (size_t)m0 * K;
    const __nv_bfloat16* a1 = Alo + (size_t)m0 * K;
    const __nv_bfloat16* b0 = Bhi + (size_t)n0 * K;
    const __nv_bfloat16* b1 = Blo + (size_t)n0 * K;

    float acc[4][4][4];
    #pragma unroll
    for (int i = 0; i < 4; i++)
        #pragma unroll
        for (int j = 0; j < 4; j++)
            #pragma unroll
            for (int t = 0; t < 4; t++) acc[i][j][t] = 0.f;

    const int a_row_l = (lane & 7) + ((lane >> 3) & 1) * 8;
    const int a_c16_l = (lane >> 4);
    const int b_row_l = (lane & 7);
    const int b_c16_l = ((lane >> 3) & 1);

    const int nch = K / GKC;   // 20

    // 3-stage prologue: chunks 0 and 1 in flight
    load_chunk4(sb, 0, a0, a1, b0, b1, 0, tid, K);
    CP_COMMIT();
    load_chunk4(sb, 1, a0, a1, b0, b1, GKC, tid, K);
    CP_COMMIT();

    int buf = 0;
    for (int it = 0; it < nch; it++) {
        if (it + 2 < nch) {
            int nb = buf + 2; if (nb >= 3) nb -= 3;
            load_chunk4(sb, nb, a0, a1, b0, b1, (it + 2) * GKC, tid, K);
            CP_COMMIT();
            CP_WAIT(2);
        } else if (it + 1 < nch) {
            CP_WAIT(1);
        } else {
            CP_WAIT(0);
        }
        __syncthreads();

        uint32_t stage = sb + (uint32_t)buf * STAGE_B;
        uint32_t sAhi = stage;
        uint32_t sAlo = stage + MAT_B;
        uint32_t sBhi = stage + 2 * MAT_B;
        uint32_t sBlo = stage + 3 * MAT_B;

        #pragma unroll
        for (int ks = 0; ks < 4; ks++) {
            uint32_t ahi[4][4], alo[4][4], bhi[4][2], blo[4][2];
            #pragma unroll
            for (int mt = 0; mt < 4; mt++) {
                uint32_t boff = (uint32_t)((wm * 64 + mt * 16 + a_row_l) * 128 +
                                           (ks * 2 + a_c16_l) * 16);
                uint32_t so = swz(boff);
                ldsm_x4(ahi[mt][0], ahi[mt][1], ahi[mt][2], ahi[mt][3], sAhi + so);
                ldsm_x4(alo[mt][0], alo[mt][1], alo[mt][2], alo[mt][3], sAlo + so);
            }
            #pragma unroll
            for (int nt = 0; nt < 4; nt++) {
                uint32_t boff = (uint32_t)((wn * 32 + nt * 8 + b_row_l) * 128 +
                                           (ks * 2 + b_c16_l) * 16);
                uint32_t so = swz(boff);
                ldsm_x2(bhi[nt][0], bhi[nt][1], sBhi + so);
                ldsm_x2(blo[nt][0], blo[nt][1], sBlo + so);
            }
            #pragma unroll
            for (int mt = 0; mt < 4; mt++)
                #pragma unroll
                for (int nt = 0; nt < 4; nt++) {
                    mma16816bf(acc[mt][nt], ahi[mt], bhi[nt]);
                    mma16816bf(acc[mt][nt], ahi[mt], blo[nt]);
                    mma16816bf(acc[mt][nt], alo[mt], bhi[nt]);
                }
        }
        __syncthreads();
        buf++; if (buf == 3) buf = 0;
    }

    const int r_base = m0 + wm * 64 + (lane >> 2);
    const int c_base = n0 + wn * 32 + (lane & 3) * 2;
    #pragma unroll
    for (int mt = 0; mt < 4; mt++) {
        #pragma unroll
        for (int nt = 0; nt < 4; nt++) {
            int col = c_base + nt * 8;
            float bx = bias[col], by = bias[col + 1];
            int r0 = r_base + mt * 16;
            float2 v0 = {acc[mt][nt][0] + bx, acc[mt][nt][1] + by};
            float2 v1 = {acc[mt][nt][2] + bx, acc[mt][nt][3] + by};
            *(float2*)(C + (size_t)r0 * N + col) = v0;
            *(float2*)(C + (size_t)(r0 + 8) * N + col) = v1;
        }
    }
}

// ---------------------------------------------------------------------------
// RoPE + split-fp16 scatter for Q (scaled) and K: [v][h][p][d]
// ---------------------------------------------------------------------------
__global__ __launch_bounds__(256) void rope_scatter(
    const float* __restrict__ qkv, const float* __restrict__ rope)
{
    int idx = blockIdx.x * 256 + threadIdx.x;
    if (idx >= VB * PP * HH * 40) return;
    int d = idx % 40;
    int h = (idx / 40) % HH;
    int p = (idx / (40 * HH)) % PP;
    int v = idx / (40 * HH * PP);

    size_t row = (size_t)v * PP + p;
    const float* qr = qkv + row * N_QKV + h * HD;
    const float* kr = qr + DD;
    const float* rp = rope + row * (2 * HD);

    float c0 = rp[d],      c1 = rp[d + 40];
    float s0 = rp[HD + d], s1 = rp[HD + d + 40];
    float q0 = qr[d], q1 = qr[d + 40];
    float k0 = kr[d], k1 = kr[d + 40];

    float qa = (q0 * c0 - q1 * s0) * QK_SCALE;
    float qb = (q1 * c1 + q0 * s1) * QK_SCALE;
    float ka = k0 * c0 - k1 * s0;
    float kb = k1 * c1 + k0 * s1;

    size_t ob = (((size_t)v * HH + h) * PP + p) * HD;
    __half hqa = __float2half_rn(qa);
    __half hqb = __float2half_rn(qb);
    __half hka = __float2half_rn(ka);
    __half hkb = __float2half_rn(kb);
    g_qhi2[ob + d]      = hqa;
    g_qhi2[ob + d + 40] = hqb;
    g_qlo2[ob + d]      = __float2half_rn(qa - __half2float(hqa));
    g_qlo2[ob + d + 40] = __float2half_rn(qb - __half2float(hqb));
    g_khi2[ob + d]      = hka;
    g_khi2[ob + d + 40] = hkb;
    g_klo2[ob + d]      = __float2half_rn(ka - __half2float(hka));
    g_klo2[ob + d + 40] = __float2half_rn(kb - __half2float(hkb));
}

// ---------------------------------------------------------------------------
// V transpose: g_qkv V-part [v][p][h*80+d] -> g_vt [v][h][d][p] fp16
// ---------------------------------------------------------------------------
__global__ __launch_bounds__(256) void v_transpose(const float* __restrict__ qkv)
{
    __shared__ float t[32][33];
    int vh = blockIdx.z;
    int v = vh >> 4, h = vh & 15;
    int p0 = blockIdx.x * 32;
    int d0 = blockIdx.y * 32;
    int tx = threadIdx.x & 31, ty = threadIdx.x >> 5;
    #pragma unroll
    for (int r = ty; r < 32; r += 8) {
        int d = d0 + tx;
        if (d < HD)
            t[r][tx] = qkv[((size_t)v * PP + p0 + r) * N_QKV + 2 * DD + h * HD + d];
    }
    __syncthreads();
    #pragma unroll
    for (int r = ty; r < 32; r += 8) {
        int d = d0 + r;
        if (d < HD)
            g_vt[((size_t)vh * HD + d) * PP + p0 + tx] = __float2half_rn(t[tx][r]);
    }
}

// ---------------------------------------------------------------------------
// Tensor-core flash attention (fused split-bf16 epilogue)
// ---------------------------------------------------------------------------
#define SQ 88
#define SV 72
#define ATTN_SMEM 113152

__global__ __launch_bounds__(256) void attn_mma(const int* __restrict__ valid_lens)
{
    extern __shared__ char smem[];
    uint32_t sb = smem_u32(smem);
    const int tid = threadIdx.x;
    const int lane = tid & 31;
    const int wq = tid >> 5;
    const int q0 = blockIdx.x * 128;
    const int h = blockIdx.y;
    const int v = blockIdx.z;
    int L = valid_lens[v];
    if (L < 1) L = 1;

    const size_t hb = ((size_t)(v * HH + h)) * PP * HD;
    const __half* qhi = g_qhi2 + hb + (size_t)q0 * HD;
    const __half* qlo = g_qlo2 + hb + (size_t)q0 * HD;
    const __half* khi = g_khi2 + hb;
    const __half* klo = g_klo2 + hb;
    const __half* vtp = g_vt + hb;   // [80][2048]

    const uint32_t bQHI = sb;
    const uint32_t bQLO = sb + 22528u;
    const uint32_t bKHI = sb + 45056u;
    const uint32_t bKLO = sb + 67584u;
    const uint32_t bVT  = sb + 90112u;

    for (int i = tid; i < 1280; i += 256) {
        int r = i / 10, g = i % 10;
        uint32_t off = (uint32_t)(r * SQ + g * 8) * 2;
        CP_ASYNC16(bQHI + off, qhi + (size_t)r * HD + g * 8);
        CP_ASYNC16(bQLO + off, qlo + (size_t)r * HD + g * 8);
    }
    {
        for (int i = tid; i < 640; i += 256) {
            int r = i / 10, g = i % 10;
            uint32_t off = (uint32_t)(r * SQ + g * 8) * 2;
            CP_ASYNC16(bKHI + off, khi + (size_t)r * HD + g * 8);
            CP_ASYNC16(bKLO + off, klo + (size_t)r * HD + g * 8);
        }
        for (int i = tid; i < 640; i += 256) {
            int d = i / 8, g = i % 8;
            CP_ASYNC16(bVT + (uint32_t)(d * SV + g * 8) * 2, vtp + (size_t)d * PP + g * 8);
        }
    }
    CP_COMMIT();

    float m_lo = -1e30f, m_hi = -1e30f, l_lo = 0.f, l_hi = 0.f;
    float o[10][4];
    #pragma unroll
    for (int i = 0; i < 10; i++)
        #pragma unroll
        for (int j = 0; j < 4; j++) o[i][j] = 0.f;

    const int a_row = wq * 16 + (lane & 7) + ((lane >> 3) & 1) * 8;
    const int a_c16 = (lane >> 4);
    const int b_row = (lane & 7);
    const int b_c16 = (lane >> 3) & 1;
    const int gc = lane & 3;

    const int nkt = (L + 63) >> 6;
    for (int kt = 0; kt < nkt; kt++) {
        const int b = kt & 1;
        if (kt + 1 < nkt) {
            const int kn = (kt + 1) * 64;
            const uint32_t kh = bKHI + (uint32_t)(b ^ 1) * 11264u;
            const uint32_t kl = bKLO + (uint32_t)(b ^ 1) * 11264u;
            const uint32_t vb = bVT + (uint32_t)(b ^ 1) * 11520u;
            for (int i = tid; i < 640; i += 256) {
                int r = i / 10, g = i % 10;
                uint32_t off = (uint32_t)(r * SQ + g * 8) * 2;
                CP_ASYNC16(kh + off, khi + (size_t)(kn + r) * HD + g * 8);
                CP_ASYNC16(kl + off, klo + (size_t)(kn + r) * HD + g * 8);
            }
            for (int i = tid; i < 640; i += 256) {
                int d = i / 8, g = i % 8;
                CP_ASYNC16(vb + (uint32_t)(d * SV + g * 8) * 2,
                           vtp + (size_t)d * PP + kn + g * 8);
            }
            CP_COMMIT();
            CP_WAIT(1);
        } else {
            CP_WAIT(0);
        }
        __syncthreads();

        const uint32_t khb = bKHI + (uint32_t)b * 11264u;
        const uint32_t klb = bKLO + (uint32_t)b * 11264u;
        const uint32_t vtb = bVT + (uint32_t)b * 11520u;

        float s[8][4];
        #pragma unroll
        for (int nt = 0; nt < 8; nt++)
            #pragma unroll
            for (int j = 0; j < 4; j++) s[nt][j] = 0.f;

        #pragma unroll
        for (int kc = 0; kc < 5; kc++) {
            uint32_t qh[4], ql[4];
            uint32_t qoff = (uint32_t)(a_row * SQ + kc * 16 + a_c16 * 8) * 2;
            ldsm_x4(qh[0], qh[1], qh[2], qh[3], bQHI + qoff);
            ldsm_x4(ql[0], ql[1], ql[2], ql[3], bQLO + qoff);
            #pragma unroll
            for (int nt = 0; nt < 8; nt++) {
                uint32_t koff = (uint32_t)((nt * 8 + b_row) * SQ + kc * 16 + b_c16 * 8) * 2;
                uint32_t kh[2], kl[2];
                ldsm_x2(kh[0], kh[1], khb + koff);
                ldsm_x2(kl[0], kl[1], klb + koff);
                mma16816h(s[nt], qh, kh);
                mma16816h(s[nt], qh, kl);
                mma16816h(s[nt], ql, kh);
            }
        }

        const int k0 = kt * 64;
        if (k0 + 64 > L) {
            #pragma unroll
            for (int nt = 0; nt < 8; nt++) {
                int kb0 = k0 + nt * 8 + gc * 2;
                if (kb0 >= L)     { s[nt][0] = -1e30f; s[nt][2] = -1e30f; }
                if (kb0 + 1 >= L) { s[nt][1] = -1e30f; s[nt][3] = -1e30f; }
            }
        }

        float mt_lo = -1e30f, mt_hi = -1e30f;
        #pragma unroll
        for (int nt = 0; nt < 8; nt++) {
            mt_lo = fmaxf(mt_lo, fmaxf(s[nt][0], s[nt][1]));
            mt_hi = fmaxf(mt_hi, fmaxf(s[nt][2], s[nt][3]));
        }
        mt_lo = fmaxf(mt_lo, __shfl_xor_sync(0xffffffffu, mt_lo, 1));
        mt_lo = fmaxf(mt_lo, __shfl_xor_sync(0xffffffffu, mt_lo, 2));
        mt_hi = fmaxf(mt_hi, __shfl_xor_sync(0xffffffffu, mt_hi, 1));
        mt_hi = fmaxf(mt_hi, __shfl_xor_sync(0xffffffffu, mt_hi, 2));

        float mn_lo = fmaxf(m_lo, mt_lo), mn_hi = fmaxf(m_hi, mt_hi);
        float al = __expf(m_lo - mn_lo), ah = __expf(m_hi - mn_hi);
        m_lo = mn_lo; m_hi = mn_hi;

        float sum_lo = 0.f, sum_hi = 0.f;
        #pragma unroll
        for (int nt = 0; nt < 8; nt++) {
            s[nt][0] = __expf(s[nt][0] - mn_lo);
            s[nt][1] = __expf(s[nt][1] - mn_lo);
            s[nt][2] = __expf(s[nt][2] - mn_hi);
            s[nt][3] = __expf(s[nt][3] - mn_hi);
            sum_lo += s[nt][0] + s[nt][1];
            sum_hi += s[nt][2] + s[nt][3];
        }
        sum_lo += __shfl_xor_sync(0xffffffffu, sum_lo, 1);
        sum_lo += __shfl_xor_sync(0xffffffffu, sum_lo, 2);
        sum_hi += __shfl_xor_sync(0xffffffffu, sum_hi, 1);
        sum_hi += __shfl_xor_sync(0xffffffffu, sum_hi, 2);
        l_lo = l_lo * al + sum_lo;
        l_hi = l_hi * ah + sum_hi;

        #pragma unroll
        for (int nt = 0; nt < 10; nt++) {
            o[nt][0] *= al; o[nt][1] *= al;
            o[nt][2] *= ah; o[nt][3] *= ah;
        }

        uint32_t pa[4][4];
        #pragma unroll
        for (int kc = 0; kc < 4; kc++) {
            __half2 t0 = __floats2half2_rn(s[2 * kc][0], s[2 * kc][1]);
            __half2 t1 = __floats2half2_rn(s[2 * kc][2], s[2 * kc][3]);
            __half2 t2 = __floats2half2_rn(s[2 * kc + 1][0], s[2 * kc + 1][1]);
            __half2 t3 = __floats2half2_rn(s[2 * kc + 1][2], s[2 * kc + 1][3]);
            pa[kc][0] = *(uint32_t*)&t0;
            pa[kc][1] = *(uint32_t*)&t1;
            pa[kc][2] = *(uint32_t*)&t2;
            pa[kc][3] = *(uint32_t*)&t3;
        }

        #pragma unroll
        for (int nt = 0; nt < 10; nt++) {
            #pragma unroll
            for (int kc = 0; kc < 4; kc++) {
                uint32_t voff = (uint32_t)((nt * 8 + b_row) * SV + kc * 16 + b_c16 * 8) * 2;
                uint32_t vv[2];
                ldsm_x2(vv[0], vv[1], vtb + voff);
                mma16816h(o[nt], pa[kc], vv);
            }
        }
        __syncthreads();
    }

    // Epilogue: write split bf16 hi/lo directly (fused split for proj GEMM)
    float inv_lo = 1.f / l_lo, inv_hi = 1.f / l_hi;
    int row_lo = q0 + wq * 16 + (lane >> 2);
    #pragma unroll
    for (int nt = 0; nt < 10; nt++) {
        int col = h * HD + nt * 8 + gc * 2;
        size_t off0 = ((size_t)v * PP + row_lo) * DD + col;
        size_t off1 = ((size_t)v * PP + row_lo + 8) * DD + col;
        float v00 = o[nt][0] * inv_lo, v01 = o[nt][1] * inv_lo;
        float v10 = o[nt][2] * inv_hi, v11 = o[nt][3] * inv_hi;
        __nv_bfloat16 h00 = __float2bfloat16(v00);
        __nv_bfloat16 h01 = __float2bfloat16(v01);
        __nv_bfloat16 h10 = __float2bfloat16(v10);
        __nv_bfloat16 h11 = __float2bfloat16(v11);
        *(__nv_bfloat162*)(g_ahi + off0) = __nv_bfloat162(h00, h01);
        *(__nv_bfloat162*)(g_ahi + off1) = __nv_bfloat162(h10, h11);
        *(__nv_bfloat162*)(g_alo + off0) = __nv_bfloat162(
            __float2bfloat16(v00 - __bfloat162float(h00)),
            __float2bfloat16(v01 - __bfloat162float(h01)));
        *(__nv_bfloat162*)(g_alo + off1) = __nv_bfloat162(
            __float2bfloat16(v10 - __bfloat162float(h10)),
            __float2bfloat16(v11 - __bfloat162float(h11)));
    }
}

// ---------------------------------------------------------------------------
// Launch
// ---------------------------------------------------------------------------
extern "C" void kernel_launch(void* const* d_in, const int* in_sizes, int n_in,
                              void* d_out, int out_size)
{
    const float* hs    = (const float*)d_in[0];
    const float* rope  = (const float*)d_in[1];
    const int*   vlens = (const int*)d_in[2];
    const float* wqkv  = (const float*)d_in[3];
    const float* bqkv  = (const float*)d_in[4];
    const float* wproj = (const float*)d_in[5];
    const float* bproj = (const float*)d_in[6];
    float* out = (float*)d_out;

    float* p_qkv;
    __nv_bfloat16 *p_ahi, *p_alo, *p_bhi, *p_blo;
    cudaGetSymbolAddress((void**)&p_qkv, g_qkv);
    cudaGetSymbolAddress((void**)&p_ahi, g_ahi);
    cudaGetSymbolAddress((void**)&p_alo, g_alo);
    cudaGetSymbolAddress((void**)&p_bhi, g_bhi);
    cudaGetSymbolAddress((void**)&p_blo, g_blo);

    cudaFuncSetAttribute(gemm_mma_bf16x3,
                         cudaFuncAttributeMaxDynamicSharedMemorySize, GEMM_SMEM);
    cudaFuncSetAttribute(attn_mma,
                         cudaFuncAttributeMaxDynamicSharedMemorySize, ATTN_SMEM);

    // 1) Split hidden states, transpose+split W_qkv
    {
        int n = M_ROWS * DD;
        split_kernel<<<(n / 4 + 255) / 256, 256>>>(hs, p_ahi, p_alo, n);
        transpose_split<<<dim3(N_QKV / 32, DD / 32), 256>>>(wqkv, p_bhi, p_blo, DD, N_QKV);
    }

    // 2) QKV GEMM (3-stage pipeline)
    gemm_mma_bf16x3<<<dim3(N_QKV / GTN, M_ROWS / GTM), 256, GEMM_SMEM>>>(
        p_ahi, p_alo, p_bhi, p_blo, bqkv, p_qkv, DD, N_QKV);

    // 3) RoPE (split fp16 Q/K) + V transpose (fp16)
    {
        int total = VB * PP * HH * 40;
        rope_scatter<<<(total + 255) / 256, 256>>>(p_qkv, rope);
        v_transpose<<<dim3(PP / 32, 3, VB * HH), 256>>>(p_qkv);
    }

    // 4) Tensor-core flash attention (writes split bf16 directly)
    attn_mma<<<dim3(PP / 128, HH, VB), 256, ATTN_SMEM>>>(vlens);

    // 5) Transpose+split W_proj (g_bhi/g_blo free after QKV GEMM)
    transpose_split<<<dim3(DD / 32, DD / 32), 256>>>(wproj, p_bhi, p_blo, DD, DD);

    // 6) Output projection
    gemm_mma_bf16x3<<<dim3(DD / GTN, M_ROWS / GTM), 256, GEMM_SMEM>>>(
        p_ahi, p_alo, p_bhi, p_blo, bproj, out, DD, DD);
}

// round 11
// speedup vs baseline: 1.1250x; 1.0595x over previous
#include <cuda_runtime.h>
#include <cuda_bf16.h>
#include <cuda_fp16.h>
#include <cstdint>

// Problem constants
#define VB 4
#define PP 2048
#define DD 1280
#define HH 16
#define HD 80
#define M_ROWS (VB * PP)     // 8192
#define N_QKV  (3 * DD)      // 3840
#define QK_SCALE 0.111803398874989484f

// ---------------------------------------------------------------------------
// Scratch (static device globals — allocation-guard safe)
// ---------------------------------------------------------------------------
__device__ float g_qkv[M_ROWS * N_QKV];               // [8192, 3840] fp32
__device__ __nv_bfloat16 g_ahi[M_ROWS * DD];          // split A (hs, then attn out)
__device__ __nv_bfloat16 g_alo[M_ROWS * DD];
__device__ __nv_bfloat16 g_bhi[N_QKV * DD];           // split W_qkv^T [N,K]
__device__ __nv_bfloat16 g_blo[N_QKV * DD];
__device__ __nv_bfloat16 g_phi[DD * DD];              // split W_proj^T [N,K]
__device__ __nv_bfloat16 g_plo[DD * DD];
// fp16 attention operands
__device__ __align__(16) __half g_qhi2[VB * HH * PP * HD];  // [v][h][p][d], scaled
__device__ __align__(16) __half g_qlo2[VB * HH * PP * HD];
__device__ __align__(16) __half g_k16[VB * HH * PP * HD];   // plain fp16 K
__device__ __align__(16) __half g_vt[VB * HH * HD * PP];    // [v][h][d][p]

// ---------------------------------------------------------------------------
// Helpers
// ---------------------------------------------------------------------------
__device__ __forceinline__ uint32_t smem_u32(const void* p) {
    uint32_t a;
    asm("{ .reg .u64 t; cvta.to.shared.u64 t, %1; cvt.u32.u64 %0, t; }" : "=r"(a) : "l"(p));
    return a;
}

#define CP_ASYNC16(dst, src) \
    asm volatile("cp.async.cg.shared.global [%0], [%1], 16;" :: "r"(dst), "l"(src))
#define CP_COMMIT() asm volatile("cp.async.commit_group;" ::: "memory")
#define CP_WAIT(n)  asm volatile("cp.async.wait_group %0;" :: "n"(n) : "memory")

__device__ __forceinline__ void ldsm_x4(uint32_t& r0, uint32_t& r1, uint32_t& r2, uint32_t& r3,
                                        uint32_t addr) {
    asm volatile("ldmatrix.sync.aligned.m8n8.x4.shared.b16 {%0,%1,%2,%3}, [%4];"
                 : "=r"(r0), "=r"(r1), "=r"(r2), "=r"(r3) : "r"(addr));
}
__device__ __forceinline__ void ldsm_x2(uint32_t& r0, uint32_t& r1, uint32_t addr) {
    asm volatile("ldmatrix.sync.aligned.m8n8.x2.shared.b16 {%0,%1}, [%2];"
                 : "=r"(r0), "=r"(r1) : "r"(addr));
}
__device__ __forceinline__ void mma16816bf(float* c, const uint32_t* a, const uint32_t* b) {
    asm volatile("mma.sync.aligned.m16n8k16.row.col.f32.bf16.bf16.f32 "
                 "{%0,%1,%2,%3}, {%4,%5,%6,%7}, {%8,%9}, {%0,%1,%2,%3};"
                 : "+f"(c[0]), "+f"(c[1]), "+f"(c[2]), "+f"(c[3])
                 : "r"(a[0]), "r"(a[1]), "r"(a[2]), "r"(a[3]), "r"(b[0]), "r"(b[1]));
}
__device__ __forceinline__ void mma16816h(float* c, const uint32_t* a, const uint32_t* b) {
    asm volatile("mma.sync.aligned.m16n8k16.row.col.f32.f16.f16.f32 "
                 "{%0,%1,%2,%3}, {%4,%5,%6,%7}, {%8,%9}, {%0,%1,%2,%3};"
                 : "+f"(c[0]), "+f"(c[1]), "+f"(c[2]), "+f"(c[3])
                 : "r"(a[0]), "r"(a[1]), "r"(a[2]), "r"(a[3]), "r"(b[0]), "r"(b[1]));
}

__device__ __forceinline__ uint32_t swz(uint32_t x) { return x ^ ((x >> 3) & 0x70u); }

// ---------------------------------------------------------------------------
// Split fp32 -> hi/lo bf16
// ---------------------------------------------------------------------------
__global__ __launch_bounds__(256) void split_kernel(
    const float* __restrict__ x, __nv_bfloat16* __restrict__ hi,
    __nv_bfloat16* __restrict__ lo, int n)
{
    int i = (blockIdx.x * 256 + threadIdx.x) * 4;
    if (i >= n) return;
    float4 v = *(const float4*)(x + i);
    __nv_bfloat16 h0 = __float2bfloat16(v.x);
    __nv_bfloat16 h1 = __float2bfloat16(v.y);
    __nv_bfloat16 h2 = __float2bfloat16(v.z);
    __nv_bfloat16 h3 = __float2bfloat16(v.w);
    ((__nv_bfloat162*)(hi + i))[0] = __nv_bfloat162(h0, h1);
    ((__nv_bfloat162*)(hi + i))[1] = __nv_bfloat162(h2, h3);
    __nv_bfloat16 l0 = __float2bfloat16(v.x - __bfloat162float(h0));
    __nv_bfloat16 l1 = __float2bfloat16(v.y - __bfloat162float(h1));
    __nv_bfloat16 l2 = __float2bfloat16(v.z - __bfloat162float(h2));
    __nv_bfloat16 l3 = __float2bfloat16(v.w - __bfloat162float(h3));
    ((__nv_bfloat162*)(lo + i))[0] = __nv_bfloat162(l0, l1);
    ((__nv_bfloat162*)(lo + i))[1] = __nv_bfloat162(l2, l3);
}

// ---------------------------------------------------------------------------
// Transpose + split: w [K,N] fp32 -> thi/tlo [N,K] bf16
// ---------------------------------------------------------------------------
__global__ __launch_bounds__(256) void transpose_split(
    const float* __restrict__ w, __nv_bfloat16* __restrict__ thi,
    __nv_bfloat16* __restrict__ tlo, int K, int N)
{
    __shared__ float t[32][33];
    int n0 = blockIdx.x * 32, k0 = blockIdx.y * 32;
    int tx = threadIdx.x & 31, ty = threadIdx.x >> 5;
    #pragma unroll
    for (int r = ty; r < 32; r += 8)
        t[r][tx] = w[(size_t)(k0 + r) * N + n0 + tx];
    __syncthreads();
    #pragma unroll
    for (int r = ty; r < 32; r += 8) {
        float v = t[tx][r];
        __nv_bfloat16 h = __float2bfloat16(v);
        size_t o = (size_t)(n0 + r) * K + k0 + tx;
        thi[o] = h;
        tlo[o] = __float2bfloat16(v - __bfloat162float(h));
    }
}

// ---------------------------------------------------------------------------
// mma.sync split-bf16 GEMM: C = A @ B^T + bias
// CTA 128x128, K-chunk 64 (SW128), 3-stage cp.async pipeline.
// ---------------------------------------------------------------------------
#define GTM 128
#define GTN 128
#define GKC 64
#define MAT_B 16384u
#define STAGE_B (4u * MAT_B)      // 64 KB
#define GEMM_SMEM (3 * STAGE_B)   // 196608 bytes (3 stages)

__device__ __forceinline__ void load_chunk4(
    uint32_t sb, int buf,
    const __nv_bfloat16* a0, const __nv_bfloat16* a1,
    const __nv_bfloat16* b0, const __nv_bfloat16* b1,
    int k0, int tid, int K)
{
    const __nv_bfloat16* srcs[4] = {a0 + k0, a1 + k0, b0 + k0, b1 + k0};
    uint32_t stage = sb + (uint32_t)buf * STAGE_B;
    #pragma unroll
    for (int mat = 0; mat < 4; mat++) {
        uint32_t tbase = stage + (uint32_t)mat * MAT_B;
        const __nv_bfloat16* s = srcs[mat];
        #pragma unroll
        for (int i = 0; i < 4; i++) {
            int g = tid + i * 256;
            int row = g >> 3;
            int c16 = g & 7;
            uint32_t boff = (uint32_t)(row * 128 + c16 * 16);
            CP_ASYNC16(tbase + swz(boff), s + (size_t)row * K + c16 * 8);
        }
    }
}

__global__ __launch_bounds__(256) void gemm_mma_bf16x3(
    const __nv_bfloat16* __restrict__ Ahi, const __nv_bfloat16* __restrict__ Alo,
    const __nv_bfloat16* __restrict__ Bhi, const __nv_bfloat16* __restrict__ Blo,
    const float* __restrict__ bias, float* __restrict__ C, int K, int N)
{
    extern __shared__ char smem[];
    uint32_t sb = smem_u32(smem);
    const int tid = threadIdx.x;
    const int lane = tid & 31;
    const int wid = tid >> 5;
    const int wm = wid >> 2;
    const int wn = wid & 3;
    const int m0 = blockIdx.y * GTM;
    const int n0 = blockIdx.x * GTN;

    const __nv_bfloat16* a0 = Ahi + (size_t)m0 * K;
    const __nv_bfloat16* a1 = Alo + (size_t)m0 * K;
    const __nv_bfloat16* b0 = Bhi + (size_t)n0 * K;
    const __nv_bfloat16* b1 = Blo + (size_t)n0 * K;

    float acc[4][4][4];
    #pragma unroll
    for (int i = 0; i < 4; i++)
        #pragma unroll
        for (int j = 0; j < 4; j++)
            #pragma unroll
            for (int t = 0; t < 4; t++) acc[i][j][t] = 0.f;

    const int a_row_l = (lane & 7) + ((lane >> 3) & 1) * 8;
    const int a_c16_l = (lane >> 4);
    const int b_row_l = (lane & 7);
    const int b_c16_l = ((lane >> 3) & 1);

    const int nch = K / GKC;

    load_chunk4(sb, 0, a0, a1, b0, b1, 0, tid, K);
    CP_COMMIT();
    load_chunk4(sb, 1, a0, a1, b0, b1, GKC, tid, K);
    CP_COMMIT();

    int buf = 0;
    for (int it = 0; it < nch; it++) {
        if (it + 2 < nch) {
            int nb = buf + 2; if (nb >= 3) nb -= 3;
            load_chunk4(sb, nb, a0, a1, b0, b1, (it + 2) * GKC, tid, K);
            CP_COMMIT();
            CP_WAIT(2);
        } else if (it + 1 < nch) {
            CP_WAIT(1);
        } else {
            CP_WAIT(0);
        }
        __syncthreads();

        uint32_t stage = sb + (uint32_t)buf * STAGE_B;
        uint32_t sAhi = stage;
        uint32_t sAlo = stage + MAT_B;
        uint32_t sBhi = stage + 2 * MAT_B;
        uint32_t sBlo = stage + 3 * MAT_B;

        #pragma unroll
        for (int ks = 0; ks < 4; ks++) {
            uint32_t ahi[4][4], alo[4][4], bhi[4][2], blo[4][2];
            #pragma unroll
            for (int mt = 0; mt < 4; mt++) {
                uint32_t boff = (uint32_t)((wm * 64 + mt * 16 + a_row_l) * 128 +
                                           (ks * 2 + a_c16_l) * 16);
                uint32_t so = swz(boff);
                ldsm_x4(ahi[mt][0], ahi[mt][1], ahi[mt][2], ahi[mt][3], sAhi + so);
                ldsm_x4(alo[mt][0], alo[mt][1], alo[mt][2], alo[mt][3], sAlo + so);
            }
            #pragma unroll
            for (int nt = 0; nt < 4; nt++) {
                uint32_t boff = (uint32_t)((wn * 32 + nt * 8 + b_row_l) * 128 +
                                           (ks * 2 + b_c16_l) * 16);
                uint32_t so = swz(boff);
                ldsm_x2(bhi[nt][0], bhi[nt][1], sBhi + so);
                ldsm_x2(blo[nt][0], blo[nt][1], sBlo + so);
            }
            #pragma unroll
            for (int mt = 0; mt < 4; mt++)
                #pragma unroll
                for (int nt = 0; nt < 4; nt++) {
                    mma16816bf(acc[mt][nt], ahi[mt], bhi[nt]);
                    mma16816bf(acc[mt][nt], ahi[mt], blo[nt]);
                    mma16816bf(acc[mt][nt], alo[mt], bhi[nt]);
                }
        }
        __syncthreads();
        buf++; if (buf == 3) buf = 0;
    }

    const int r_base = m0 + wm * 64 + (lane >> 2);
    const int c_base = n0 + wn * 32 + (lane & 3) * 2;
    #pragma unroll
    for (int mt = 0; mt < 4; mt++) {
        #pragma unroll
        for (int nt = 0; nt < 4; nt++) {
            int col = c_base + nt * 8;
            float bx = bias[col], by = bias[col + 1];
            int r0 = r_base + mt * 16;
            float2 v0 = {acc[mt][nt][0] + bx, acc[mt][nt][1] + by};
            float2 v1 = {acc[mt][nt][2] + bx, acc[mt][nt][3] + by};
            *(float2*)(C + (size_t)r0 * N + col) = v0;
            *(float2*)(C + (size_t)(r0 + 8) * N + col) = v1;
        }
    }
}

// ---------------------------------------------------------------------------
// RoPE: Q -> split fp16 (scaled), K -> plain fp16. [v][h][p][d]
// ---------------------------------------------------------------------------
__global__ __launch_bounds__(256) void rope_scatter(
    const float* __restrict__ qkv, const float* __restrict__ rope)
{
    int idx = blockIdx.x * 256 + threadIdx.x;
    if (idx >= VB * PP * HH * 40) return;
    int d = idx % 40;
    int h = (idx / 40) % HH;
    int p = (idx / (40 * HH)) % PP;
    int v = idx / (40 * HH * PP);

    size_t row = (size_t)v * PP + p;
    const float* qr = qkv + row * N_QKV + h * HD;
    const float* kr = qr + DD;
    const float* rp = rope + row * (2 * HD);

    float c0 = rp[d],      c1 = rp[d + 40];
    float s0 = rp[HD + d], s1 = rp[HD + d + 40];
    float q0 = qr[d], q1 = qr[d + 40];
    float k0 = kr[d], k1 = kr[d + 40];

    float qa = (q0 * c0 - q1 * s0) * QK_SCALE;
    float qb = (q1 * c1 + q0 * s1) * QK_SCALE;
    float ka = k0 * c0 - k1 * s0;
    float kb = k1 * c1 + k0 * s1;

    size_t ob = (((size_t)v * HH + h) * PP + p) * HD;
    __half hqa = __float2half_rn(qa);
    __half hqb = __float2half_rn(qb);
    g_qhi2[ob + d]      = hqa;
    g_qhi2[ob + d + 40] = hqb;
    g_qlo2[ob + d]      = __float2half_rn(qa - __half2float(hqa));
    g_qlo2[ob + d + 40] = __float2half_rn(qb - __half2float(hqb));
    g_k16[ob + d]       = __float2half_rn(ka);
    g_k16[ob + d + 40]  = __float2half_rn(kb);
}

// ---------------------------------------------------------------------------
// V transpose: g_qkv V-part [v][p][h*80+d] -> g_vt [v][h][d][p] fp16
// ---------------------------------------------------------------------------
__global__ __launch_bounds__(256) void v_transpose(const float* __restrict__ qkv)
{
    __shared__ float t[32][33];
    int vh = blockIdx.z;
    int v = vh >> 4, h = vh & 15;
    int p0 = blockIdx.x * 32;
    int d0 = blockIdx.y * 32;
    int tx = threadIdx.x & 31, ty = threadIdx.x >> 5;
    #pragma unroll
    for (int r = ty; r < 32; r += 8) {
        int d = d0 + tx;
        if (d < HD)
            t[r][tx] = qkv[((size_t)v * PP + p0 + r) * N_QKV + 2 * DD + h * HD + d];
    }
    __syncthreads();
    #pragma unroll
    for (int r = ty; r < 32; r += 8) {
        int d = d0 + r;
        if (d < HD)
            g_vt[((size_t)vh * HD + d) * PP + p0 + tx] = __float2half_rn(t[tx][r]);
    }
}

// ---------------------------------------------------------------------------
// Tensor-core flash attention: QK 2-product (Q split, K plain fp16),
// PV fp16, fused split-bf16 epilogue.
// Smem (bytes): Qhi 22528 | Qlo 22528 | K 2x11264 | Vt 2x11520
// ---------------------------------------------------------------------------
#define SQ 88
#define SV 72
#define ATTN_SMEM 90624

__global__ __launch_bounds__(256) void attn_mma(const int* __restrict__ valid_lens)
{
    extern __shared__ char smem[];
    uint32_t sb = smem_u32(smem);
    const int tid = threadIdx.x;
    const int lane = tid & 31;
    const int wq = tid >> 5;
    const int q0 = blockIdx.x * 128;
    const int h = blockIdx.y;
    const int v = blockIdx.z;
    int L = valid_lens[v];
    if (L < 1) L = 1;

    const size_t hb = ((size_t)(v * HH + h)) * PP * HD;
    const __half* qhi = g_qhi2 + hb + (size_t)q0 * HD;
    const __half* qlo = g_qlo2 + hb + (size_t)q0 * HD;
    const __half* kpt = g_k16 + hb;
    const __half* vtp = g_vt + hb;   // [80][2048]

    const uint32_t bQHI = sb;
    const uint32_t bQLO = sb + 22528u;
    const uint32_t bK   = sb + 45056u;   // 2 x 11264
    const uint32_t bVT  = sb + 67584u;   // 2 x 11520

    for (int i = tid; i < 1280; i += 256) {
        int r = i / 10, g = i % 10;
        uint32_t off = (uint32_t)(r * SQ + g * 8) * 2;
        CP_ASYNC16(bQHI + off, qhi + (size_t)r * HD + g * 8);
        CP_ASYNC16(bQLO + off, qlo + (size_t)r * HD + g * 8);
    }
    {
        for (int i = tid; i < 640; i += 256) {
            int r = i / 10, g = i % 10;
            uint32_t off = (uint32_t)(r * SQ + g * 8) * 2;
            CP_ASYNC16(bK + off, kpt + (size_t)r * HD + g * 8);
        }
        for (int i = tid; i < 640; i += 256) {
            int d = i / 8, g = i % 8;
            CP_ASYNC16(bVT + (uint32_t)(d * SV + g * 8) * 2, vtp + (size_t)d * PP + g * 8);
        }
    }
    CP_COMMIT();

    float m_lo = -1e30f, m_hi = -1e30f, l_lo = 0.f, l_hi = 0.f;
    float o[10][4];
    #pragma unroll
    for (int i = 0; i < 10; i++)
        #pragma unroll
        for (int j = 0; j < 4; j++) o[i][j] = 0.f;

    const int a_row = wq * 16 + (lane & 7) + ((lane >> 3) & 1) * 8;
    const int a_c16 = (lane >> 4);
    const int b_row = (lane & 7);
    const int b_c16 = (lane >> 3) & 1;
    const int gc = lane & 3;

    const int nkt = (L + 63) >> 6;
    for (int kt = 0; kt < nkt; kt++) {
        const int b = kt & 1;
        if (kt + 1 < nkt) {
            const int kn = (kt + 1) * 64;
            const uint32_t kh = bK + (uint32_t)(b ^ 1) * 11264u;
            const uint32_t vb = bVT + (uint32_t)(b ^ 1) * 11520u;
            for (int i = tid; i < 640; i += 256) {
                int r = i / 10, g = i % 10;
                uint32_t off = (uint32_t)(r * SQ + g * 8) * 2;
                CP_ASYNC16(kh + off, kpt + (size_t)(kn + r) * HD + g * 8);
            }
            for (int i = tid; i < 640; i += 256) {
                int d = i / 8, g = i % 8;
                CP_ASYNC16(vb + (uint32_t)(d * SV + g * 8) * 2,
                           vtp + (size_t)d * PP + kn + g * 8);
            }
            CP_COMMIT();
            CP_WAIT(1);
        } else {
            CP_WAIT(0);
        }
        __syncthreads();

        const uint32_t khb = bK + (uint32_t)b * 11264u;
        const uint32_t vtb = bVT + (uint32_t)b * 11520u;

        float s[8][4];
        #pragma unroll
        for (int nt = 0; nt < 8; nt++)
            #pragma unroll
            for (int j = 0; j < 4; j++) s[nt][j] = 0.f;

        #pragma unroll
        for (int kc = 0; kc < 5; kc++) {
            uint32_t qh[4], ql[4];
            uint32_t qoff = (uint32_t)(a_row * SQ + kc * 16 + a_c16 * 8) * 2;
            ldsm_x4(qh[0], qh[1], qh[2], qh[3], bQHI + qoff);
            ldsm_x4(ql[0], ql[1], ql[2], ql[3], bQLO + qoff);
            #pragma unroll
            for (int nt = 0; nt < 8; nt++) {
                uint32_t koff = (uint32_t)((nt * 8 + b_row) * SQ + kc * 16 + b_c16 * 8) * 2;
                uint32_t kk[2];
                ldsm_x2(kk[0], kk[1], khb + koff);
                mma16816h(s[nt], qh, kk);
                mma16816h(s[nt], ql, kk);
            }
        }

        const int k0 = kt * 64;
        if (k0 + 64 > L) {
            #pragma unroll
            for (int nt = 0; nt < 8; nt++) {
                int kb0 = k0 + nt * 8 + gc * 2;
                if (kb0 >= L)     { s[nt][0] = -1e30f; s[nt][2] = -1e30f; }
                if (kb0 + 1 >= L) { s[nt][1] = -1e30f; s[nt][3] = -1e30f; }
            }
        }

        float mt_lo = -1e30f, mt_hi = -1e30f;
        #pragma unroll
        for (int nt = 0; nt < 8; nt++) {
            mt_lo = fmaxf(mt_lo, fmaxf(s[nt][0], s[nt][1]));
            mt_hi = fmaxf(mt_hi, fmaxf(s[nt][2], s[nt][3]));
        }
        mt_lo = fmaxf(mt_lo, __shfl_xor_sync(0xffffffffu, mt_lo, 1));
        mt_lo = fmaxf(mt_lo, __shfl_xor_sync(0xffffffffu, mt_lo, 2));
        mt_hi = fmaxf(mt_hi, __shfl_xor_sync(0xffffffffu, mt_hi, 1));
        mt_hi = fmaxf(mt_hi, __shfl_xor_sync(0xffffffffu, mt_hi, 2));

        float mn_lo = fmaxf(m_lo, mt_lo), mn_hi = fmaxf(m_hi, mt_hi);
        float al = __expf(m_lo - mn_lo), ah = __expf(m_hi - mn_hi);
        m_lo = mn_lo; m_hi = mn_hi;

        float sum_lo = 0.f, sum_hi = 0.f;
        #pragma unroll
        for (int nt = 0; nt < 8; nt++) {
            s[nt][0] = __expf(s[nt][0] - mn_lo);
            s[nt][1] = __expf(s[nt][1] - mn_lo);
            s[nt][2] = __expf(s[nt][2] - mn_hi);
            s[nt][3] = __expf(s[nt][3] - mn_hi);
            sum_lo += s[nt][0] + s[nt][1];
            sum_hi += s[nt][2] + s[nt][3];
        }
        sum_lo += __shfl_xor_sync(0xffffffffu, sum_lo, 1);
        sum_lo += __shfl_xor_sync(0xffffffffu, sum_lo, 2);
        sum_hi += __shfl_xor_sync(0xffffffffu, sum_hi, 1);
        sum_hi += __shfl_xor_sync(0xffffffffu, sum_hi, 2);
        l_lo = l_lo * al + sum_lo;
        l_hi = l_hi * ah + sum_hi;

        #pragma unroll
        for (int nt = 0; nt < 10; nt++) {
            o[nt][0] *= al; o[nt][1] *= al;
            o[nt][2] *= ah; o[nt][3] *= ah;
        }

        uint32_t pa[4][4];
        #pragma unroll
        for (int kc = 0; kc < 4; kc++) {
            __half2 t0 = __floats2half2_rn(s[2 * kc][0], s[2 * kc][1]);
            __half2 t1 = __floats2half2_rn(s[2 * kc][2], s[2 * kc][3]);
            __half2 t2 = __floats2half2_rn(s[2 * kc + 1][0], s[2 * kc + 1][1]);
            __half2 t3 = __floats2half2_rn(s[2 * kc + 1][2], s[2 * kc + 1][3]);
            pa[kc][0] = *(uint32_t*)&t0;
            pa[kc][1] = *(uint32_t*)&t1;
            pa[kc][2] = *(uint32_t*)&t2;
            pa[kc][3] = *(uint32_t*)&t3;
        }

        #pragma unroll
        for (int nt = 0; nt < 10; nt++) {
            #pragma unroll
            for (int kc = 0; kc < 4; kc++) {
                uint32_t voff = (uint32_t)((nt * 8 + b_row) * SV + kc * 16 + b_c16 * 8) * 2;
                uint32_t vv[2];
                ldsm_x2(vv[0], vv[1], vtb + voff);
                mma16816h(o[nt], pa[kc], vv);
            }
        }
        __syncthreads();
    }

    // Epilogue: write split bf16 hi/lo directly (fused split for proj GEMM)
    float inv_lo = 1.f / l_lo, inv_hi = 1.f / l_hi;
    int row_lo = q0 + wq * 16 + (lane >> 2);
    #pragma unroll
    for (int nt = 0; nt < 10; nt++) {
        int col = h * HD + nt * 8 + gc * 2;
        size_t off0 = ((size_t)v * PP + row_lo) * DD + col;
        size_t off1 = ((size_t)v * PP + row_lo + 8) * DD + col;
        float v00 = o[nt][0] * inv_lo, v01 = o[nt][1] * inv_lo;
        float v10 = o[nt][2] * inv_hi, v11 = o[nt][3] * inv_hi;
        __nv_bfloat16 h00 = __float2bfloat16(v00);
        __nv_bfloat16 h01 = __float2bfloat16(v01);
        __nv_bfloat16 h10 = __float2bfloat16(v10);
        __nv_bfloat16 h11 = __float2bfloat16(v11);
        *(__nv_bfloat162*)(g_ahi + off0) = __nv_bfloat162(h00, h01);
        *(__nv_bfloat162*)(g_ahi + off1) = __nv_bfloat162(h10, h11);
        *(__nv_bfloat162*)(g_alo + off0) = __nv_bfloat162(
            __float2bfloat16(v00 - __bfloat162float(h00)),
            __float2bfloat16(v01 - __bfloat162float(h01)));
        *(__nv_bfloat162*)(g_alo + off1) = __nv_bfloat162(
            __float2bfloat16(v10 - __bfloat162float(h10)),
            __float2bfloat16(v11 - __bfloat162float(h11)));
    }
}

// ---------------------------------------------------------------------------
// Launch — ordered so the QKV GEMM is the 4th launch (ncu capture slot)
// ---------------------------------------------------------------------------
extern "C" void kernel_launch(void* const* d_in, const int* in_sizes, int n_in,
                              void* d_out, int out_size)
{
    const float* hs    = (const float*)d_in[0];
    const float* rope  = (const float*)d_in[1];
    const int*   vlens = (const int*)d_in[2];
    const float* wqkv  = (const float*)d_in[3];
    const float* bqkv  = (const float*)d_in[4];
    const float* wproj = (const float*)d_in[5];
    const float* bproj = (const float*)d_in[6];
    float* out = (float*)d_out;

    float* p_qkv;
    __nv_bfloat16 *p_ahi, *p_alo, *p_bhi, *p_blo, *p_phi, *p_plo;
    cudaGetSymbolAddress((void**)&p_qkv, g_qkv);
    cudaGetSymbolAddress((void**)&p_ahi, g_ahi);
    cudaGetSymbolAddress((void**)&p_alo, g_alo);
    cudaGetSymbolAddress((void**)&p_bhi, g_bhi);
    cudaGetSymbolAddress((void**)&p_blo, g_blo);
    cudaGetSymbolAddress((void**)&p_phi, g_phi);
    cudaGetSymbolAddress((void**)&p_plo, g_plo);

    cudaFuncSetAttribute(gemm_mma_bf16x3,
                         cudaFuncAttributeMaxDynamicSharedMemorySize, GEMM_SMEM);
    cudaFuncSetAttribute(attn_mma,
                         cudaFuncAttributeMaxDynamicSharedMemorySize, ATTN_SMEM);

    // 1) Split hidden states
    {
        int n = M_ROWS * DD;
        split_kernel<<<(n / 4 + 255) / 256, 256>>>(hs, p_ahi, p_alo, n);
    }
    // 2) Transpose+split W_qkv
    transpose_split<<<dim3(N_QKV / 32, DD / 32), 256>>>(wqkv, p_bhi, p_blo, DD, N_QKV);
    // 3) Transpose+split W_proj (independent; into its own buffers)
    transpose_split<<<dim3(DD / 32, DD / 32), 256>>>(wproj, p_phi, p_plo, DD, DD);

    // 4) QKV GEMM  <-- ncu capture slot
    gemm_mma_bf16x3<<<dim3(N_QKV / GTN, M_ROWS / GTM), 256, GEMM_SMEM>>>(
        p_ahi, p_alo, p_bhi, p_blo, bqkv, p_qkv, DD, N_QKV);

    // 5) RoPE (Q split fp16 scaled, K plain fp16)
    {
        int total = VB * PP * HH * 40;
        rope_scatter<<<(total + 255) / 256, 256>>>(p_qkv, rope);
    }
    // 6) V transpose (fp16)
    v_transpose<<<dim3(PP / 32, 3, VB * HH), 256>>>(p_qkv);

    // 7) Tensor-core flash attention (writes split bf16 directly)
    attn_mma<<<dim3(PP / 128, HH, VB), 256, ATTN_SMEM>>>(vlens);

    // 8) Output projection
    gemm_mma_bf16x3<<<dim3(DD / GTN, M_ROWS / GTM), 256, GEMM_SMEM>>>(
        p_ahi, p_alo, p_phi, p_plo, bproj, out, DD, DD);
}

// round 12
// speedup vs baseline: 1.2914x; 1.1480x over previous
#include <cuda_runtime.h>
#include <cuda_bf16.h>
#include <cuda_fp16.h>
#include <cstdint>

// Problem constants
#define VB 4
#define PP 2048
#define DD 1280
#define HH 16
#define HD 80
#define M_ROWS (VB * PP)     // 8192
#define N_QKV  (3 * DD)      // 3840
#define QK_SCALE 0.111803398874989484f

// ---------------------------------------------------------------------------
// Scratch (static device globals — allocation-guard safe)
// ---------------------------------------------------------------------------
__device__ float g_qkv[M_ROWS * N_QKV];               // [8192, 3840] fp32
__device__ __align__(16) __half g_ahi[M_ROWS * DD];   // split A (hs, then attn out)
__device__ __align__(16) __half g_alo[M_ROWS * DD];
__device__ __align__(16) __half g_bh[N_QKV * DD];     // W_qkv^T [N,K] plain fp16
__device__ __align__(16) __half g_ph[DD * DD];        // W_proj^T [N,K] plain fp16
// fp16 attention operands
__device__ __align__(16) __half g_qhi2[VB * HH * PP * HD];  // [v][h][p][d], scaled
__device__ __align__(16) __half g_qlo2[VB * HH * PP * HD];
__device__ __align__(16) __half g_khi2[VB * HH * PP * HD];
__device__ __align__(16) __half g_klo2[VB * HH * PP * HD];
__device__ __align__(16) __half g_vt[VB * HH * HD * PP];    // [v][h][d][p]

// ---------------------------------------------------------------------------
// Helpers
// ---------------------------------------------------------------------------
__device__ __forceinline__ uint32_t smem_u32(const void* p) {
    uint32_t a;
    asm("{ .reg .u64 t; cvta.to.shared.u64 t, %1; cvt.u32.u64 %0, t; }" : "=r"(a) : "l"(p));
    return a;
}

#define CP_ASYNC16(dst, src) \
    asm volatile("cp.async.cg.shared.global [%0], [%1], 16;" :: "r"(dst), "l"(src))
#define CP_COMMIT() asm volatile("cp.async.commit_group;" ::: "memory")
#define CP_WAIT(n)  asm volatile("cp.async.wait_group %0;" :: "n"(n) : "memory")

__device__ __forceinline__ void ldsm_x4(uint32_t& r0, uint32_t& r1, uint32_t& r2, uint32_t& r3,
                                        uint32_t addr) {
    asm volatile("ldmatrix.sync.aligned.m8n8.x4.shared.b16 {%0,%1,%2,%3}, [%4];"
                 : "=r"(r0), "=r"(r1), "=r"(r2), "=r"(r3) : "r"(addr));
}
__device__ __forceinline__ void ldsm_x2(uint32_t& r0, uint32_t& r1, uint32_t addr) {
    asm volatile("ldmatrix.sync.aligned.m8n8.x2.shared.b16 {%0,%1}, [%2];"
                 : "=r"(r0), "=r"(r1) : "r"(addr));
}
__device__ __forceinline__ void mma16816h(float* c, const uint32_t* a, const uint32_t* b) {
    asm volatile("mma.sync.aligned.m16n8k16.row.col.f32.f16.f16.f32 "
                 "{%0,%1,%2,%3}, {%4,%5,%6,%7}, {%8,%9}, {%0,%1,%2,%3};"
                 : "+f"(c[0]), "+f"(c[1]), "+f"(c[2]), "+f"(c[3])
                 : "r"(a[0]), "r"(a[1]), "r"(a[2]), "r"(a[3]), "r"(b[0]), "r"(b[1]));
}

__device__ __forceinline__ uint32_t swz(uint32_t x) { return x ^ ((x >> 3) & 0x70u); }

// ---------------------------------------------------------------------------
// Split fp32 -> hi/lo fp16
// ---------------------------------------------------------------------------
__global__ __launch_bounds__(256) void split_fp16(
    const float* __restrict__ x, __half* __restrict__ hi,
    __half* __restrict__ lo, int n)
{
    int i = (blockIdx.x * 256 + threadIdx.x) * 4;
    if (i >= n) return;
    float4 v = *(const float4*)(x + i);
    __half h0 = __float2half_rn(v.x);
    __half h1 = __float2half_rn(v.y);
    __half h2 = __float2half_rn(v.z);
    __half h3 = __float2half_rn(v.w);
    ((__half2*)(hi + i))[0] = __half2(h0, h1);
    ((__half2*)(hi + i))[1] = __half2(h2, h3);
    ((__half2*)(lo + i))[0] = __half2(
        __float2half_rn(v.x - __half2float(h0)),
        __float2half_rn(v.y - __half2float(h1)));
    ((__half2*)(lo + i))[1] = __half2(
        __float2half_rn(v.z - __half2float(h2)),
        __float2half_rn(v.w - __half2float(h3)));
}

// ---------------------------------------------------------------------------
// Transpose: w [K,N] fp32 -> wT [N,K] plain fp16
// ---------------------------------------------------------------------------
__global__ __launch_bounds__(256) void transpose_fp16(
    const float* __restrict__ w, __half* __restrict__ wt, int K, int N)
{
    __shared__ float t[32][33];
    int n0 = blockIdx.x * 32, k0 = blockIdx.y * 32;
    int tx = threadIdx.x & 31, ty = threadIdx.x >> 5;
    #pragma unroll
    for (int r = ty; r < 32; r += 8)
        t[r][tx] = w[(size_t)(k0 + r) * N + n0 + tx];
    __syncthreads();
    #pragma unroll
    for (int r = ty; r < 32; r += 8)
        wt[(size_t)(n0 + r) * K + k0 + tx] = __float2half_rn(t[tx][r]);
}

// ---------------------------------------------------------------------------
// mma.sync fp16 2-product GEMM: C = (Ahi+Alo) @ B^T + bias
// CTA 128x128, K-chunk 64 (SW128), 3-stage cp.async pipeline.
// ---------------------------------------------------------------------------
#define GTM 128
#define GTN 128
#define GKC 64
#define MAT_B 16384u
#define STAGE_B (3u * MAT_B)      // Ahi | Alo | B = 48 KB
#define GEMM_SMEM (3 * STAGE_B)   // 147456 bytes (3 stages)

__device__ __forceinline__ void load_chunk3(
    uint32_t sb, int buf,
    const __half* a0, const __half* a1, const __half* b0,
    int k0, int tid, int K)
{
    const __half* srcs[3] = {a0 + k0, a1 + k0, b0 + k0};
    uint32_t stage = sb + (uint32_t)buf * STAGE_B;
    #pragma unroll
    for (int mat = 0; mat < 3; mat++) {
        uint32_t tbase = stage + (uint32_t)mat * MAT_B;
        const __half* s = srcs[mat];
        #pragma unroll
        for (int i = 0; i < 4; i++) {
            int g = tid + i * 256;
            int row = g >> 3;
            int c16 = g & 7;
            uint32_t boff = (uint32_t)(row * 128 + c16 * 16);
            CP_ASYNC16(tbase + swz(boff), s + (size_t)row * K + c16 * 8);
        }
    }
}

__global__ __launch_bounds__(256) void gemm_mma_f16x2(
    const __half* __restrict__ Ahi, const __half* __restrict__ Alo,
    const __half* __restrict__ B,
    const float* __restrict__ bias, float* __restrict__ C, int K, int N)
{
    extern __shared__ char smem[];
    uint32_t sb = smem_u32(smem);
    const int tid = threadIdx.x;
    const int lane = tid & 31;
    const int wid = tid >> 5;
    const int wm = wid >> 2;
    const int wn = wid & 3;
    const int m0 = blockIdx.y * GTM;
    const int n0 = blockIdx.x * GTN;

    const __half* a0 = Ahi + (size_t)m0 * K;
    const __half* a1 = Alo + (size_t)m0 * K;
    const __half* b0 = B + (size_t)n0 * K;

    float acc[4][4][4];
    #pragma unroll
    for (int i = 0; i < 4; i++)
        #pragma unroll
        for (int j = 0; j < 4; j++)
            #pragma unroll
            for (int t = 0; t < 4; t++) acc[i][j][t] = 0.f;

    const int a_row_l = (lane & 7) + ((lane >> 3) & 1) * 8;
    const int a_c16_l = (lane >> 4);
    const int b_row_l = (lane & 7);
    const int b_c16_l = ((lane >> 3) & 1);

    const int nch = K / GKC;

    load_chunk3(sb, 0, a0, a1, b0, 0, tid, K);
    CP_COMMIT();
    load_chunk3(sb, 1, a0, a1, b0, GKC, tid, K);
    CP_COMMIT();

    int buf = 0;
    for (int it = 0; it < nch; it++) {
        if (it + 2 < nch) {
            int nb = buf + 2; if (nb >= 3) nb -= 3;
            load_chunk3(sb, nb, a0, a1, b0, (it + 2) * GKC, tid, K);
            CP_COMMIT();
            CP_WAIT(2);
        } else if (it + 1 < nch) {
            CP_WAIT(1);
        } else {
            CP_WAIT(0);
        }
        __syncthreads();

        uint32_t stage = sb + (uint32_t)buf * STAGE_B;
        uint32_t sAhi = stage;
        uint32_t sAlo = stage + MAT_B;
        uint32_t sB   = stage + 2 * MAT_B;

        #pragma unroll
        for (int ks = 0; ks < 4; ks++) {
            uint32_t bb[4][2];
            #pragma unroll
            for (int nt = 0; nt < 4; nt++) {
                uint32_t boff = (uint32_t)((wn * 32 + nt * 8 + b_row_l) * 128 +
                                           (ks * 2 + b_c16_l) * 16);
                uint32_t so = swz(boff);
                ldsm_x2(bb[nt][0], bb[nt][1], sB + so);
            }
            #pragma unroll
            for (int mt = 0; mt < 4; mt++) {
                uint32_t boff = (uint32_t)((wm * 64 + mt * 16 + a_row_l) * 128 +
                                           (ks * 2 + a_c16_l) * 16);
                uint32_t so = swz(boff);
                uint32_t ahi[4], alo[4];
                ldsm_x4(ahi[0], ahi[1], ahi[2], ahi[3], sAhi + so);
                ldsm_x4(alo[0], alo[1], alo[2], alo[3], sAlo + so);
                #pragma unroll
                for (int nt = 0; nt < 4; nt++) {
                    mma16816h(acc[mt][nt], ahi, bb[nt]);
                    mma16816h(acc[mt][nt], alo, bb[nt]);
                }
            }
        }
        __syncthreads();
        buf++; if (buf == 3) buf = 0;
    }

    const int r_base = m0 + wm * 64 + (lane >> 2);
    const int c_base = n0 + wn * 32 + (lane & 3) * 2;
    #pragma unroll
    for (int mt = 0; mt < 4; mt++) {
        #pragma unroll
        for (int nt = 0; nt < 4; nt++) {
            int col = c_base + nt * 8;
            float bx = bias[col], by = bias[col + 1];
            int r0 = r_base + mt * 16;
            float2 v0 = {acc[mt][nt][0] + bx, acc[mt][nt][1] + by};
            float2 v1 = {acc[mt][nt][2] + bx, acc[mt][nt][3] + by};
            *(float2*)(C + (size_t)r0 * N + col) = v0;
            *(float2*)(C + (size_t)(r0 + 8) * N + col) = v1;
        }
    }
}

// ---------------------------------------------------------------------------
// RoPE + split-fp16 scatter for Q (scaled) and K: [v][h][p][d]
// ---------------------------------------------------------------------------
__global__ __launch_bounds__(256) void rope_scatter(
    const float* __restrict__ qkv, const float* __restrict__ rope)
{
    int idx = blockIdx.x * 256 + threadIdx.x;
    if (idx >= VB * PP * HH * 40) return;
    int d = idx % 40;
    int h = (idx / 40) % HH;
    int p = (idx / (40 * HH)) % PP;
    int v = idx / (40 * HH * PP);

    size_t row = (size_t)v * PP + p;
    const float* qr = qkv + row * N_QKV + h * HD;
    const float* kr = qr + DD;
    const float* rp = rope + row * (2 * HD);

    float c0 = rp[d],      c1 = rp[d + 40];
    float s0 = rp[HD + d], s1 = rp[HD + d + 40];
    float q0 = qr[d], q1 = qr[d + 40];
    float k0 = kr[d], k1 = kr[d + 40];

    float qa = (q0 * c0 - q1 * s0) * QK_SCALE;
    float qb = (q1 * c1 + q0 * s1) * QK_SCALE;
    float ka = k0 * c0 - k1 * s0;
    float kb = k1 * c1 + k0 * s1;

    size_t ob = (((size_t)v * HH + h) * PP + p) * HD;
    __half hqa = __float2half_rn(qa);
    __half hqb = __float2half_rn(qb);
    __half hka = __float2half_rn(ka);
    __half hkb = __float2half_rn(kb);
    g_qhi2[ob + d]      = hqa;
    g_qhi2[ob + d + 40] = hqb;
    g_qlo2[ob + d]      = __float2half_rn(qa - __half2float(hqa));
    g_qlo2[ob + d + 40] = __float2half_rn(qb - __half2float(hqb));
    g_khi2[ob + d]      = hka;
    g_khi2[ob + d + 40] = hkb;
    g_klo2[ob + d]      = __float2half_rn(ka - __half2float(hka));
    g_klo2[ob + d + 40] = __float2half_rn(kb - __half2float(hkb));
}

// ---------------------------------------------------------------------------
// V transpose: g_qkv V-part [v][p][h*80+d] -> g_vt [v][h][d][p] fp16
// ---------------------------------------------------------------------------
__global__ __launch_bounds__(256) void v_transpose(const float* __restrict__ qkv)
{
    __shared__ float t[32][33];
    int vh = blockIdx.z;
    int v = vh >> 4, h = vh & 15;
    int p0 = blockIdx.x * 32;
    int d0 = blockIdx.y * 32;
    int tx = threadIdx.x & 31, ty = threadIdx.x >> 5;
    #pragma unroll
    for (int r = ty; r < 32; r += 8) {
        int d = d0 + tx;
        if (d < HD)
            t[r][tx] = qkv[((size_t)v * PP + p0 + r) * N_QKV + 2 * DD + h * HD + d];
    }
    __syncthreads();
    #pragma unroll
    for (int r = ty; r < 32; r += 8) {
        int d = d0 + r;
        if (d < HD)
            g_vt[((size_t)vh * HD + d) * PP + p0 + tx] = __float2half_rn(t[tx][r]);
    }
}

// ---------------------------------------------------------------------------
// Tensor-core flash attention: QK 3-product (Q split, K split), PV fp16,
// fused split-fp16 epilogue for proj GEMM.
// Smem (halves): Qhi[128][88] Qlo[128][88] | Khi[2][64][88] Klo[2][64][88] | Vt[2][80][72]
// ---------------------------------------------------------------------------
#define SQ 88
#define SV 72
#define ATTN_SMEM 113152

__global__ __launch_bounds__(256) void attn_mma(const int* __restrict__ valid_lens)
{
    extern __shared__ char smem[];
    uint32_t sb = smem_u32(smem);
    const int tid = threadIdx.x;
    const int lane = tid & 31;
    const int wq = tid >> 5;
    const int q0 = blockIdx.x * 128;
    const int h = blockIdx.y;
    const int v = blockIdx.z;
    int L = valid_lens[v];
    if (L < 1) L = 1;

    const size_t hb = ((size_t)(v * HH + h)) * PP * HD;
    const __half* qhi = g_qhi2 + hb + (size_t)q0 * HD;
    const __half* qlo = g_qlo2 + hb + (size_t)q0 * HD;
    const __half* khi = g_khi2 + hb;
    const __half* klo = g_klo2 + hb;
    const __half* vtp = g_vt + hb;   // [80][2048]

    const uint32_t bQHI = sb;
    const uint32_t bQLO = sb + 22528u;
    const uint32_t bKHI = sb + 45056u;
    const uint32_t bKLO = sb + 67584u;
    const uint32_t bVT  = sb + 90112u;

    for (int i = tid; i < 1280; i += 256) {
        int r = i / 10, g = i % 10;
        uint32_t off = (uint32_t)(r * SQ + g * 8) * 2;
        CP_ASYNC16(bQHI + off, qhi + (size_t)r * HD + g * 8);
        CP_ASYNC16(bQLO + off, qlo + (size_t)r * HD + g * 8);
    }
    {
        for (int i = tid; i < 640; i += 256) {
            int r = i / 10, g = i % 10;
            uint32_t off = (uint32_t)(r * SQ + g * 8) * 2;
            CP_ASYNC16(bKHI + off, khi + (size_t)r * HD + g * 8);
            CP_ASYNC16(bKLO + off, klo + (size_t)r * HD + g * 8);
        }
        for (int i = tid; i < 640; i += 256) {
            int d = i / 8, g = i % 8;
            CP_ASYNC16(bVT + (uint32_t)(d * SV + g * 8) * 2, vtp + (size_t)d * PP + g * 8);
        }
    }
    CP_COMMIT();

    float m_lo = -1e30f, m_hi = -1e30f, l_lo = 0.f, l_hi = 0.f;
    float o[10][4];
    #pragma unroll
    for (int i = 0; i < 10; i++)
        #pragma unroll
        for (int j = 0; j < 4; j++) o[i][j] = 0.f;

    const int a_row = wq * 16 + (lane & 7) + ((lane >> 3) & 1) * 8;
    const int a_c16 = (lane >> 4);
    const int b_row = (lane & 7);
    const int b_c16 = (lane >> 3) & 1;
    const int gc = lane & 3;

    const int nkt = (L + 63) >> 6;
    for (int kt = 0; kt < nkt; kt++) {
        const int b = kt & 1;
        if (kt + 1 < nkt) {
            const int kn = (kt + 1) * 64;
            const uint32_t kh = bKHI + (uint32_t)(b ^ 1) * 11264u;
            const uint32_t kl = bKLO + (uint32_t)(b ^ 1) * 11264u;
            const uint32_t vb = bVT + (uint32_t)(b ^ 1) * 11520u;
            for (int i = tid; i < 640; i += 256) {
                int r = i / 10, g = i % 10;
                uint32_t off = (uint32_t)(r * SQ + g * 8) * 2;
                CP_ASYNC16(kh + off, khi + (size_t)(kn + r) * HD + g * 8);
                CP_ASYNC16(kl + off, klo + (size_t)(kn + r) * HD + g * 8);
            }
            for (int i = tid; i < 640; i += 256) {
                int d = i / 8, g = i % 8;
                CP_ASYNC16(vb + (uint32_t)(d * SV + g * 8) * 2,
                           vtp + (size_t)d * PP + kn + g * 8);
            }
            CP_COMMIT();
            CP_WAIT(1);
        } else {
            CP_WAIT(0);
        }
        __syncthreads();

        const uint32_t khb = bKHI + (uint32_t)b * 11264u;
        const uint32_t klb = bKLO + (uint32_t)b * 11264u;
        const uint32_t vtb = bVT + (uint32_t)b * 11520u;

        float s[8][4];
        #pragma unroll
        for (int nt = 0; nt < 8; nt++)
            #pragma unroll
            for (int j = 0; j < 4; j++) s[nt][j] = 0.f;

        #pragma unroll
        for (int kc = 0; kc < 5; kc++) {
            uint32_t qh[4], ql[4];
            uint32_t qoff = (uint32_t)(a_row * SQ + kc * 16 + a_c16 * 8) * 2;
            ldsm_x4(qh[0], qh[1], qh[2], qh[3], bQHI + qoff);
            ldsm_x4(ql[0], ql[1], ql[2], ql[3], bQLO + qoff);
            #pragma unroll
            for (int nt = 0; nt < 8; nt++) {
                uint32_t koff = (uint32_t)((nt * 8 + b_row) * SQ + kc * 16 + b_c16 * 8) * 2;
                uint32_t kh[2], kl[2];
                ldsm_x2(kh[0], kh[1], khb + koff);
                ldsm_x2(kl[0], kl[1], klb + koff);
                mma16816h(s[nt], qh, kh);
                mma16816h(s[nt], qh, kl);
                mma16816h(s[nt], ql, kh);
            }
        }

        const int k0 = kt * 64;
        if (k0 + 64 > L) {
            #pragma unroll
            for (int nt = 0; nt < 8; nt++) {
                int kb0 = k0 + nt * 8 + gc * 2;
                if (kb0 >= L)     { s[nt][0] = -1e30f; s[nt][2] = -1e30f; }
                if (kb0 + 1 >= L) { s[nt][1] = -1e30f; s[nt][3] = -1e30f; }
            }
        }

        float mt_lo = -1e30f, mt_hi = -1e30f;
        #pragma unroll
        for (int nt = 0; nt < 8; nt++) {
            mt_lo = fmaxf(mt_lo, fmaxf(s[nt][0], s[nt][1]));
            mt_hi = fmaxf(mt_hi, fmaxf(s[nt][2], s[nt][3]));
        }
        mt_lo = fmaxf(mt_lo, __shfl_xor_sync(0xffffffffu, mt_lo, 1));
        mt_lo = fmaxf(mt_lo, __shfl_xor_sync(0xffffffffu, mt_lo, 2));
        mt_hi = fmaxf(mt_hi, __shfl_xor_sync(0xffffffffu, mt_hi, 1));
        mt_hi = fmaxf(mt_hi, __shfl_xor_sync(0xffffffffu, mt_hi, 2));

        float mn_lo = fmaxf(m_lo, mt_lo), mn_hi = fmaxf(m_hi, mt_hi);
        float al = __expf(m_lo - mn_lo), ah = __expf(m_hi - mn_hi);
        m_lo = mn_lo; m_hi = mn_hi;

        float sum_lo = 0.f, sum_hi = 0.f;
        #pragma unroll
        for (int nt = 0; nt < 8; nt++) {
            s[nt][0] = __expf(s[nt][0] - mn_lo);
            s[nt][1] = __expf(s[nt][1] - mn_lo);
            s[nt][2] = __expf(s[nt][2] - mn_hi);
            s[nt][3] = __expf(s[nt][3] - mn_hi);
            sum_lo += s[nt][0] + s[nt][1];
            sum_hi += s[nt][2] + s[nt][3];
        }
        sum_lo += __shfl_xor_sync(0xffffffffu, sum_lo, 1);
        sum_lo += __shfl_xor_sync(0xffffffffu, sum_lo, 2);
        sum_hi += __shfl_xor_sync(0xffffffffu, sum_hi, 1);
        sum_hi += __shfl_xor_sync(0xffffffffu, sum_hi, 2);
        l_lo = l_lo * al + sum_lo;
        l_hi = l_hi * ah + sum_hi;

        #pragma unroll
        for (int nt = 0; nt < 10; nt++) {
            o[nt][0] *= al; o[nt][1] *= al;
            o[nt][2] *= ah; o[nt][3] *= ah;
        }

        uint32_t pa[4][4];
        #pragma unroll
        for (int kc = 0; kc < 4; kc++) {
            __half2 t0 = __floats2half2_rn(s[2 * kc][0], s[2 * kc][1]);
            __half2 t1 = __floats2half2_rn(s[2 * kc][2], s[2 * kc][3]);
            __half2 t2 = __floats2half2_rn(s[2 * kc + 1][0], s[2 * kc + 1][1]);
            __half2 t3 = __floats2half2_rn(s[2 * kc + 1][2], s[2 * kc + 1][3]);
            pa[kc][0] = *(uint32_t*)&t0;
            pa[kc][1] = *(uint32_t*)&t1;
            pa[kc][2] = *(uint32_t*)&t2;
            pa[kc][3] = *(uint32_t*)&t3;
        }

        #pragma unroll
        for (int nt = 0; nt < 10; nt++) {
            #pragma unroll
            for (int kc = 0; kc < 4; kc++) {
                uint32_t voff = (uint32_t)((nt * 8 + b_row) * SV + kc * 16 + b_c16 * 8) * 2;
                uint32_t vv[2];
                ldsm_x2(vv[0], vv[1], vtb + voff);
                mma16816h(o[nt], pa[kc], vv);
            }
        }
        __syncthreads();
    }

    // Epilogue: write split fp16 hi/lo directly (fused split for proj GEMM)
    float inv_lo = 1.f / l_lo, inv_hi = 1.f / l_hi;
    int row_lo = q0 + wq * 16 + (lane >> 2);
    #pragma unroll
    for (int nt = 0; nt < 10; nt++) {
        int col = h * HD + nt * 8 + gc * 2;
        size_t off0 = ((size_t)v * PP + row_lo) * DD + col;
        size_t off1 = ((size_t)v * PP + row_lo + 8) * DD + col;
        float v00 = o[nt][0] * inv_lo, v01 = o[nt][1] * inv_lo;
        float v10 = o[nt][2] * inv_hi, v11 = o[nt][3] * inv_hi;
        __half h00 = __float2half_rn(v00);
        __half h01 = __float2half_rn(v01);
        __half h10 = __float2half_rn(v10);
        __half h11 = __float2half_rn(v11);
        *(__half2*)(g_ahi + off0) = __half2(h00, h01);
        *(__half2*)(g_ahi + off1) = __half2(h10, h11);
        *(__half2*)(g_alo + off0) = __half2(
            __float2half_rn(v00 - __half2float(h00)),
            __float2half_rn(v01 - __half2float(h01)));
        *(__half2*)(g_alo + off1) = __half2(
            __float2half_rn(v10 - __half2float(h10)),
            __float2half_rn(v11 - __half2float(h11)));
    }
}

// ---------------------------------------------------------------------------
// Launch — ordered so the QKV GEMM is the 4th launch (ncu capture slot)
// ---------------------------------------------------------------------------
extern "C" void kernel_launch(void* const* d_in, const int* in_sizes, int n_in,
                              void* d_out, int out_size)
{
    const float* hs    = (const float*)d_in[0];
    const float* rope  = (const float*)d_in[1];
    const int*   vlens = (const int*)d_in[2];
    const float* wqkv  = (const float*)d_in[3];
    const float* bqkv  = (const float*)d_in[4];
    const float* wproj = (const float*)d_in[5];
    const float* bproj = (const float*)d_in[6];
    float* out = (float*)d_out;

    float* p_qkv;
    __half *p_ahi, *p_alo, *p_bh, *p_ph;
    cudaGetSymbolAddress((void**)&p_qkv, g_qkv);
    cudaGetSymbolAddress((void**)&p_ahi, g_ahi);
    cudaGetSymbolAddress((void**)&p_alo, g_alo);
    cudaGetSymbolAddress((void**)&p_bh,  g_bh);
    cudaGetSymbolAddress((void**)&p_ph,  g_ph);

    cudaFuncSetAttribute(gemm_mma_f16x2,
                         cudaFuncAttributeMaxDynamicSharedMemorySize, GEMM_SMEM);
    cudaFuncSetAttribute(attn_mma,
                         cudaFuncAttributeMaxDynamicSharedMemorySize, ATTN_SMEM);

    // 1) Split hidden states (fp16 hi/lo)
    {
        int n = M_ROWS * DD;
        split_fp16<<<(n / 4 + 255) / 256, 256>>>(hs, p_ahi, p_alo, n);
    }
    // 2) Transpose W_qkv (plain fp16)
    transpose_fp16<<<dim3(N_QKV / 32, DD / 32), 256>>>(wqkv, p_bh, DD, N_QKV);
    // 3) Transpose W_proj (plain fp16)
    transpose_fp16<<<dim3(DD / 32, DD / 32), 256>>>(wproj, p_ph, DD, DD);

    // 4) QKV GEMM (fp16 2-product)  <-- ncu capture slot
    gemm_mma_f16x2<<<dim3(N_QKV / GTN, M_ROWS / GTM), 256, GEMM_SMEM>>>(
        p_ahi, p_alo, p_bh, bqkv, p_qkv, DD, N_QKV);

    // 5) RoPE (Q split fp16 scaled, K split fp16)
    {
        int total = VB * PP * HH * 40;
        rope_scatter<<<(total + 255) / 256, 256>>>(p_qkv, rope);
    }
    // 6) V transpose (fp16)
    v_transpose<<<dim3(PP / 32, 3, VB * HH), 256>>>(p_qkv);

    // 7) Tensor-core flash attention (3-product QK, writes split fp16)
    attn_mma<<<dim3(PP / 128, HH, VB), 256, ATTN_SMEM>>>(vlens);

    // 8) Output projection (fp16 2-product)
    gemm_mma_f16x2<<<dim3(DD / GTN, M_ROWS / GTM), 256, GEMM_SMEM>>>(
        p_ahi, p_alo, p_ph, bproj, out, DD, DD);
}

// round 13
// speedup vs baseline: 1.4162x; 1.0966x over previous
#include <cuda_runtime.h>
#include <cuda_bf16.h>
#include <cuda_fp16.h>
#include <cstdint>

// Problem constants
#define VB 4
#define PP 2048
#define DD 1280
#define HH 16
#define HD 80
#define M_ROWS (VB * PP)     // 8192
#define N_QKV  (3 * DD)      // 3840
#define QK_SCALE 0.111803398874989484f

// ---------------------------------------------------------------------------
// Scratch (static device globals — allocation-guard safe)
// ---------------------------------------------------------------------------
__device__ float g_qkv[M_ROWS * N_QKV];               // [8192, 3840] fp32
__device__ __align__(16) __half g_ahi[M_ROWS * DD];   // split A (hs, then attn out)
__device__ __align__(16) __half g_alo[M_ROWS * DD];
__device__ __align__(16) __half g_bh[N_QKV * DD];     // W_qkv^T [N,K] plain fp16
__device__ __align__(16) __half g_ph[DD * DD];        // W_proj^T [N,K] plain fp16
// fp16 attention operands
__device__ __align__(16) __half g_qhi2[VB * HH * PP * HD];  // [v][h][p][d], scaled
__device__ __align__(16) __half g_qlo2[VB * HH * PP * HD];
__device__ __align__(16) __half g_khi2[VB * HH * PP * HD];
__device__ __align__(16) __half g_klo2[VB * HH * PP * HD];
__device__ __align__(16) __half g_vt[VB * HH * HD * PP];    // [v][h][d][p]

// ---------------------------------------------------------------------------
// Helpers
// ---------------------------------------------------------------------------
__device__ __forceinline__ uint32_t smem_u32(const void* p) {
    uint32_t a;
    asm("{ .reg .u64 t; cvta.to.shared.u64 t, %1; cvt.u32.u64 %0, t; }" : "=r"(a) : "l"(p));
    return a;
}

#define CP_ASYNC16(dst, src) \
    asm volatile("cp.async.cg.shared.global [%0], [%1], 16;" :: "r"(dst), "l"(src))
#define CP_COMMIT() asm volatile("cp.async.commit_group;" ::: "memory")
#define CP_WAIT(n)  asm volatile("cp.async.wait_group %0;" :: "n"(n) : "memory")

__device__ __forceinline__ void ldsm_x4(uint32_t& r0, uint32_t& r1, uint32_t& r2, uint32_t& r3,
                                        uint32_t addr) {
    asm volatile("ldmatrix.sync.aligned.m8n8.x4.shared.b16 {%0,%1,%2,%3}, [%4];"
                 : "=r"(r0), "=r"(r1), "=r"(r2), "=r"(r3) : "r"(addr));
}
__device__ __forceinline__ void ldsm_x2(uint32_t& r0, uint32_t& r1, uint32_t addr) {
    asm volatile("ldmatrix.sync.aligned.m8n8.x2.shared.b16 {%0,%1}, [%2];"
                 : "=r"(r0), "=r"(r1) : "r"(addr));
}
__device__ __forceinline__ void mma16816h(float* c, const uint32_t* a, const uint32_t* b) {
    asm volatile("mma.sync.aligned.m16n8k16.row.col.f32.f16.f16.f32 "
                 "{%0,%1,%2,%3}, {%4,%5,%6,%7}, {%8,%9}, {%0,%1,%2,%3};"
                 : "+f"(c[0]), "+f"(c[1]), "+f"(c[2]), "+f"(c[3])
                 : "r"(a[0]), "r"(a[1]), "r"(a[2]), "r"(a[3]), "r"(b[0]), "r"(b[1]));
}

__device__ __forceinline__ uint32_t swz(uint32_t x) { return x ^ ((x >> 3) & 0x70u); }

// ---------------------------------------------------------------------------
// Split fp32 -> hi/lo fp16
// ---------------------------------------------------------------------------
__global__ __launch_bounds__(256) void split_fp16(
    const float* __restrict__ x, __half* __restrict__ hi,
    __half* __restrict__ lo, int n)
{
    int i = (blockIdx.x * 256 + threadIdx.x) * 4;
    if (i >= n) return;
    float4 v = *(const float4*)(x + i);
    __half h0 = __float2half_rn(v.x);
    __half h1 = __float2half_rn(v.y);
    __half h2 = __float2half_rn(v.z);
    __half h3 = __float2half_rn(v.w);
    ((__half2*)(hi + i))[0] = __half2(h0, h1);
    ((__half2*)(hi + i))[1] = __half2(h2, h3);
    ((__half2*)(lo + i))[0] = __half2(
        __float2half_rn(v.x - __half2float(h0)),
        __float2half_rn(v.y - __half2float(h1)));
    ((__half2*)(lo + i))[1] = __half2(
        __float2half_rn(v.z - __half2float(h2)),
        __float2half_rn(v.w - __half2float(h3)));
}

// ---------------------------------------------------------------------------
// Transpose: w [K,N] fp32 -> wT [N,K] plain fp16
// ---------------------------------------------------------------------------
__global__ __launch_bounds__(256) void transpose_fp16(
    const float* __restrict__ w, __half* __restrict__ wt, int K, int N)
{
    __shared__ float t[32][33];
    int n0 = blockIdx.x * 32, k0 = blockIdx.y * 32;
    int tx = threadIdx.x & 31, ty = threadIdx.x >> 5;
    #pragma unroll
    for (int r = ty; r < 32; r += 8)
        t[r][tx] = w[(size_t)(k0 + r) * N + n0 + tx];
    __syncthreads();
    #pragma unroll
    for (int r = ty; r < 32; r += 8)
        wt[(size_t)(n0 + r) * K + k0 + tx] = __float2half_rn(t[tx][r]);
}

// ---------------------------------------------------------------------------
// mma.sync fp16 2-product GEMM: C = (Ahi+Alo) @ B^T + bias
// CTA 128x128, K-chunk 64 (SW128), 2-stage pipeline, 2 CTAs/SM (96 KB smem).
// ---------------------------------------------------------------------------
#define GTM 128
#define GTN 128
#define GKC 64
#define MAT_B 16384u
#define STAGE_B (3u * MAT_B)      // Ahi | Alo | B = 48 KB
#define GEMM_SMEM (2 * STAGE_B)   // 98304 bytes (2 stages -> 2 CTAs/SM)

__device__ __forceinline__ void load_chunk3(
    uint32_t sb, int buf,
    const __half* a0, const __half* a1, const __half* b0,
    int k0, int tid, int K)
{
    const __half* srcs[3] = {a0 + k0, a1 + k0, b0 + k0};
    uint32_t stage = sb + (uint32_t)buf * STAGE_B;
    #pragma unroll
    for (int mat = 0; mat < 3; mat++) {
        uint32_t tbase = stage + (uint32_t)mat * MAT_B;
        const __half* s = srcs[mat];
        #pragma unroll
        for (int i = 0; i < 4; i++) {
            int g = tid + i * 256;
            int row = g >> 3;
            int c16 = g & 7;
            uint32_t boff = (uint32_t)(row * 128 + c16 * 16);
            CP_ASYNC16(tbase + swz(boff), s + (size_t)row * K + c16 * 8);
        }
    }
}

__global__ __launch_bounds__(256, 2) void gemm_mma_f16x2(
    const __half* __restrict__ Ahi, const __half* __restrict__ Alo,
    const __half* __restrict__ B,
    const float* __restrict__ bias, float* __restrict__ C, int K, int N)
{
    extern __shared__ char smem[];
    uint32_t sb = smem_u32(smem);
    const int tid = threadIdx.x;
    const int lane = tid & 31;
    const int wid = tid >> 5;
    const int wm = wid >> 2;
    const int wn = wid & 3;
    const int m0 = blockIdx.y * GTM;
    const int n0 = blockIdx.x * GTN;

    const __half* a0 = Ahi + (size_t)m0 * K;
    const __half* a1 = Alo + (size_t)m0 * K;
    const __half* b0 = B + (size_t)n0 * K;

    float acc[4][4][4];
    #pragma unroll
    for (int i = 0; i < 4; i++)
        #pragma unroll
        for (int j = 0; j < 4; j++)
            #pragma unroll
            for (int t = 0; t < 4; t++) acc[i][j][t] = 0.f;

    const int a_row_l = (lane & 7) + ((lane >> 3) & 1) * 8;
    const int a_c16_l = (lane >> 4);
    const int b_row_l = (lane & 7);
    const int b_c16_l = ((lane >> 3) & 1);

    const int nch = K / GKC;

    load_chunk3(sb, 0, a0, a1, b0, 0, tid, K);
    CP_COMMIT();

    for (int it = 0; it < nch; it++) {
        const int b = it & 1;
        if (it + 1 < nch) {
            load_chunk3(sb, b ^ 1, a0, a1, b0, (it + 1) * GKC, tid, K);
            CP_COMMIT();
            CP_WAIT(1);
        } else {
            CP_WAIT(0);
        }
        __syncthreads();

        uint32_t stage = sb + (uint32_t)b * STAGE_B;
        uint32_t sAhi = stage;
        uint32_t sAlo = stage + MAT_B;
        uint32_t sB   = stage + 2 * MAT_B;

        #pragma unroll
        for (int ks = 0; ks < 4; ks++) {
            uint32_t bb[4][2];
            #pragma unroll
            for (int nt = 0; nt < 4; nt++) {
                uint32_t boff = (uint32_t)((wn * 32 + nt * 8 + b_row_l) * 128 +
                                           (ks * 2 + b_c16_l) * 16);
                uint32_t so = swz(boff);
                ldsm_x2(bb[nt][0], bb[nt][1], sB + so);
            }
            #pragma unroll
            for (int mt = 0; mt < 4; mt++) {
                uint32_t boff = (uint32_t)((wm * 64 + mt * 16 + a_row_l) * 128 +
                                           (ks * 2 + a_c16_l) * 16);
                uint32_t so = swz(boff);
                uint32_t ahi[4], alo[4];
                ldsm_x4(ahi[0], ahi[1], ahi[2], ahi[3], sAhi + so);
                ldsm_x4(alo[0], alo[1], alo[2], alo[3], sAlo + so);
                #pragma unroll
                for (int nt = 0; nt < 4; nt++) {
                    mma16816h(acc[mt][nt], ahi, bb[nt]);
                    mma16816h(acc[mt][nt], alo, bb[nt]);
                }
            }
        }
        __syncthreads();
    }

    const int r_base = m0 + wm * 64 + (lane >> 2);
    const int c_base = n0 + wn * 32 + (lane & 3) * 2;
    #pragma unroll
    for (int mt = 0; mt < 4; mt++) {
        #pragma unroll
        for (int nt = 0; nt < 4; nt++) {
            int col = c_base + nt * 8;
            float bx = bias[col], by = bias[col + 1];
            int r0 = r_base + mt * 16;
            float2 v0 = {acc[mt][nt][0] + bx, acc[mt][nt][1] + by};
            float2 v1 = {acc[mt][nt][2] + bx, acc[mt][nt][3] + by};
            *(float2*)(C + (size_t)r0 * N + col) = v0;
            *(float2*)(C + (size_t)(r0 + 8) * N + col) = v1;
        }
    }
}

// ---------------------------------------------------------------------------
// RoPE + split-fp16 scatter for Q (scaled) and K: [v][h][p][d]
// ---------------------------------------------------------------------------
__global__ __launch_bounds__(256) void rope_scatter(
    const float* __restrict__ qkv, const float* __restrict__ rope)
{
    int idx = blockIdx.x * 256 + threadIdx.x;
    if (idx >= VB * PP * HH * 40) return;
    int d = idx % 40;
    int h = (idx / 40) % HH;
    int p = (idx / (40 * HH)) % PP;
    int v = idx / (40 * HH * PP);

    size_t row = (size_t)v * PP + p;
    const float* qr = qkv + row * N_QKV + h * HD;
    const float* kr = qr + DD;
    const float* rp = rope + row * (2 * HD);

    float c0 = rp[d],      c1 = rp[d + 40];
    float s0 = rp[HD + d], s1 = rp[HD + d + 40];
    float q0 = qr[d], q1 = qr[d + 40];
    float k0 = kr[d], k1 = kr[d + 40];

    float qa = (q0 * c0 - q1 * s0) * QK_SCALE;
    float qb = (q1 * c1 + q0 * s1) * QK_SCALE;
    float ka = k0 * c0 - k1 * s0;
    float kb = k1 * c1 + k0 * s1;

    size_t ob = (((size_t)v * HH + h) * PP + p) * HD;
    __half hqa = __float2half_rn(qa);
    __half hqb = __float2half_rn(qb);
    __half hka = __float2half_rn(ka);
    __half hkb = __float2half_rn(kb);
    g_qhi2[ob + d]      = hqa;
    g_qhi2[ob + d + 40] = hqb;
    g_qlo2[ob + d]      = __float2half_rn(qa - __half2float(hqa));
    g_qlo2[ob + d + 40] = __float2half_rn(qb - __half2float(hqb));
    g_khi2[ob + d]      = hka;
    g_khi2[ob + d + 40] = hkb;
    g_klo2[ob + d]      = __float2half_rn(ka - __half2float(hka));
    g_klo2[ob + d + 40] = __float2half_rn(kb - __half2float(hkb));
}

// ---------------------------------------------------------------------------
// V transpose: g_qkv V-part [v][p][h*80+d] -> g_vt [v][h][d][p] fp16
// ---------------------------------------------------------------------------
__global__ __launch_bounds__(256) void v_transpose(const float* __restrict__ qkv)
{
    __shared__ float t[32][33];
    int vh = blockIdx.z;
    int v = vh >> 4, h = vh & 15;
    int p0 = blockIdx.x * 32;
    int d0 = blockIdx.y * 32;
    int tx = threadIdx.x & 31, ty = threadIdx.x >> 5;
    #pragma unroll
    for (int r = ty; r < 32; r += 8) {
        int d = d0 + tx;
        if (d < HD)
            t[r][tx] = qkv[((size_t)v * PP + p0 + r) * N_QKV + 2 * DD + h * HD + d];
    }
    __syncthreads();
    #pragma unroll
    for (int r = ty; r < 32; r += 8) {
        int d = d0 + r;
        if (d < HD)
            g_vt[((size_t)vh * HD + d) * PP + p0 + tx] = __float2half_rn(t[tx][r]);
    }
}

// ---------------------------------------------------------------------------
// Tensor-core flash attention: QK 3-product (Q split, K split), PV fp16,
// fused split-fp16 epilogue for proj GEMM.
// ---------------------------------------------------------------------------
#define SQ 88
#define SV 72
#define ATTN_SMEM 113152

__global__ __launch_bounds__(256) void attn_mma(const int* __restrict__ valid_lens)
{
    extern __shared__ char smem[];
    uint32_t sb = smem_u32(smem);
    const int tid = threadIdx.x;
    const int lane = tid & 31;
    const int wq = tid >> 5;
    const int q0 = blockIdx.x * 128;
    const int h = blockIdx.y;
    const int v = blockIdx.z;
    int L = valid_lens[v];
    if (L < 1) L = 1;

    const size_t hb = ((size_t)(v * HH + h)) * PP * HD;
    const __half* qhi = g_qhi2 + hb + (size_t)q0 * HD;
    const __half* qlo = g_qlo2 + hb + (size_t)q0 * HD;
    const __half* khi = g_khi2 + hb;
    const __half* klo = g_klo2 + hb;
    const __half* vtp = g_vt + hb;   // [80][2048]

    const uint32_t bQHI = sb;
    const uint32_t bQLO = sb + 22528u;
    const uint32_t bKHI = sb + 45056u;
    const uint32_t bKLO = sb + 67584u;
    const uint32_t bVT  = sb + 90112u;

    for (int i = tid; i < 1280; i += 256) {
        int r = i / 10, g = i % 10;
        uint32_t off = (uint32_t)(r * SQ + g * 8) * 2;
        CP_ASYNC16(bQHI + off, qhi + (size_t)r * HD + g * 8);
        CP_ASYNC16(bQLO + off, qlo + (size_t)r * HD + g * 8);
    }
    {
        for (int i = tid; i < 640; i += 256) {
            int r = i / 10, g = i % 10;
            uint32_t off = (uint32_t)(r * SQ + g * 8) * 2;
            CP_ASYNC16(bKHI + off, khi + (size_t)r * HD + g * 8);
            CP_ASYNC16(bKLO + off, klo + (size_t)r * HD + g * 8);
        }
        for (int i = tid; i < 640; i += 256) {
            int d = i / 8, g = i % 8;
            CP_ASYNC16(bVT + (uint32_t)(d * SV + g * 8) * 2, vtp + (size_t)d * PP + g * 8);
        }
    }
    CP_COMMIT();

    float m_lo = -1e30f, m_hi = -1e30f, l_lo = 0.f, l_hi = 0.f;
    float o[10][4];
    #pragma unroll
    for (int i = 0; i < 10; i++)
        #pragma unroll
        for (int j = 0; j < 4; j++) o[i][j] = 0.f;

    const int a_row = wq * 16 + (lane & 7) + ((lane >> 3) & 1) * 8;
    const int a_c16 = (lane >> 4);
    const int b_row = (lane & 7);
    const int b_c16 = (lane >> 3) & 1;
    const int gc = lane & 3;

    const int nkt = (L + 63) >> 6;
    for (int kt = 0; kt < nkt; kt++) {
        const int b = kt & 1;
        if (kt + 1 < nkt) {
            const int kn = (kt + 1) * 64;
            const uint32_t kh = bKHI + (uint32_t)(b ^ 1) * 11264u;
            const uint32_t kl = bKLO + (uint32_t)(b ^ 1) * 11264u;
            const uint32_t vb = bVT + (uint32_t)(b ^ 1) * 11520u;
            for (int i = tid; i < 640; i += 256) {
                int r = i / 10, g = i % 10;
                uint32_t off = (uint32_t)(r * SQ + g * 8) * 2;
                CP_ASYNC16(kh + off, khi + (size_t)(kn + r) * HD + g * 8);
                CP_ASYNC16(kl + off, klo + (size_t)(kn + r) * HD + g * 8);
            }
            for (int i = tid; i < 640; i += 256) {
                int d = i / 8, g = i % 8;
                CP_ASYNC16(vb + (uint32_t)(d * SV + g * 8) * 2,
                           vtp + (size_t)d * PP + kn + g * 8);
            }
            CP_COMMIT();
            CP_WAIT(1);
        } else {
            CP_WAIT(0);
        }
        __syncthreads();

        const uint32_t khb = bKHI + (uint32_t)b * 11264u;
        const uint32_t klb = bKLO + (uint32_t)b * 11264u;
        const uint32_t vtb = bVT + (uint32_t)b * 11520u;

        float s[8][4];
        #pragma unroll
        for (int nt = 0; nt < 8; nt++)
            #pragma unroll
            for (int j = 0; j < 4; j++) s[nt][j] = 0.f;

        #pragma unroll
        for (int kc = 0; kc < 5; kc++) {
            uint32_t qh[4], ql[4];
            uint32_t qoff = (uint32_t)(a_row * SQ + kc * 16 + a_c16 * 8) * 2;
            ldsm_x4(qh[0], qh[1], qh[2], qh[3], bQHI + qoff);
            ldsm_x4(ql[0], ql[1], ql[2], ql[3], bQLO + qoff);
            #pragma unroll
            for (int nt = 0; nt < 8; nt++) {
                uint32_t koff = (uint32_t)((nt * 8 + b_row) * SQ + kc * 16 + b_c16 * 8) * 2;
                uint32_t kh[2], kl[2];
                ldsm_x2(kh[0], kh[1], khb + koff);
                ldsm_x2(kl[0], kl[1], klb + koff);
                mma16816h(s[nt], qh, kh);
                mma16816h(s[nt], qh, kl);
                mma16816h(s[nt], ql, kh);
            }
        }

        const int k0 = kt * 64;
        if (k0 + 64 > L) {
            #pragma unroll
            for (int nt = 0; nt < 8; nt++) {
                int kb0 = k0 + nt * 8 + gc * 2;
                if (kb0 >= L)     { s[nt][0] = -1e30f; s[nt][2] = -1e30f; }
                if (kb0 + 1 >= L) { s[nt][1] = -1e30f; s[nt][3] = -1e30f; }
            }
        }

        float mt_lo = -1e30f, mt_hi = -1e30f;
        #pragma unroll
        for (int nt = 0; nt < 8; nt++) {
            mt_lo = fmaxf(mt_lo, fmaxf(s[nt][0], s[nt][1]));
            mt_hi = fmaxf(mt_hi, fmaxf(s[nt][2], s[nt][3]));
        }
        mt_lo = fmaxf(mt_lo, __shfl_xor_sync(0xffffffffu, mt_lo, 1));
        mt_lo = fmaxf(mt_lo, __shfl_xor_sync(0xffffffffu, mt_lo, 2));
        mt_hi = fmaxf(mt_hi, __shfl_xor_sync(0xffffffffu, mt_hi, 1));
        mt_hi = fmaxf(mt_hi, __shfl_xor_sync(0xffffffffu, mt_hi, 2));

        float mn_lo = fmaxf(m_lo, mt_lo), mn_hi = fmaxf(m_hi, mt_hi);
        float al = __expf(m_lo - mn_lo), ah = __expf(m_hi - mn_hi);
        m_lo = mn_lo; m_hi = mn_hi;

        float sum_lo = 0.f, sum_hi = 0.f;
        #pragma unroll
        for (int nt = 0; nt < 8; nt++) {
            s[nt][0] = __expf(s[nt][0] - mn_lo);
            s[nt][1] = __expf(s[nt][1] - mn_lo);
            s[nt][2] = __expf(s[nt][2] - mn_hi);
            s[nt][3] = __expf(s[nt][3] - mn_hi);
            sum_lo += s[nt][0] + s[nt][1];
            sum_hi += s[nt][2] + s[nt][3];
        }
        sum_lo += __shfl_xor_sync(0xffffffffu, sum_lo, 1);
        sum_lo += __shfl_xor_sync(0xffffffffu, sum_lo, 2);
        sum_hi += __shfl_xor_sync(0xffffffffu, sum_hi, 1);
        sum_hi += __shfl_xor_sync(0xffffffffu, sum_hi, 2);
        l_lo = l_lo * al + sum_lo;
        l_hi = l_hi * ah + sum_hi;

        #pragma unroll
        for (int nt = 0; nt < 10; nt++) {
            o[nt][0] *= al; o[nt][1] *= al;
            o[nt][2] *= ah; o[nt][3] *= ah;
        }

        uint32_t pa[4][4];
        #pragma unroll
        for (int kc = 0; kc < 4; kc++) {
            __half2 t0 = __floats2half2_rn(s[2 * kc][0], s[2 * kc][1]);
            __half2 t1 = __floats2half2_rn(s[2 * kc][2], s[2 * kc][3]);
            __half2 t2 = __floats2half2_rn(s[2 * kc + 1][0], s[2 * kc + 1][1]);
            __half2 t3 = __floats2half2_rn(s[2 * kc + 1][2], s[2 * kc + 1][3]);
            pa[kc][0] = *(uint32_t*)&t0;
            pa[kc][1] = *(uint32_t*)&t1;
            pa[kc][2] = *(uint32_t*)&t2;
            pa[kc][3] = *(uint32_t*)&t3;
        }

        #pragma unroll
        for (int nt = 0; nt < 10; nt++) {
            #pragma unroll
            for (int kc = 0; kc < 4; kc++) {
                uint32_t voff = (uint32_t)((nt * 8 + b_row) * SV + kc * 16 + b_c16 * 8) * 2;
                uint32_t vv[2];
                ldsm_x2(vv[0], vv[1], vtb + voff);
                mma16816h(o[nt], pa[kc], vv);
            }
        }
        __syncthreads();
    }

    // Epilogue: write split fp16 hi/lo directly (fused split for proj GEMM)
    float inv_lo = 1.f / l_lo, inv_hi = 1.f / l_hi;
    int row_lo = q0 + wq * 16 + (lane >> 2);
    #pragma unroll
    for (int nt = 0; nt < 10; nt++) {
        int col = h * HD + nt * 8 + gc * 2;
        size_t off0 = ((size_t)v * PP + row_lo) * DD + col;
        size_t off1 = ((size_t)v * PP + row_lo + 8) * DD + col;
        float v00 = o[nt][0] * inv_lo, v01 = o[nt][1] * inv_lo;
        float v10 = o[nt][2] * inv_hi, v11 = o[nt][3] * inv_hi;
        __half h00 = __float2half_rn(v00);
        __half h01 = __float2half_rn(v01);
        __half h10 = __float2half_rn(v10);
        __half h11 = __float2half_rn(v11);
        *(__half2*)(g_ahi + off0) = __half2(h00, h01);
        *(__half2*)(g_ahi + off1) = __half2(h10, h11);
        *(__half2*)(g_alo + off0) = __half2(
            __float2half_rn(v00 - __half2float(h00)),
            __float2half_rn(v01 - __half2float(h01)));
        *(__half2*)(g_alo + off1) = __half2(
            __float2half_rn(v10 - __half2float(h10)),
            __float2half_rn(v11 - __half2float(h11)));
    }
}

// ---------------------------------------------------------------------------
// Launch — ordered so the QKV GEMM is the 4th launch (ncu capture slot)
// ---------------------------------------------------------------------------
extern "C" void kernel_launch(void* const* d_in, const int* in_sizes, int n_in,
                              void* d_out, int out_size)
{
    const float* hs    = (const float*)d_in[0];
    const float* rope  = (const float*)d_in[1];
    const int*   vlens = (const int*)d_in[2];
    const float* wqkv  = (const float*)d_in[3];
    const float* bqkv  = (const float*)d_in[4];
    const float* wproj = (const float*)d_in[5];
    const float* bproj = (const float*)d_in[6];
    float* out = (float*)d_out;

    float* p_qkv;
    __half *p_ahi, *p_alo, *p_bh, *p_ph;
    cudaGetSymbolAddress((void**)&p_qkv, g_qkv);
    cudaGetSymbolAddress((void**)&p_ahi, g_ahi);
    cudaGetSymbolAddress((void**)&p_alo, g_alo);
    cudaGetSymbolAddress((void**)&p_bh,  g_bh);
    cudaGetSymbolAddress((void**)&p_ph,  g_ph);

    cudaFuncSetAttribute(gemm_mma_f16x2,
                         cudaFuncAttributeMaxDynamicSharedMemorySize, GEMM_SMEM);
    cudaFuncSetAttribute(attn_mma,
                         cudaFuncAttributeMaxDynamicSharedMemorySize, ATTN_SMEM);

    // 1) Split hidden states (fp16 hi/lo)
    {
        int n = M_ROWS * DD;
        split_fp16<<<(n / 4 + 255) / 256, 256>>>(hs, p_ahi, p_alo, n);
    }
    // 2) Transpose W_qkv (plain fp16)
    transpose_fp16<<<dim3(N_QKV / 32, DD / 32), 256>>>(wqkv, p_bh, DD, N_QKV);
    // 3) Transpose W_proj (plain fp16)
    transpose_fp16<<<dim3(DD / 32, DD / 32), 256>>>(wproj, p_ph, DD, DD);

    // 4) QKV GEMM (fp16 2-product, 2 CTAs/SM)  <-- ncu capture slot
    gemm_mma_f16x2<<<dim3(N_QKV / GTN, M_ROWS / GTM), 256, GEMM_SMEM>>>(
        p_ahi, p_alo, p_bh, bqkv, p_qkv, DD, N_QKV);

    // 5) RoPE (Q split fp16 scaled, K split fp16)
    {
        int total = VB * PP * HH * 40;
        rope_scatter<<<(total + 255) / 256, 256>>>(p_qkv, rope);
    }
    // 6) V transpose (fp16)
    v_transpose<<<dim3(PP / 32, 3, VB * HH), 256>>>(p_qkv);

    // 7) Tensor-core flash attention (3-product QK, writes split fp16)
    attn_mma<<<dim3(PP / 128, HH, VB), 256, ATTN_SMEM>>>(vlens);

    // 8) Output projection (fp16 2-product)
    gemm_mma_f16x2<<<dim3(DD / GTN, M_ROWS / GTM), 256, GEMM_SMEM>>>(
        p_ahi, p_alo, p_ph, bproj, out, DD, DD);
}

// round 14
// speedup vs baseline: 1.4629x; 1.0330x over previous
#include <cuda_runtime.h>
#include <cuda_bf16.h>
#include <cuda_fp16.h>
#include <cstdint>

// Problem constants
#define VB 4
#define PP 2048
#define DD 1280
#define HH 16
#define HD 80
#define M_ROWS (VB * PP)     // 8192
#define N_QKV  (3 * DD)      // 3840
#define QK_SCALE 0.111803398874989484f

// ---------------------------------------------------------------------------
// Scratch (static device globals — allocation-guard safe)
// ---------------------------------------------------------------------------
__device__ float g_qkv[M_ROWS * N_QKV];               // [8192, 3840] fp32
__device__ __align__(16) __half g_ahi[M_ROWS * DD];   // split A (hs, then attn out)
__device__ __align__(16) __half g_alo[M_ROWS * DD];
__device__ __align__(16) __half g_bh[N_QKV * DD];     // W_qkv^T [N,K] plain fp16
__device__ __align__(16) __half g_ph[DD * DD];        // W_proj^T [N,K] plain fp16
// fp16 attention operands
__device__ __align__(16) __half g_qhi2[VB * HH * PP * HD];  // [v][h][p][d], scaled
__device__ __align__(16) __half g_qlo2[VB * HH * PP * HD];
__device__ __align__(16) __half g_khi2[VB * HH * PP * HD];
__device__ __align__(16) __half g_klo2[VB * HH * PP * HD];
__device__ __align__(16) __half g_vt[VB * HH * HD * PP];    // [v][h][d][p]

// ---------------------------------------------------------------------------
// Helpers
// ---------------------------------------------------------------------------
__device__ __forceinline__ uint32_t smem_u32(const void* p) {
    uint32_t a;
    asm("{ .reg .u64 t; cvta.to.shared.u64 t, %1; cvt.u32.u64 %0, t; }" : "=r"(a) : "l"(p));
    return a;
}

#define CP_ASYNC16(dst, src) \
    asm volatile("cp.async.cg.shared.global [%0], [%1], 16;" :: "r"(dst), "l"(src))
#define CP_COMMIT() asm volatile("cp.async.commit_group;" ::: "memory")
#define CP_WAIT(n)  asm volatile("cp.async.wait_group %0;" :: "n"(n) : "memory")

__device__ __forceinline__ void ldsm_x4(uint32_t& r0, uint32_t& r1, uint32_t& r2, uint32_t& r3,
                                        uint32_t addr) {
    asm volatile("ldmatrix.sync.aligned.m8n8.x4.shared.b16 {%0,%1,%2,%3}, [%4];"
                 : "=r"(r0), "=r"(r1), "=r"(r2), "=r"(r3) : "r"(addr));
}
__device__ __forceinline__ void ldsm_x2(uint32_t& r0, uint32_t& r1, uint32_t addr) {
    asm volatile("ldmatrix.sync.aligned.m8n8.x2.shared.b16 {%0,%1}, [%2];"
                 : "=r"(r0), "=r"(r1) : "r"(addr));
}
__device__ __forceinline__ void mma16816h(float* c, const uint32_t* a, const uint32_t* b) {
    asm volatile("mma.sync.aligned.m16n8k16.row.col.f32.f16.f16.f32 "
                 "{%0,%1,%2,%3}, {%4,%5,%6,%7}, {%8,%9}, {%0,%1,%2,%3};"
                 : "+f"(c[0]), "+f"(c[1]), "+f"(c[2]), "+f"(c[3])
                 : "r"(a[0]), "r"(a[1]), "r"(a[2]), "r"(a[3]), "r"(b[0]), "r"(b[1]));
}

__device__ __forceinline__ uint32_t swz(uint32_t x) { return x ^ ((x >> 3) & 0x70u); }

// ---------------------------------------------------------------------------
// Split fp32 -> hi/lo fp16
// ---------------------------------------------------------------------------
__global__ __launch_bounds__(256) void split_fp16(
    const float* __restrict__ x, __half* __restrict__ hi,
    __half* __restrict__ lo, int n)
{
    int i = (blockIdx.x * 256 + threadIdx.x) * 4;
    if (i >= n) return;
    float4 v = *(const float4*)(x + i);
    __half h0 = __float2half_rn(v.x);
    __half h1 = __float2half_rn(v.y);
    __half h2 = __float2half_rn(v.z);
    __half h3 = __float2half_rn(v.w);
    ((__half2*)(hi + i))[0] = __half2(h0, h1);
    ((__half2*)(hi + i))[1] = __half2(h2, h3);
    ((__half2*)(lo + i))[0] = __half2(
        __float2half_rn(v.x - __half2float(h0)),
        __float2half_rn(v.y - __half2float(h1)));
    ((__half2*)(lo + i))[1] = __half2(
        __float2half_rn(v.z - __half2float(h2)),
        __float2half_rn(v.w - __half2float(h3)));
}

// ---------------------------------------------------------------------------
// Transpose: w [K,N] fp32 -> wT [N,K] plain fp16
// ---------------------------------------------------------------------------
__global__ __launch_bounds__(256) void transpose_fp16(
    const float* __restrict__ w, __half* __restrict__ wt, int K, int N)
{
    __shared__ float t[32][33];
    int n0 = blockIdx.x * 32, k0 = blockIdx.y * 32;
    int tx = threadIdx.x & 31, ty = threadIdx.x >> 5;
    #pragma unroll
    for (int r = ty; r < 32; r += 8)
        t[r][tx] = w[(size_t)(k0 + r) * N + n0 + tx];
    __syncthreads();
    #pragma unroll
    for (int r = ty; r < 32; r += 8)
        wt[(size_t)(n0 + r) * K + k0 + tx] = __float2half_rn(t[tx][r]);
}

// ---------------------------------------------------------------------------
// GEMM tiling constants (shared by both variants)
// ---------------------------------------------------------------------------
#define GTM 128
#define GTN 128
#define GKC 64
#define MAT_B 16384u
// 2-product variant: stage = Ahi | Alo | B = 48 KB, 2 stages
#define STAGE2_B (3u * MAT_B)
#define GEMM2_SMEM (2 * STAGE2_B)   // 98304
// 1-product variant: stage = Ahi | B = 32 KB, 2 stages
#define STAGE1_B (2u * MAT_B)
#define GEMM1_SMEM (2 * STAGE1_B)   // 65536

__device__ __forceinline__ void load_chunk3(
    uint32_t sb, int buf,
    const __half* a0, const __half* a1, const __half* b0,
    int k0, int tid, int K)
{
    const __half* srcs[3] = {a0 + k0, a1 + k0, b0 + k0};
    uint32_t stage = sb + (uint32_t)buf * STAGE2_B;
    #pragma unroll
    for (int mat = 0; mat < 3; mat++) {
        uint32_t tbase = stage + (uint32_t)mat * MAT_B;
        const __half* s = srcs[mat];
        #pragma unroll
        for (int i = 0; i < 4; i++) {
            int g = tid + i * 256;
            int row = g >> 3;
            int c16 = g & 7;
            uint32_t boff = (uint32_t)(row * 128 + c16 * 16);
            CP_ASYNC16(tbase + swz(boff), s + (size_t)row * K + c16 * 8);
        }
    }
}

__device__ __forceinline__ void load_chunk2(
    uint32_t sb, int buf,
    const __half* a0, const __half* b0,
    int k0, int tid, int K)
{
    const __half* srcs[2] = {a0 + k0, b0 + k0};
    uint32_t stage = sb + (uint32_t)buf * STAGE1_B;
    #pragma unroll
    for (int mat = 0; mat < 2; mat++) {
        uint32_t tbase = stage + (uint32_t)mat * MAT_B;
        const __half* s = srcs[mat];
        #pragma unroll
        for (int i = 0; i < 4; i++) {
            int g = tid + i * 256;
            int row = g >> 3;
            int c16 = g & 7;
            uint32_t boff = (uint32_t)(row * 128 + c16 * 16);
            CP_ASYNC16(tbase + swz(boff), s + (size_t)row * K + c16 * 8);
        }
    }
}

// ---------------------------------------------------------------------------
// 2-product GEMM: C = (Ahi+Alo) @ B^T + bias.  C has row-stride ldc.
// ---------------------------------------------------------------------------
__global__ __launch_bounds__(256, 2) void gemm_mma_f16x2(
    const __half* __restrict__ Ahi, const __half* __restrict__ Alo,
    const __half* __restrict__ B,
    const float* __restrict__ bias, float* __restrict__ C, int K, int ldc)
{
    extern __shared__ char smem[];
    uint32_t sb = smem_u32(smem);
    const int tid = threadIdx.x;
    const int lane = tid & 31;
    const int wid = tid >> 5;
    const int wm = wid >> 2;
    const int wn = wid & 3;
    const int m0 = blockIdx.y * GTM;
    const int n0 = blockIdx.x * GTN;

    const __half* a0 = Ahi + (size_t)m0 * K;
    const __half* a1 = Alo + (size_t)m0 * K;
    const __half* b0 = B + (size_t)n0 * K;

    float acc[4][4][4];
    #pragma unroll
    for (int i = 0; i < 4; i++)
        #pragma unroll
        for (int j = 0; j < 4; j++)
            #pragma unroll
            for (int t = 0; t < 4; t++) acc[i][j][t] = 0.f;

    const int a_row_l = (lane & 7) + ((lane >> 3) & 1) * 8;
    const int a_c16_l = (lane >> 4);
    const int b_row_l = (lane & 7);
    const int b_c16_l = ((lane >> 3) & 1);

    const int nch = K / GKC;

    load_chunk3(sb, 0, a0, a1, b0, 0, tid, K);
    CP_COMMIT();

    for (int it = 0; it < nch; it++) {
        const int b = it & 1;
        if (it + 1 < nch) {
            load_chunk3(sb, b ^ 1, a0, a1, b0, (it + 1) * GKC, tid, K);
            CP_COMMIT();
            CP_WAIT(1);
        } else {
            CP_WAIT(0);
        }
        __syncthreads();

        uint32_t stage = sb + (uint32_t)b * STAGE2_B;
        uint32_t sAhi = stage;
        uint32_t sAlo = stage + MAT_B;
        uint32_t sB   = stage + 2 * MAT_B;

        #pragma unroll
        for (int ks = 0; ks < 4; ks++) {
            uint32_t bb[4][2];
            #pragma unroll
            for (int nt = 0; nt < 4; nt++) {
                uint32_t boff = (uint32_t)((wn * 32 + nt * 8 + b_row_l) * 128 +
                                           (ks * 2 + b_c16_l) * 16);
                uint32_t so = swz(boff);
                ldsm_x2(bb[nt][0], bb[nt][1], sB + so);
            }
            #pragma unroll
            for (int mt = 0; mt < 4; mt++) {
                uint32_t boff = (uint32_t)((wm * 64 + mt * 16 + a_row_l) * 128 +
                                           (ks * 2 + a_c16_l) * 16);
                uint32_t so = swz(boff);
                uint32_t ahi[4], alo[4];
                ldsm_x4(ahi[0], ahi[1], ahi[2], ahi[3], sAhi + so);
                ldsm_x4(alo[0], alo[1], alo[2], alo[3], sAlo + so);
                #pragma unroll
                for (int nt = 0; nt < 4; nt++) {
                    mma16816h(acc[mt][nt], ahi, bb[nt]);
                    mma16816h(acc[mt][nt], alo, bb[nt]);
                }
            }
        }
        __syncthreads();
    }

    const int r_base = m0 + wm * 64 + (lane >> 2);
    const int c_base = n0 + wn * 32 + (lane & 3) * 2;
    #pragma unroll
    for (int mt = 0; mt < 4; mt++) {
        #pragma unroll
        for (int nt = 0; nt < 4; nt++) {
            int col = c_base + nt * 8;
            float bx = bias[col], by = bias[col + 1];
            int r0 = r_base + mt * 16;
            float2 v0 = {acc[mt][nt][0] + bx, acc[mt][nt][1] + by};
            float2 v1 = {acc[mt][nt][2] + bx, acc[mt][nt][3] + by};
            *(float2*)(C + (size_t)r0 * ldc + col) = v0;
            *(float2*)(C + (size_t)(r0 + 8) * ldc + col) = v1;
        }
    }
}

// ---------------------------------------------------------------------------
// 1-product GEMM: C = Ahi @ B^T + bias (for V columns — fp16-rounded anyway)
// ---------------------------------------------------------------------------
__global__ __launch_bounds__(256, 2) void gemm_mma_f16x1(
    const __half* __restrict__ Ahi, const __half* __restrict__ B,
    const float* __restrict__ bias, float* __restrict__ C, int K, int ldc)
{
    extern __shared__ char smem[];
    uint32_t sb = smem_u32(smem);
    const int tid = threadIdx.x;
    const int lane = tid & 31;
    const int wid = tid >> 5;
    const int wm = wid >> 2;
    const int wn = wid & 3;
    const int m0 = blockIdx.y * GTM;
    const int n0 = blockIdx.x * GTN;

    const __half* a0 = Ahi + (size_t)m0 * K;
    const __half* b0 = B + (size_t)n0 * K;

    float acc[4][4][4];
    #pragma unroll
    for (int i = 0; i < 4; i++)
        #pragma unroll
        for (int j = 0; j < 4; j++)
            #pragma unroll
            for (int t = 0; t < 4; t++) acc[i][j][t] = 0.f;

    const int a_row_l = (lane & 7) + ((lane >> 3) & 1) * 8;
    const int a_c16_l = (lane >> 4);
    const int b_row_l = (lane & 7);
    const int b_c16_l = ((lane >> 3) & 1);

    const int nch = K / GKC;

    load_chunk2(sb, 0, a0, b0, 0, tid, K);
    CP_COMMIT();

    for (int it = 0; it < nch; it++) {
        const int b = it & 1;
        if (it + 1 < nch) {
            load_chunk2(sb, b ^ 1, a0, b0, (it + 1) * GKC, tid, K);
            CP_COMMIT();
            CP_WAIT(1);
        } else {
            CP_WAIT(0);
        }
        __syncthreads();

        uint32_t stage = sb + (uint32_t)b * STAGE1_B;
        uint32_t sAhi = stage;
        uint32_t sB   = stage + MAT_B;

        #pragma unroll
        for (int ks = 0; ks < 4; ks++) {
            uint32_t bb[4][2];
            #pragma unroll
            for (int nt = 0; nt < 4; nt++) {
                uint32_t boff = (uint32_t)((wn * 32 + nt * 8 + b_row_l) * 128 +
                                           (ks * 2 + b_c16_l) * 16);
                uint32_t so = swz(boff);
                ldsm_x2(bb[nt][0], bb[nt][1], sB + so);
            }
            #pragma unroll
            for (int mt = 0; mt < 4; mt++) {
                uint32_t boff = (uint32_t)((wm * 64 + mt * 16 + a_row_l) * 128 +
                                           (ks * 2 + a_c16_l) * 16);
                uint32_t so = swz(boff);
                uint32_t ahi[4];
                ldsm_x4(ahi[0], ahi[1], ahi[2], ahi[3], sAhi + so);
                #pragma unroll
                for (int nt = 0; nt < 4; nt++)
                    mma16816h(acc[mt][nt], ahi, bb[nt]);
            }
        }
        __syncthreads();
    }

    const int r_base = m0 + wm * 64 + (lane >> 2);
    const int c_base = n0 + wn * 32 + (lane & 3) * 2;
    #pragma unroll
    for (int mt = 0; mt < 4; mt++) {
        #pragma unroll
        for (int nt = 0; nt < 4; nt++) {
            int col = c_base + nt * 8;
            float bx = bias[col], by = bias[col + 1];
            int r0 = r_base + mt * 16;
            float2 v0 = {acc[mt][nt][0] + bx, acc[mt][nt][1] + by};
            float2 v1 = {acc[mt][nt][2] + bx, acc[mt][nt][3] + by};
            *(float2*)(C + (size_t)r0 * ldc + col) = v0;
            *(float2*)(C + (size_t)(r0 + 8) * ldc + col) = v1;
        }
    }
}

// ---------------------------------------------------------------------------
// RoPE + split-fp16 scatter for Q (scaled) and K: [v][h][p][d]
// ---------------------------------------------------------------------------
__global__ __launch_bounds__(256) void rope_scatter(
    const float* __restrict__ qkv, const float* __restrict__ rope)
{
    int idx = blockIdx.x * 256 + threadIdx.x;
    if (idx >= VB * PP * HH * 40) return;
    int d = idx % 40;
    int h = (idx / 40) % HH;
    int p = (idx / (40 * HH)) % PP;
    int v = idx / (40 * HH * PP);

    size_t row = (size_t)v * PP + p;
    const float* qr = qkv + row * N_QKV + h * HD;
    const float* kr = qr + DD;
    const float* rp = rope + row * (2 * HD);

    float c0 = rp[d],      c1 = rp[d + 40];
    float s0 = rp[HD + d], s1 = rp[HD + d + 40];
    float q0 = qr[d], q1 = qr[d + 40];
    float k0 = kr[d], k1 = kr[d + 40];

    float qa = (q0 * c0 - q1 * s0) * QK_SCALE;
    float qb = (q1 * c1 + q0 * s1) * QK_SCALE;
    float ka = k0 * c0 - k1 * s0;
    float kb = k1 * c1 + k0 * s1;

    size_t ob = (((size_t)v * HH + h) * PP + p) * HD;
    __half hqa = __float2half_rn(qa);
    __half hqb = __float2half_rn(qb);
    __half hka = __float2half_rn(ka);
    __half hkb = __float2half_rn(kb);
    g_qhi2[ob + d]      = hqa;
    g_qhi2[ob + d + 40] = hqb;
    g_qlo2[ob + d]      = __float2half_rn(qa - __half2float(hqa));
    g_qlo2[ob + d + 40] = __float2half_rn(qb - __half2float(hqb));
    g_khi2[ob + d]      = hka;
    g_khi2[ob + d + 40] = hkb;
    g_klo2[ob + d]      = __float2half_rn(ka - __half2float(hka));
    g_klo2[ob + d + 40] = __float2half_rn(kb - __half2float(hkb));
}

// ---------------------------------------------------------------------------
// V transpose: g_qkv V-part [v][p][h*80+d] -> g_vt [v][h][d][p] fp16
// ---------------------------------------------------------------------------
__global__ __launch_bounds__(256) void v_transpose(const float* __restrict__ qkv)
{
    __shared__ float t[32][33];
    int vh = blockIdx.z;
    int v = vh >> 4, h = vh & 15;
    int p0 = blockIdx.x * 32;
    int d0 = blockIdx.y * 32;
    int tx = threadIdx.x & 31, ty = threadIdx.x >> 5;
    #pragma unroll
    for (int r = ty; r < 32; r += 8) {
        int d = d0 + tx;
        if (d < HD)
            t[r][tx] = qkv[((size_t)v * PP + p0 + r) * N_QKV + 2 * DD + h * HD + d];
    }
    __syncthreads();
    #pragma unroll
    for (int r = ty; r < 32; r += 8) {
        int d = d0 + r;
        if (d < HD)
            g_vt[((size_t)vh * HD + d) * PP + p0 + tx] = __float2half_rn(t[tx][r]);
    }
}

// ---------------------------------------------------------------------------
// Tensor-core flash attention: QK 3-product (Q split, K split), PV fp16,
// fused split-fp16 epilogue for proj GEMM.
// ---------------------------------------------------------------------------
#define SQ 88
#define SV 72
#define ATTN_SMEM 113152

__global__ __launch_bounds__(256) void attn_mma(const int* __restrict__ valid_lens)
{
    extern __shared__ char smem[];
    uint32_t sb = smem_u32(smem);
    const int tid = threadIdx.x;
    const int lane = tid & 31;
    const int wq = tid >> 5;
    const int q0 = blockIdx.x * 128;
    const int h = blockIdx.y;
    const int v = blockIdx.z;
    int L = valid_lens[v];
    if (L < 1) L = 1;

    const size_t hb = ((size_t)(v * HH + h)) * PP * HD;
    const __half* qhi = g_qhi2 + hb + (size_t)q0 * HD;
    const __half* qlo = g_qlo2 + hb + (size_t)q0 * HD;
    const __half* khi = g_khi2 + hb;
    const __half* klo = g_klo2 + hb;
    const __half* vtp = g_vt + hb;   // [80][2048]

    const uint32_t bQHI = sb;
    const uint32_t bQLO = sb + 22528u;
    const uint32_t bKHI = sb + 45056u;
    const uint32_t bKLO = sb + 67584u;
    const uint32_t bVT  = sb + 90112u;

    for (int i = tid; i < 1280; i += 256) {
        int r = i / 10, g = i % 10;
        uint32_t off = (uint32_t)(r * SQ + g * 8) * 2;
        CP_ASYNC16(bQHI + off, qhi + (size_t)r * HD + g * 8);
        CP_ASYNC16(bQLO + off, qlo + (size_t)r * HD + g * 8);
    }
    {
        for (int i = tid; i < 640; i += 256) {
            int r = i / 10, g = i % 10;
            uint32_t off = (uint32_t)(r * SQ + g * 8) * 2;
            CP_ASYNC16(bKHI + off, khi + (size_t)r * HD + g * 8);
            CP_ASYNC16(bKLO + off, klo + (size_t)r * HD + g * 8);
        }
        for (int i = tid; i < 640; i += 256) {
            int d = i / 8, g = i % 8;
            CP_ASYNC16(bVT + (uint32_t)(d * SV + g * 8) * 2, vtp + (size_t)d * PP + g * 8);
        }
    }
    CP_COMMIT();

    float m_lo = -1e30f, m_hi = -1e30f, l_lo = 0.f, l_hi = 0.f;
    float o[10][4];
    #pragma unroll
    for (int i = 0; i < 10; i++)
        #pragma unroll
        for (int j = 0; j < 4; j++) o[i][j] = 0.f;

    const int a_row = wq * 16 + (lane & 7) + ((lane >> 3) & 1) * 8;
    const int a_c16 = (lane >> 4);
    const int b_row = (lane & 7);
    const int b_c16 = (lane >> 3) & 1;
    const int gc = lane & 3;

    const int nkt = (L + 63) >> 6;
    for (int kt = 0; kt < nkt; kt++) {
        const int b = kt & 1;
        if (kt + 1 < nkt) {
            const int kn = (kt + 1) * 64;
            const uint32_t kh = bKHI + (uint32_t)(b ^ 1) * 11264u;
            const uint32_t kl = bKLO + (uint32_t)(b ^ 1) * 11264u;
            const uint32_t vb = bVT + (uint32_t)(b ^ 1) * 11520u;
            for (int i = tid; i < 640; i += 256) {
                int r = i / 10, g = i % 10;
                uint32_t off = (uint32_t)(r * SQ + g * 8) * 2;
                CP_ASYNC16(kh + off, khi + (size_t)(kn + r) * HD + g * 8);
                CP_ASYNC16(kl + off, klo + (size_t)(kn + r) * HD + g * 8);
            }
            for (int i = tid; i < 640; i += 256) {
                int d = i / 8, g = i % 8;
                CP_ASYNC16(vb + (uint32_t)(d * SV + g * 8) * 2,
                           vtp + (size_t)d * PP + kn + g * 8);
            }
            CP_COMMIT();
            CP_WAIT(1);
        } else {
            CP_WAIT(0);
        }
        __syncthreads();

        const uint32_t khb = bKHI + (uint32_t)b * 11264u;
        const uint32_t klb = bKLO + (uint32_t)b * 11264u;
        const uint32_t vtb = bVT + (uint32_t)b * 11520u;

        float s[8][4];
        #pragma unroll
        for (int nt = 0; nt < 8; nt++)
            #pragma unroll
            for (int j = 0; j < 4; j++) s[nt][j] = 0.f;

        #pragma unroll
        for (int kc = 0; kc < 5; kc++) {
            uint32_t qh[4], ql[4];
            uint32_t qoff = (uint32_t)(a_row * SQ + kc * 16 + a_c16 * 8) * 2;
            ldsm_x4(qh[0], qh[1], qh[2], qh[3], bQHI + qoff);
            ldsm_x4(ql[0], ql[1], ql[2], ql[3], bQLO + qoff);
            #pragma unroll
            for (int nt = 0; nt < 8; nt++) {
                uint32_t koff = (uint32_t)((nt * 8 + b_row) * SQ + kc * 16 + b_c16 * 8) * 2;
                uint32_t kh[2], kl[2];
                ldsm_x2(kh[0], kh[1], khb + koff);
                ldsm_x2(kl[0], kl[1], klb + koff);
                mma16816h(s[nt], qh, kh);
                mma16816h(s[nt], qh, kl);
                mma16816h(s[nt], ql, kh);
            }
        }

        const int k0 = kt * 64;
        if (k0 + 64 > L) {
            #pragma unroll
            for (int nt = 0; nt < 8; nt++) {
                int kb0 = k0 + nt * 8 + gc * 2;
                if (kb0 >= L)     { s[nt][0] = -1e30f; s[nt][2] = -1e30f; }
                if (kb0 + 1 >= L) { s[nt][1] = -1e30f; s[nt][3] = -1e30f; }
            }
        }

        float mt_lo = -1e30f, mt_hi = -1e30f;
        #pragma unroll
        for (int nt = 0; nt < 8; nt++) {
            mt_lo = fmaxf(mt_lo, fmaxf(s[nt][0], s[nt][1]));
            mt_hi = fmaxf(mt_hi, fmaxf(s[nt][2], s[nt][3]));
        }
        mt_lo = fmaxf(mt_lo, __shfl_xor_sync(0xffffffffu, mt_lo, 1));
        mt_lo = fmaxf(mt_lo, __shfl_xor_sync(0xffffffffu, mt_lo, 2));
        mt_hi = fmaxf(mt_hi, __shfl_xor_sync(0xffffffffu, mt_hi, 1));
        mt_hi = fmaxf(mt_hi, __shfl_xor_sync(0xffffffffu, mt_hi, 2));

        float mn_lo = fmaxf(m_lo, mt_lo), mn_hi = fmaxf(m_hi, mt_hi);
        float al = __expf(m_lo - mn_lo), ah = __expf(m_hi - mn_hi);
        m_lo = mn_lo; m_hi = mn_hi;

        float sum_lo = 0.f, sum_hi = 0.f;
        #pragma unroll
        for (int nt = 0; nt < 8; nt++) {
            s[nt][0] = __expf(s[nt][0] - mn_lo);
            s[nt][1] = __expf(s[nt][1] - mn_lo);
            s[nt][2] = __expf(s[nt][2] - mn_hi);
            s[nt][3] = __expf(s[nt][3] - mn_hi);
            sum_lo += s[nt][0] + s[nt][1];
            sum_hi += s[nt][2] + s[nt][3];
        }
        sum_lo += __shfl_xor_sync(0xffffffffu, sum_lo, 1);
        sum_lo += __shfl_xor_sync(0xffffffffu, sum_lo, 2);
        sum_hi += __shfl_xor_sync(0xffffffffu, sum_hi, 1);
        sum_hi += __shfl_xor_sync(0xffffffffu, sum_hi, 2);
        l_lo = l_lo * al + sum_lo;
        l_hi = l_hi * ah + sum_hi;

        #pragma unroll
        for (int nt = 0; nt < 10; nt++) {
            o[nt][0] *= al; o[nt][1] *= al;
            o[nt][2] *= ah; o[nt][3] *= ah;
        }

        uint32_t pa[4][4];
        #pragma unroll
        for (int kc = 0; kc < 4; kc++) {
            __half2 t0 = __floats2half2_rn(s[2 * kc][0], s[2 * kc][1]);
            __half2 t1 = __floats2half2_rn(s[2 * kc][2], s[2 * kc][3]);
            __half2 t2 = __floats2half2_rn(s[2 * kc + 1][0], s[2 * kc + 1][1]);
            __half2 t3 = __floats2half2_rn(s[2 * kc + 1][2], s[2 * kc + 1][3]);
            pa[kc][0] = *(uint32_t*)&t0;
            pa[kc][1] = *(uint32_t*)&t1;
            pa[kc][2] = *(uint32_t*)&t2;
            pa[kc][3] = *(uint32_t*)&t3;
        }

        #pragma unroll
        for (int nt = 0; nt < 10; nt++) {
            #pragma unroll
            for (int kc = 0; kc < 4; kc++) {
                uint32_t voff = (uint32_t)((nt * 8 + b_row) * SV + kc * 16 + b_c16 * 8) * 2;
                uint32_t vv[2];
                ldsm_x2(vv[0], vv[1], vtb + voff);
                mma16816h(o[nt], pa[kc], vv);
            }
        }
        __syncthreads();
    }

    // Epilogue: write split fp16 hi/lo directly (fused split for proj GEMM)
    float inv_lo = 1.f / l_lo, inv_hi = 1.f / l_hi;
    int row_lo = q0 + wq * 16 + (lane >> 2);
    #pragma unroll
    for (int nt = 0; nt < 10; nt++) {
        int col = h * HD + nt * 8 + gc * 2;
        size_t off0 = ((size_t)v * PP + row_lo) * DD + col;
        size_t off1 = ((size_t)v * PP + row_lo + 8) * DD + col;
        float v00 = o[nt][0] * inv_lo, v01 = o[nt][1] * inv_lo;
        float v10 = o[nt][2] * inv_hi, v11 = o[nt][3] * inv_hi;
        __half h00 = __float2half_rn(v00);
        __half h01 = __float2half_rn(v01);
        __half h10 = __float2half_rn(v10);
        __half h11 = __float2half_rn(v11);
        *(__half2*)(g_ahi + off0) = __half2(h00, h01);
        *(__half2*)(g_ahi + off1) = __half2(h10, h11);
        *(__half2*)(g_alo + off0) = __half2(
            __float2half_rn(v00 - __half2float(h00)),
            __float2half_rn(v01 - __half2float(h01)));
        *(__half2*)(g_alo + off1) = __half2(
            __float2half_rn(v10 - __half2float(h10)),
            __float2half_rn(v11 - __half2float(h11)));
    }
}

// ---------------------------------------------------------------------------
// Launch — QK GEMM in the 4th launch slot (ncu capture)
// ---------------------------------------------------------------------------
extern "C" void kernel_launch(void* const* d_in, const int* in_sizes, int n_in,
                              void* d_out, int out_size)
{
    const float* hs    = (const float*)d_in[0];
    const float* rope  = (const float*)d_in[1];
    const int*   vlens = (const int*)d_in[2];
    const float* wqkv  = (const float*)d_in[3];
    const float* bqkv  = (const float*)d_in[4];
    const float* wproj = (const float*)d_in[5];
    const float* bproj = (const float*)d_in[6];
    float* out = (float*)d_out;

    float* p_qkv;
    __half *p_ahi, *p_alo, *p_bh, *p_ph;
    cudaGetSymbolAddress((void**)&p_qkv, g_qkv);
    cudaGetSymbolAddress((void**)&p_ahi, g_ahi);
    cudaGetSymbolAddress((void**)&p_alo, g_alo);
    cudaGetSymbolAddress((void**)&p_bh,  g_bh);
    cudaGetSymbolAddress((void**)&p_ph,  g_ph);

    cudaFuncSetAttribute(gemm_mma_f16x2,
                         cudaFuncAttributeMaxDynamicSharedMemorySize, GEMM2_SMEM);
    cudaFuncSetAttribute(gemm_mma_f16x1,
                         cudaFuncAttributeMaxDynamicSharedMemorySize, GEMM1_SMEM);
    cudaFuncSetAttribute(attn_mma,
                         cudaFuncAttributeMaxDynamicSharedMemorySize, ATTN_SMEM);

    // 1) Split hidden states (fp16 hi/lo)
    {
        int n = M_ROWS * DD;
        split_fp16<<<(n / 4 + 255) / 256, 256>>>(hs, p_ahi, p_alo, n);
    }
    // 2) Transpose W_qkv (plain fp16)
    transpose_fp16<<<dim3(N_QKV / 32, DD / 32), 256>>>(wqkv, p_bh, DD, N_QKV);
    // 3) Transpose W_proj (plain fp16)
    transpose_fp16<<<dim3(DD / 32, DD / 32), 256>>>(wproj, p_ph, DD, DD);

    // 4) QK GEMM: cols [0, 2560), 2-product  <-- ncu capture slot
    gemm_mma_f16x2<<<dim3(2 * DD / GTN, M_ROWS / GTM), 256, GEMM2_SMEM>>>(
        p_ahi, p_alo, p_bh, bqkv, p_qkv, DD, N_QKV);

    // 5) V GEMM: cols [2560, 3840), 1-product (V is fp16-rounded downstream)
    gemm_mma_f16x1<<<dim3(DD / GTN, M_ROWS / GTM), 256, GEMM1_SMEM>>>(
        p_ahi, p_bh + (size_t)2 * DD * DD, bqkv + 2 * DD, p_qkv + 2 * DD, DD, N_QKV);

    // 6) RoPE (Q split fp16 scaled, K split fp16)
    {
        int total = VB * PP * HH * 40;
        rope_scatter<<<(total + 255) / 256, 256>>>(p_qkv, rope);
    }
    // 7) V transpose (fp16)
    v_transpose<<<dim3(PP / 32, 3, VB * HH), 256>>>(p_qkv);

    // 8) Tensor-core flash attention (3-product QK, writes split fp16)
    attn_mma<<<dim3(PP / 128, HH, VB), 256, ATTN_SMEM>>>(vlens);

    // 9) Output projection (fp16 2-product)
    gemm_mma_f16x2<<<dim3(DD / GTN, M_ROWS / GTM), 256, GEMM2_SMEM>>>(
        p_ahi, p_alo, p_ph, bproj, out, DD, DD);
}

// round 15
// speedup vs baseline: 1.4788x; 1.0109x over previous
#include <cuda_runtime.h>
#include <cuda_bf16.h>
#include <cuda_fp16.h>
#include <cstdint>

// Problem constants
#define VB 4
#define PP 2048
#define DD 1280
#define HH 16
#define HD 80
#define M_ROWS (VB * PP)     // 8192
#define N_QKV  (3 * DD)      // 3840
#define QK_SCALE 0.111803398874989484f

// ---------------------------------------------------------------------------
// Scratch (static device globals — allocation-guard safe)
// ---------------------------------------------------------------------------
__device__ float g_qkv[M_ROWS * N_QKV];               // [8192, 3840] fp32
__device__ __align__(16) __half g_ahi[M_ROWS * DD];   // split A (hs, then attn out)
__device__ __align__(16) __half g_alo[M_ROWS * DD];
__device__ __align__(16) __half g_bh[N_QKV * DD];     // W_qkv^T [N,K] plain fp16
__device__ __align__(16) __half g_ph[DD * DD];        // W_proj^T [N,K] plain fp16
// fp16 attention operands
__device__ __align__(16) __half g_qhi2[VB * HH * PP * HD];  // [v][h][p][d], scaled
__device__ __align__(16) __half g_qlo2[VB * HH * PP * HD];
__device__ __align__(16) __half g_khi2[VB * HH * PP * HD];
__device__ __align__(16) __half g_klo2[VB * HH * PP * HD];
__device__ __align__(16) __half g_vt[VB * HH * HD * PP];    // [v][h][d][p]

// ---------------------------------------------------------------------------
// Helpers
// ---------------------------------------------------------------------------
__device__ __forceinline__ uint32_t smem_u32(const void* p) {
    uint32_t a;
    asm("{ .reg .u64 t; cvta.to.shared.u64 t, %1; cvt.u32.u64 %0, t; }" : "=r"(a) : "l"(p));
    return a;
}

#define CP_ASYNC16(dst, src) \
    asm volatile("cp.async.cg.shared.global [%0], [%1], 16;" :: "r"(dst), "l"(src))
#define CP_COMMIT() asm volatile("cp.async.commit_group;" ::: "memory")
#define CP_WAIT(n)  asm volatile("cp.async.wait_group %0;" :: "n"(n) : "memory")

__device__ __forceinline__ void ldsm_x4(uint32_t& r0, uint32_t& r1, uint32_t& r2, uint32_t& r3,
                                        uint32_t addr) {
    asm volatile("ldmatrix.sync.aligned.m8n8.x4.shared.b16 {%0,%1,%2,%3}, [%4];"
                 : "=r"(r0), "=r"(r1), "=r"(r2), "=r"(r3) : "r"(addr));
}
__device__ __forceinline__ void ldsm_x2(uint32_t& r0, uint32_t& r1, uint32_t addr) {
    asm volatile("ldmatrix.sync.aligned.m8n8.x2.shared.b16 {%0,%1}, [%2];"
                 : "=r"(r0), "=r"(r1) : "r"(addr));
}
__device__ __forceinline__ void mma16816h(float* c, const uint32_t* a, const uint32_t* b) {
    asm volatile("mma.sync.aligned.m16n8k16.row.col.f32.f16.f16.f32 "
                 "{%0,%1,%2,%3}, {%4,%5,%6,%7}, {%8,%9}, {%0,%1,%2,%3};"
                 : "+f"(c[0]), "+f"(c[1]), "+f"(c[2]), "+f"(c[3])
                 : "r"(a[0]), "r"(a[1]), "r"(a[2]), "r"(a[3]), "r"(b[0]), "r"(b[1]));
}

__device__ __forceinline__ uint32_t swz(uint32_t x) { return x ^ ((x >> 3) & 0x70u); }

// ---------------------------------------------------------------------------
// Fused prep: split hidden states (blocks [0,10240)),
// transpose W_qkv (blocks [10240,15040)), transpose W_proj (blocks [15040,16640))
// ---------------------------------------------------------------------------
#define PREP_SPLIT_BLKS 10240
#define PREP_TQKV_BLKS  4800
#define PREP_BLOCKS     (PREP_SPLIT_BLKS + PREP_TQKV_BLKS + 1600)

__global__ __launch_bounds__(256) void prep_fused(
    const float* __restrict__ hs,
    const float* __restrict__ wqkv, const float* __restrict__ wproj)
{
    __shared__ float t[32][33];
    int bx = blockIdx.x;
    int tid = threadIdx.x;

    if (bx < PREP_SPLIT_BLKS) {
        // split hs -> g_ahi/g_alo
        int i = (bx * 256 + tid) * 4;
        float4 v = *(const float4*)(hs + i);
        __half h0 = __float2half_rn(v.x);
        __half h1 = __float2half_rn(v.y);
        __half h2 = __float2half_rn(v.z);
        __half h3 = __float2half_rn(v.w);
        ((__half2*)(g_ahi + i))[0] = __half2(h0, h1);
        ((__half2*)(g_ahi + i))[1] = __half2(h2, h3);
        ((__half2*)(g_alo + i))[0] = __half2(
            __float2half_rn(v.x - __half2float(h0)),
            __float2half_rn(v.y - __half2float(h1)));
        ((__half2*)(g_alo + i))[1] = __half2(
            __float2half_rn(v.z - __half2float(h2)),
            __float2half_rn(v.w - __half2float(h3)));
        return;
    }

    // transpose paths
    const float* w;
    __half* wt;
    int N, n0, k0;
    int b2 = bx - PREP_SPLIT_BLKS;
    if (b2 < PREP_TQKV_BLKS) {
        w = wqkv; wt = g_bh; N = N_QKV;
        n0 = (b2 % 120) * 32; k0 = (b2 / 120) * 32;
    } else {
        int b3 = b2 - PREP_TQKV_BLKS;
        w = wproj; wt = g_ph; N = DD;
        n0 = (b3 % 40) * 32; k0 = (b3 / 40) * 32;
    }
    int tx = tid & 31, ty = tid >> 5;
    #pragma unroll
    for (int r = ty; r < 32; r += 8)
        t[r][tx] = w[(size_t)(k0 + r) * N + n0 + tx];
    __syncthreads();
    #pragma unroll
    for (int r = ty; r < 32; r += 8)
        wt[(size_t)(n0 + r) * DD + k0 + tx] = __float2half_rn(t[tx][r]);
}

// ---------------------------------------------------------------------------
// Hybrid GEMM: C = (Ahi [+ Alo if col<2560]) @ B^T + bias, row-stride ldc.
// CTA 128x128, K-chunk 64 (SW128), 2-stage, 2 CTAs/SM.
// Tiles with n0 >= 2560 (the V columns) use the 1-product path (V is
// fp16-rounded downstream anyway). Proj GEMM (N=1280) always takes 2-product.
// ---------------------------------------------------------------------------
#define GTM 128
#define GTN 128
#define GKC 64
#define MAT_B 16384u
#define STAGE_B (3u * MAT_B)      // Ahi | Alo | B = 48 KB
#define GEMM_SMEM (2 * STAGE_B)   // 98304 (2 stages -> 2 CTAs/SM)
#define N_LO_SPLIT (2 * DD)       // cols below this get the Alo product

__device__ __forceinline__ void load_chunk_h(
    uint32_t sb, int buf,
    const __half* a0, const __half* a1, const __half* b0,
    int k0, int tid, int K, bool need_lo)
{
    const __half* srcs[3] = {a0 + k0, a1 + k0, b0 + k0};
    uint32_t stage = sb + (uint32_t)buf * STAGE_B;
    #pragma unroll
    for (int mat = 0; mat < 3; mat++) {
        if (mat == 1 && !need_lo) continue;
        uint32_t tbase = stage + (uint32_t)mat * MAT_B;
        const __half* s = srcs[mat];
        #pragma unroll
        for (int i = 0; i < 4; i++) {
            int g = tid + i * 256;
            int row = g >> 3;
            int c16 = g & 7;
            uint32_t boff = (uint32_t)(row * 128 + c16 * 16);
            CP_ASYNC16(tbase + swz(boff), s + (size_t)row * K + c16 * 8);
        }
    }
}

__global__ __launch_bounds__(256, 2) void gemm_qkv_hybrid(
    const __half* __restrict__ Ahi, const __half* __restrict__ Alo,
    const __half* __restrict__ B,
    const float* __restrict__ bias, float* __restrict__ C, int K, int ldc)
{
    extern __shared__ char smem[];
    uint32_t sb = smem_u32(smem);
    const int tid = threadIdx.x;
    const int lane = tid & 31;
    const int wid = tid >> 5;
    const int wm = wid >> 2;
    const int wn = wid & 3;
    const int m0 = blockIdx.y * GTM;
    const int n0 = blockIdx.x * GTN;
    const bool lo = (n0 < N_LO_SPLIT);

    const __half* a0 = Ahi + (size_t)m0 * K;
    const __half* a1 = Alo + (size_t)m0 * K;
    const __half* b0 = B + (size_t)n0 * K;

    float acc[4][4][4];
    #pragma unroll
    for (int i = 0; i < 4; i++)
        #pragma unroll
        for (int j = 0; j < 4; j++)
            #pragma unroll
            for (int t = 0; t < 4; t++) acc[i][j][t] = 0.f;

    const int a_row_l = (lane & 7) + ((lane >> 3) & 1) * 8;
    const int a_c16_l = (lane >> 4);
    const int b_row_l = (lane & 7);
    const int b_c16_l = ((lane >> 3) & 1);

    const int nch = K / GKC;

    load_chunk_h(sb, 0, a0, a1, b0, 0, tid, K, lo);
    CP_COMMIT();

    for (int it = 0; it < nch; it++) {
        const int b = it & 1;
        if (it + 1 < nch) {
            load_chunk_h(sb, b ^ 1, a0, a1, b0, (it + 1) * GKC, tid, K, lo);
            CP_COMMIT();
            CP_WAIT(1);
        } else {
            CP_WAIT(0);
        }
        __syncthreads();

        uint32_t stage = sb + (uint32_t)b * STAGE_B;
        uint32_t sAhi = stage;
        uint32_t sAlo = stage + MAT_B;
        uint32_t sB   = stage + 2 * MAT_B;

        #pragma unroll
        for (int ks = 0; ks < 4; ks++) {
            uint32_t bb[4][2];
            #pragma unroll
            for (int nt = 0; nt < 4; nt++) {
                uint32_t boff = (uint32_t)((wn * 32 + nt * 8 + b_row_l) * 128 +
                                           (ks * 2 + b_c16_l) * 16);
                uint32_t so = swz(boff);
                ldsm_x2(bb[nt][0], bb[nt][1], sB + so);
            }
            #pragma unroll
            for (int mt = 0; mt < 4; mt++) {
                uint32_t boff = (uint32_t)((wm * 64 + mt * 16 + a_row_l) * 128 +
                                           (ks * 2 + a_c16_l) * 16);
                uint32_t so = swz(boff);
                uint32_t ahi[4];
                ldsm_x4(ahi[0], ahi[1], ahi[2], ahi[3], sAhi + so);
                #pragma unroll
                for (int nt = 0; nt < 4; nt++)
                    mma16816h(acc[mt][nt], ahi, bb[nt]);
                if (lo) {
                    uint32_t alo[4];
                    ldsm_x4(alo[0], alo[1], alo[2], alo[3], sAlo + so);
                    #pragma unroll
                    for (int nt = 0; nt < 4; nt++)
                        mma16816h(acc[mt][nt], alo, bb[nt]);
                }
            }
        }
        __syncthreads();
    }

    const int r_base = m0 + wm * 64 + (lane >> 2);
    const int c_base = n0 + wn * 32 + (lane & 3) * 2;
    #pragma unroll
    for (int mt = 0; mt < 4; mt++) {
        #pragma unroll
        for (int nt = 0; nt < 4; nt++) {
            int col = c_base + nt * 8;
            float bx = bias[col], by = bias[col + 1];
            int r0 = r_base + mt * 16;
            float2 v0 = {acc[mt][nt][0] + bx, acc[mt][nt][1] + by};
            float2 v1 = {acc[mt][nt][2] + bx, acc[mt][nt][3] + by};
            *(float2*)(C + (size_t)r0 * ldc + col) = v0;
            *(float2*)(C + (size_t)(r0 + 8) * ldc + col) = v1;
        }
    }
}

// ---------------------------------------------------------------------------
// Fused RoPE (blocks [0,20480)) + V transpose (blocks [20480,32768))
// ---------------------------------------------------------------------------
#define RVT_ROPE_BLKS 20480
#define RVT_BLOCKS (RVT_ROPE_BLKS + 12288)

__global__ __launch_bounds__(256) void rope_vt(
    const float* __restrict__ qkv, const float* __restrict__ rope)
{
    __shared__ float t[32][33];
    int bx = blockIdx.x;
    int tid = threadIdx.x;

    if (bx < RVT_ROPE_BLKS) {
        int idx = bx * 256 + tid;
        int d = idx % 40;
        int h = (idx / 40) % HH;
        int p = (idx / (40 * HH)) % PP;
        int v = idx / (40 * HH * PP);

        size_t row = (size_t)v * PP + p;
        const float* qr = qkv + row * N_QKV + h * HD;
        const float* kr = qr + DD;
        const float* rp = rope + row * (2 * HD);

        float c0 = rp[d],      c1 = rp[d + 40];
        float s0 = rp[HD + d], s1 = rp[HD + d + 40];
        float q0 = qr[d], q1 = qr[d + 40];
        float k0 = kr[d], k1 = kr[d + 40];

        float qa = (q0 * c0 - q1 * s0) * QK_SCALE;
        float qb = (q1 * c1 + q0 * s1) * QK_SCALE;
        float ka = k0 * c0 - k1 * s0;
        float kb = k1 * c1 + k0 * s1;

        size_t ob = (((size_t)v * HH + h) * PP + p) * HD;
        __half hqa = __float2half_rn(qa);
        __half hqb = __float2half_rn(qb);
        __half hka = __float2half_rn(ka);
        __half hkb = __float2half_rn(kb);
        g_qhi2[ob + d]      = hqa;
        g_qhi2[ob + d + 40] = hqb;
        g_qlo2[ob + d]      = __float2half_rn(qa - __half2float(hqa));
        g_qlo2[ob + d + 40] = __float2half_rn(qb - __half2float(hqb));
        g_khi2[ob + d]      = hka;
        g_khi2[ob + d + 40] = hkb;
        g_klo2[ob + d]      = __float2half_rn(ka - __half2float(hka));
        g_klo2[ob + d + 40] = __float2half_rn(kb - __half2float(hkb));
        return;
    }

    // V transpose: [v][p][h*80+d] -> g_vt [v][h][d][p]
    int b2 = bx - RVT_ROPE_BLKS;
    int p0 = (b2 & 63) * 32;
    int d0 = ((b2 >> 6) % 3) * 32;
    int vh = b2 / 192;
    int v = vh >> 4, h = vh & 15;
    int tx = tid & 31, ty = tid >> 5;
    #pragma unroll
    for (int r = ty; r < 32; r += 8) {
        int d = d0 + tx;
        if (d < HD)
            t[r][tx] = qkv[((size_t)v * PP + p0 + r) * N_QKV + 2 * DD + h * HD + d];
    }
    __syncthreads();
    #pragma unroll
    for (int r = ty; r < 32; r += 8) {
        int d = d0 + r;
        if (d < HD)
            g_vt[((size_t)vh * HD + d) * PP + p0 + tx] = __float2half_rn(t[tx][r]);
    }
}

// ---------------------------------------------------------------------------
// Tensor-core flash attention: QK 3-product (Q split, K split), PV fp16,
// fused split-fp16 epilogue. 2 CTAs/SM target (221 KiB smem total).
// ---------------------------------------------------------------------------
#define SQ 88
#define SV 72
#define ATTN_SMEM 113152

__global__ __launch_bounds__(256, 2) void attn_mma(const int* __restrict__ valid_lens)
{
    extern __shared__ char smem[];
    uint32_t sb = smem_u32(smem);
    const int tid = threadIdx.x;
    const int lane = tid & 31;
    const int wq = tid >> 5;
    const int q0 = blockIdx.x * 128;
    const int h = blockIdx.y;
    const int v = blockIdx.z;
    int L = valid_lens[v];
    if (L < 1) L = 1;

    const size_t hb = ((size_t)(v * HH + h)) * PP * HD;
    const __half* qhi = g_qhi2 + hb + (size_t)q0 * HD;
    const __half* qlo = g_qlo2 + hb + (size_t)q0 * HD;
    const __half* khi = g_khi2 + hb;
    const __half* klo = g_klo2 + hb;
    const __half* vtp = g_vt + hb;   // [80][2048]

    const uint32_t bQHI = sb;
    const uint32_t bQLO = sb + 22528u;
    const uint32_t bKHI = sb + 45056u;
    const uint32_t bKLO = sb + 67584u;
    const uint32_t bVT  = sb + 90112u;

    for (int i = tid; i < 1280; i += 256) {
        int r = i / 10, g = i % 10;
        uint32_t off = (uint32_t)(r * SQ + g * 8) * 2;
        CP_ASYNC16(bQHI + off, qhi + (size_t)r * HD + g * 8);
        CP_ASYNC16(bQLO + off, qlo + (size_t)r * HD + g * 8);
    }
    {
        for (int i = tid; i < 640; i += 256) {
            int r = i / 10, g = i % 10;
            uint32_t off = (uint32_t)(r * SQ + g * 8) * 2;
            CP_ASYNC16(bKHI + off, khi + (size_t)r * HD + g * 8);
            CP_ASYNC16(bKLO + off, klo + (size_t)r * HD + g * 8);
        }
        for (int i = tid; i < 640; i += 256) {
            int d = i / 8, g = i % 8;
            CP_ASYNC16(bVT + (uint32_t)(d * SV + g * 8) * 2, vtp + (size_t)d * PP + g * 8);
        }
    }
    CP_COMMIT();

    float m_lo = -1e30f, m_hi = -1e30f, l_lo = 0.f, l_hi = 0.f;
    float o[10][4];
    #pragma unroll
    for (int i = 0; i < 10; i++)
        #pragma unroll
        for (int j = 0; j < 4; j++) o[i][j] = 0.f;

    const int a_row = wq * 16 + (lane & 7) + ((lane >> 3) & 1) * 8;
    const int a_c16 = (lane >> 4);
    const int b_row = (lane & 7);
    const int b_c16 = (lane >> 3) & 1;
    const int gc = lane & 3;

    const int nkt = (L + 63) >> 6;
    for (int kt = 0; kt < nkt; kt++) {
        const int b = kt & 1;
        if (kt + 1 < nkt) {
            const int kn = (kt + 1) * 64;
            const uint32_t kh = bKHI + (uint32_t)(b ^ 1) * 11264u;
            const uint32_t kl = bKLO + (uint32_t)(b ^ 1) * 11264u;
            const uint32_t vb = bVT + (uint32_t)(b ^ 1) * 11520u;
            for (int i = tid; i < 640; i += 256) {
                int r = i / 10, g = i % 10;
                uint32_t off = (uint32_t)(r * SQ + g * 8) * 2;
                CP_ASYNC16(kh + off, khi + (size_t)(kn + r) * HD + g * 8);
                CP_ASYNC16(kl + off, klo + (size_t)(kn + r) * HD + g * 8);
            }
            for (int i = tid; i < 640; i += 256) {
                int d = i / 8, g = i % 8;
                CP_ASYNC16(vb + (uint32_t)(d * SV + g * 8) * 2,
                           vtp + (size_t)d * PP + kn + g * 8);
            }
            CP_COMMIT();
            CP_WAIT(1);
        } else {
            CP_WAIT(0);
        }
        __syncthreads();

        const uint32_t khb = bKHI + (uint32_t)b * 11264u;
        const uint32_t klb = bKLO + (uint32_t)b * 11264u;
        const uint32_t vtb = bVT + (uint32_t)b * 11520u;

        float s[8][4];
        #pragma unroll
        for (int nt = 0; nt < 8; nt++)
            #pragma unroll
            for (int j = 0; j < 4; j++) s[nt][j] = 0.f;

        #pragma unroll
        for (int kc = 0; kc < 5; kc++) {
            uint32_t qh[4], ql[4];
            uint32_t qoff = (uint32_t)(a_row * SQ + kc * 16 + a_c16 * 8) * 2;
            ldsm_x4(qh[0], qh[1], qh[2], qh[3], bQHI + qoff);
            ldsm_x4(ql[0], ql[1], ql[2], ql[3], bQLO + qoff);
            #pragma unroll
            for (int nt = 0; nt < 8; nt++) {
                uint32_t koff = (uint32_t)((nt * 8 + b_row) * SQ + kc * 16 + b_c16 * 8) * 2;
                uint32_t kh[2], kl[2];
                ldsm_x2(kh[0], kh[1], khb + koff);
                ldsm_x2(kl[0], kl[1], klb + koff);
                mma16816h(s[nt], qh, kh);
                mma16816h(s[nt], qh, kl);
                mma16816h(s[nt], ql, kh);
            }
        }

        const int k0 = kt * 64;
        if (k0 + 64 > L) {
            #pragma unroll
            for (int nt = 0; nt < 8; nt++) {
                int kb0 = k0 + nt * 8 + gc * 2;
                if (kb0 >= L)     { s[nt][0] = -1e30f; s[nt][2] = -1e30f; }
                if (kb0 + 1 >= L) { s[nt][1] = -1e30f; s[nt][3] = -1e30f; }
            }
        }

        float mt_lo = -1e30f, mt_hi = -1e30f;
        #pragma unroll
        for (int nt = 0; nt < 8; nt++) {
            mt_lo = fmaxf(mt_lo, fmaxf(s[nt][0], s[nt][1]));
            mt_hi = fmaxf(mt_hi, fmaxf(s[nt][2], s[nt][3]));
        }
        mt_lo = fmaxf(mt_lo, __shfl_xor_sync(0xffffffffu, mt_lo, 1));
        mt_lo = fmaxf(mt_lo, __shfl_xor_sync(0xffffffffu, mt_lo, 2));
        mt_hi = fmaxf(mt_hi, __shfl_xor_sync(0xffffffffu, mt_hi, 1));
        mt_hi = fmaxf(mt_hi, __shfl_xor_sync(0xffffffffu, mt_hi, 2));

        float mn_lo = fmaxf(m_lo, mt_lo), mn_hi = fmaxf(m_hi, mt_hi);
        float al = __expf(m_lo - mn_lo), ah = __expf(m_hi - mn_hi);
        m_lo = mn_lo; m_hi = mn_hi;

        float sum_lo = 0.f, sum_hi = 0.f;
        #pragma unroll
        for (int nt = 0; nt < 8; nt++) {
            s[nt][0] = __expf(s[nt][0] - mn_lo);
            s[nt][1] = __expf(s[nt][1] - mn_lo);
            s[nt][2] = __expf(s[nt][2] - mn_hi);
            s[nt][3] = __expf(s[nt][3] - mn_hi);
            sum_lo += s[nt][0] + s[nt][1];
            sum_hi += s[nt][2] + s[nt][3];
        }
        sum_lo += __shfl_xor_sync(0xffffffffu, sum_lo, 1);
        sum_lo += __shfl_xor_sync(0xffffffffu, sum_lo, 2);
        sum_hi += __shfl_xor_sync(0xffffffffu, sum_hi, 1);
        sum_hi += __shfl_xor_sync(0xffffffffu, sum_hi, 2);
        l_lo = l_lo * al + sum_lo;
        l_hi = l_hi * ah + sum_hi;

        #pragma unroll
        for (int nt = 0; nt < 10; nt++) {
            o[nt][0] *= al; o[nt][1] *= al;
            o[nt][2] *= ah; o[nt][3] *= ah;
        }

        uint32_t pa[4][4];
        #pragma unroll
        for (int kc = 0; kc < 4; kc++) {
            __half2 t0 = __floats2half2_rn(s[2 * kc][0], s[2 * kc][1]);
            __half2 t1 = __floats2half2_rn(s[2 * kc][2], s[2 * kc][3]);
            __half2 t2 = __floats2half2_rn(s[2 * kc + 1][0], s[2 * kc + 1][1]);
            __half2 t3 = __floats2half2_rn(s[2 * kc + 1][2], s[2 * kc + 1][3]);
            pa[kc][0] = *(uint32_t*)&t0;
            pa[kc][1] = *(uint32_t*)&t1;
            pa[kc][2] = *(uint32_t*)&t2;
            pa[kc][3] = *(uint32_t*)&t3;
        }

        #pragma unroll
        for (int nt = 0; nt < 10; nt++) {
            #pragma unroll
            for (int kc = 0; kc < 4; kc++) {
                uint32_t voff = (uint32_t)((nt * 8 + b_row) * SV + kc * 16 + b_c16 * 8) * 2;
                uint32_t vv[2];
                ldsm_x2(vv[0], vv[1], vtb + voff);
                mma16816h(o[nt], pa[kc], vv);
            }
        }
        __syncthreads();
    }

    // Epilogue: write split fp16 hi/lo directly (fused split for proj GEMM)
    float inv_lo = 1.f / l_lo, inv_hi = 1.f / l_hi;
    int row_lo = q0 + wq * 16 + (lane >> 2);
    #pragma unroll
    for (int nt = 0; nt < 10; nt++) {
        int col = h * HD + nt * 8 + gc * 2;
        size_t off0 = ((size_t)v * PP + row_lo) * DD + col;
        size_t off1 = ((size_t)v * PP + row_lo + 8) * DD + col;
        float v00 = o[nt][0] * inv_lo, v01 = o[nt][1] * inv_lo;
        float v10 = o[nt][2] * inv_hi, v11 = o[nt][3] * inv_hi;
        __half h00 = __float2half_rn(v00);
        __half h01 = __float2half_rn(v01);
        __half h10 = __float2half_rn(v10);
        __half h11 = __float2half_rn(v11);
        *(__half2*)(g_ahi + off0) = __half2(h00, h01);
        *(__half2*)(g_ahi + off1) = __half2(h10, h11);
        *(__half2*)(g_alo + off0) = __half2(
            __float2half_rn(v00 - __half2float(h00)),
            __float2half_rn(v01 - __half2float(h01)));
        *(__half2*)(g_alo + off1) = __half2(
            __float2half_rn(v10 - __half2float(h10)),
            __float2half_rn(v11 - __half2float(h11)));
    }
}

// ---------------------------------------------------------------------------
// Launch — 5 launches, attention in the 4th slot (ncu capture)
// ---------------------------------------------------------------------------
extern "C" void kernel_launch(void* const* d_in, const int* in_sizes, int n_in,
                              void* d_out, int out_size)
{
    const float* hs    = (const float*)d_in[0];
    const float* rope  = (const float*)d_in[1];
    const int*   vlens = (const int*)d_in[2];
    const float* wqkv  = (const float*)d_in[3];
    const float* bqkv  = (const float*)d_in[4];
    const float* wproj = (const float*)d_in[5];
    const float* bproj = (const float*)d_in[6];
    float* out = (float*)d_out;

    float* p_qkv;
    __half *p_ahi, *p_alo, *p_bh, *p_ph;
    cudaGetSymbolAddress((void**)&p_qkv, g_qkv);
    cudaGetSymbolAddress((void**)&p_ahi, g_ahi);
    cudaGetSymbolAddress((void**)&p_alo, g_alo);
    cudaGetSymbolAddress((void**)&p_bh,  g_bh);
    cudaGetSymbolAddress((void**)&p_ph,  g_ph);

    cudaFuncSetAttribute(gemm_qkv_hybrid,
                         cudaFuncAttributeMaxDynamicSharedMemorySize, GEMM_SMEM);
    cudaFuncSetAttribute(attn_mma,
                         cudaFuncAttributeMaxDynamicSharedMemorySize, ATTN_SMEM);

    // 1) Fused prep: split hs + transpose W_qkv + transpose W_proj
    prep_fused<<<PREP_BLOCKS, 256>>>(hs, wqkv, wproj);

    // 2) Hybrid QKV GEMM: QK cols 2-product, V cols 1-product
    gemm_qkv_hybrid<<<dim3(N_QKV / GTN, M_ROWS / GTM), 256, GEMM_SMEM>>>(
        p_ahi, p_alo, p_bh, bqkv, p_qkv, DD, N_QKV);

    // 3) Fused RoPE + V transpose
    rope_vt<<<RVT_BLOCKS, 256>>>(p_qkv, rope);

    // 4) Tensor-core flash attention  <-- ncu capture slot
    attn_mma<<<dim3(PP / 128, HH, VB), 256, ATTN_SMEM>>>(vlens);

    // 5) Output projection (all tiles take the 2-product path: n0 < 2560)
    gemm_qkv_hybrid<<<dim3(DD / GTN, M_ROWS / GTM), 256, GEMM_SMEM>>>(
        p_ahi, p_alo, p_ph, bproj, out, DD, DD);
}

// round 16
// speedup vs baseline: 1.4928x; 1.0094x over previous
#include <cuda_runtime.h>
#include <cuda_bf16.h>
#include <cuda_fp16.h>
#include <cstdint>

// Problem constants
#define VB 4
#define PP 2048
#define DD 1280
#define HH 16
#define HD 80
#define M_ROWS (VB * PP)     // 8192
#define N_QKV  (3 * DD)      // 3840
// QK scale with log2(e) folded in (softmax done in exp2 domain)
#define QK_SCALE_L2E 0.161290101f   // 80^-0.5 * log2(e)

// ---------------------------------------------------------------------------
// Scratch (static device globals — allocation-guard safe)
// ---------------------------------------------------------------------------
__device__ float g_qkv[M_ROWS * N_QKV];               // [8192, 3840] fp32
__device__ __align__(16) __half g_ahi[M_ROWS * DD];   // split A (hs, then attn out)
__device__ __align__(16) __half g_alo[M_ROWS * DD];
__device__ __align__(16) __half g_bh[N_QKV * DD];     // W_qkv^T [N,K] plain fp16
__device__ __align__(16) __half g_ph[DD * DD];        // W_proj^T [N,K] plain fp16
// fp16 attention operands
__device__ __align__(16) __half g_qhi2[VB * HH * PP * HD];  // [v][h][p][d], scaled
__device__ __align__(16) __half g_qlo2[VB * HH * PP * HD];
__device__ __align__(16) __half g_khi2[VB * HH * PP * HD];
__device__ __align__(16) __half g_klo2[VB * HH * PP * HD];
__device__ __align__(16) __half g_vt[VB * HH * HD * PP];    // [v][h][d][p]

// ---------------------------------------------------------------------------
// Helpers
// ---------------------------------------------------------------------------
__device__ __forceinline__ uint32_t smem_u32(const void* p) {
    uint32_t a;
    asm("{ .reg .u64 t; cvta.to.shared.u64 t, %1; cvt.u32.u64 %0, t; }" : "=r"(a) : "l"(p));
    return a;
}

#define CP_ASYNC16(dst, src) \
    asm volatile("cp.async.cg.shared.global [%0], [%1], 16;" :: "r"(dst), "l"(src))
#define CP_COMMIT() asm volatile("cp.async.commit_group;" ::: "memory")
#define CP_WAIT(n)  asm volatile("cp.async.wait_group %0;" :: "n"(n) : "memory")

__device__ __forceinline__ void ldsm_x4(uint32_t& r0, uint32_t& r1, uint32_t& r2, uint32_t& r3,
                                        uint32_t addr) {
    asm volatile("ldmatrix.sync.aligned.m8n8.x4.shared.b16 {%0,%1,%2,%3}, [%4];"
                 : "=r"(r0), "=r"(r1), "=r"(r2), "=r"(r3) : "r"(addr));
}
__device__ __forceinline__ void ldsm_x2(uint32_t& r0, uint32_t& r1, uint32_t addr) {
    asm volatile("ldmatrix.sync.aligned.m8n8.x2.shared.b16 {%0,%1}, [%2];"
                 : "=r"(r0), "=r"(r1) : "r"(addr));
}
__device__ __forceinline__ void mma16816h(float* c, const uint32_t* a, const uint32_t* b) {
    asm volatile("mma.sync.aligned.m16n8k16.row.col.f32.f16.f16.f32 "
                 "{%0,%1,%2,%3}, {%4,%5,%6,%7}, {%8,%9}, {%0,%1,%2,%3};"
                 : "+f"(c[0]), "+f"(c[1]), "+f"(c[2]), "+f"(c[3])
                 : "r"(a[0]), "r"(a[1]), "r"(a[2]), "r"(a[3]), "r"(b[0]), "r"(b[1]));
}

__device__ __forceinline__ uint32_t swz(uint32_t x) { return x ^ ((x >> 3) & 0x70u); }

// ---------------------------------------------------------------------------
// Fused prep: split hidden states (blocks [0,10240)),
// transpose W_qkv (blocks [10240,15040)), transpose W_proj (blocks [15040,16640))
// ---------------------------------------------------------------------------
#define PREP_SPLIT_BLKS 10240
#define PREP_TQKV_BLKS  4800
#define PREP_BLOCKS     (PREP_SPLIT_BLKS + PREP_TQKV_BLKS + 1600)

__global__ __launch_bounds__(256) void prep_fused(
    const float* __restrict__ hs,
    const float* __restrict__ wqkv, const float* __restrict__ wproj)
{
    __shared__ float t[32][33];
    int bx = blockIdx.x;
    int tid = threadIdx.x;

    if (bx < PREP_SPLIT_BLKS) {
        int i = (bx * 256 + tid) * 4;
        float4 v = *(const float4*)(hs + i);
        __half h0 = __float2half_rn(v.x);
        __half h1 = __float2half_rn(v.y);
        __half h2 = __float2half_rn(v.z);
        __half h3 = __float2half_rn(v.w);
        ((__half2*)(g_ahi + i))[0] = __half2(h0, h1);
        ((__half2*)(g_ahi + i))[1] = __half2(h2, h3);
        ((__half2*)(g_alo + i))[0] = __half2(
            __float2half_rn(v.x - __half2float(h0)),
            __float2half_rn(v.y - __half2float(h1)));
        ((__half2*)(g_alo + i))[1] = __half2(
            __float2half_rn(v.z - __half2float(h2)),
            __float2half_rn(v.w - __half2float(h3)));
        return;
    }

    const float* w;
    __half* wt;
    int N, n0, k0;
    int b2 = bx - PREP_SPLIT_BLKS;
    if (b2 < PREP_TQKV_BLKS) {
        w = wqkv; wt = g_bh; N = N_QKV;
        n0 = (b2 % 120) * 32; k0 = (b2 / 120) * 32;
    } else {
        int b3 = b2 - PREP_TQKV_BLKS;
        w = wproj; wt = g_ph; N = DD;
        n0 = (b3 % 40) * 32; k0 = (b3 / 40) * 32;
    }
    int tx = tid & 31, ty = tid >> 5;
    #pragma unroll
    for (int r = ty; r < 32; r += 8)
        t[r][tx] = w[(size_t)(k0 + r) * N + n0 + tx];
    __syncthreads();
    #pragma unroll
    for (int r = ty; r < 32; r += 8)
        wt[(size_t)(n0 + r) * DD + k0 + tx] = __float2half_rn(t[tx][r]);
}

// ---------------------------------------------------------------------------
// Hybrid GEMM: C = (Ahi [+ Alo if col<2560]) @ B^T + bias, row-stride ldc.
// ---------------------------------------------------------------------------
#define GTM 128
#define GTN 128
#define GKC 64
#define MAT_B 16384u
#define STAGE_B (3u * MAT_B)      // Ahi | Alo | B = 48 KB
#define GEMM_SMEM (2 * STAGE_B)   // 98304 (2 stages -> 2 CTAs/SM)
#define N_LO_SPLIT (2 * DD)

__device__ __forceinline__ void load_chunk_h(
    uint32_t sb, int buf,
    const __half* a0, const __half* a1, const __half* b0,
    int k0, int tid, int K, bool need_lo)
{
    const __half* srcs[3] = {a0 + k0, a1 + k0, b0 + k0};
    uint32_t stage = sb + (uint32_t)buf * STAGE_B;
    #pragma unroll
    for (int mat = 0; mat < 3; mat++) {
        if (mat == 1 && !need_lo) continue;
        uint32_t tbase = stage + (uint32_t)mat * MAT_B;
        const __half* s = srcs[mat];
        #pragma unroll
        for (int i = 0; i < 4; i++) {
            int g = tid + i * 256;
            int row = g >> 3;
            int c16 = g & 7;
            uint32_t boff = (uint32_t)(row * 128 + c16 * 16);
            CP_ASYNC16(tbase + swz(boff), s + (size_t)row * K + c16 * 8);
        }
    }
}

__global__ __launch_bounds__(256, 2) void gemm_qkv_hybrid(
    const __half* __restrict__ Ahi, const __half* __restrict__ Alo,
    const __half* __restrict__ B,
    const float* __restrict__ bias, float* __restrict__ C, int K, int ldc)
{
    extern __shared__ char smem[];
    uint32_t sb = smem_u32(smem);
    const int tid = threadIdx.x;
    const int lane = tid & 31;
    const int wid = tid >> 5;
    const int wm = wid >> 2;
    const int wn = wid & 3;
    const int m0 = blockIdx.y * GTM;
    const int n0 = blockIdx.x * GTN;
    const bool lo = (n0 < N_LO_SPLIT);

    const __half* a0 = Ahi + (size_t)m0 * K;
    const __half* a1 = Alo + (size_t)m0 * K;
    const __half* b0 = B + (size_t)n0 * K;

    float acc[4][4][4];
    #pragma unroll
    for (int i = 0; i < 4; i++)
        #pragma unroll
        for (int j = 0; j < 4; j++)
            #pragma unroll
            for (int t = 0; t < 4; t++) acc[i][j][t] = 0.f;

    const int a_row_l = (lane & 7) + ((lane >> 3) & 1) * 8;
    const int a_c16_l = (lane >> 4);
    const int b_row_l = (lane & 7);
    const int b_c16_l = ((lane >> 3) & 1);

    const int nch = K / GKC;

    load_chunk_h(sb, 0, a0, a1, b0, 0, tid, K, lo);
    CP_COMMIT();

    for (int it = 0; it < nch; it++) {
        const int b = it & 1;
        if (it + 1 < nch) {
            load_chunk_h(sb, b ^ 1, a0, a1, b0, (it + 1) * GKC, tid, K, lo);
            CP_COMMIT();
            CP_WAIT(1);
        } else {
            CP_WAIT(0);
        }
        __syncthreads();

        uint32_t stage = sb + (uint32_t)b * STAGE_B;
        uint32_t sAhi = stage;
        uint32_t sAlo = stage + MAT_B;
        uint32_t sB   = stage + 2 * MAT_B;

        #pragma unroll
        for (int ks = 0; ks < 4; ks++) {
            uint32_t bb[4][2];
            #pragma unroll
            for (int nt = 0; nt < 4; nt++) {
                uint32_t boff = (uint32_t)((wn * 32 + nt * 8 + b_row_l) * 128 +
                                           (ks * 2 + b_c16_l) * 16);
                uint32_t so = swz(boff);
                ldsm_x2(bb[nt][0], bb[nt][1], sB + so);
            }
            #pragma unroll
            for (int mt = 0; mt < 4; mt++) {
                uint32_t boff = (uint32_t)((wm * 64 + mt * 16 + a_row_l) * 128 +
                                           (ks * 2 + a_c16_l) * 16);
                uint32_t so = swz(boff);
                uint32_t ahi[4];
                ldsm_x4(ahi[0], ahi[1], ahi[2], ahi[3], sAhi + so);
                #pragma unroll
                for (int nt = 0; nt < 4; nt++)
                    mma16816h(acc[mt][nt], ahi, bb[nt]);
                if (lo) {
                    uint32_t alo[4];
                    ldsm_x4(alo[0], alo[1], alo[2], alo[3], sAlo + so);
                    #pragma unroll
                    for (int nt = 0; nt < 4; nt++)
                        mma16816h(acc[mt][nt], alo, bb[nt]);
                }
            }
        }
        __syncthreads();
    }

    const int r_base = m0 + wm * 64 + (lane >> 2);
    const int c_base = n0 + wn * 32 + (lane & 3) * 2;
    #pragma unroll
    for (int mt = 0; mt < 4; mt++) {
        #pragma unroll
        for (int nt = 0; nt < 4; nt++) {
            int col = c_base + nt * 8;
            float bx = bias[col], by = bias[col + 1];
            int r0 = r_base + mt * 16;
            float2 v0 = {acc[mt][nt][0] + bx, acc[mt][nt][1] + by};
            float2 v1 = {acc[mt][nt][2] + bx, acc[mt][nt][3] + by};
            *(float2*)(C + (size_t)r0 * ldc + col) = v0;
            *(float2*)(C + (size_t)(r0 + 8) * ldc + col) = v1;
        }
    }
}

// ---------------------------------------------------------------------------
// Fused RoPE (blocks [0,20480)) + V transpose (blocks [20480,32768))
// Q scale now folds log2(e) for exp2-domain softmax.
// ---------------------------------------------------------------------------
#define RVT_ROPE_BLKS 20480
#define RVT_BLOCKS (RVT_ROPE_BLKS + 12288)

__global__ __launch_bounds__(256) void rope_vt(
    const float* __restrict__ qkv, const float* __restrict__ rope)
{
    __shared__ float t[32][33];
    int bx = blockIdx.x;
    int tid = threadIdx.x;

    if (bx < RVT_ROPE_BLKS) {
        int idx = bx * 256 + tid;
        int d = idx % 40;
        int h = (idx / 40) % HH;
        int p = (idx / (40 * HH)) % PP;
        int v = idx / (40 * HH * PP);

        size_t row = (size_t)v * PP + p;
        const float* qr = qkv + row * N_QKV + h * HD;
        const float* kr = qr + DD;
        const float* rp = rope + row * (2 * HD);

        float c0 = rp[d],      c1 = rp[d + 40];
        float s0 = rp[HD + d], s1 = rp[HD + d + 40];
        float q0 = qr[d], q1 = qr[d + 40];
        float k0 = kr[d], k1 = kr[d + 40];

        float qa = (q0 * c0 - q1 * s0) * QK_SCALE_L2E;
        float qb = (q1 * c1 + q0 * s1) * QK_SCALE_L2E;
        float ka = k0 * c0 - k1 * s0;
        float kb = k1 * c1 + k0 * s1;

        size_t ob = (((size_t)v * HH + h) * PP + p) * HD;
        __half hqa = __float2half_rn(qa);
        __half hqb = __float2half_rn(qb);
        __half hka = __float2half_rn(ka);
        __half hkb = __float2half_rn(kb);
        g_qhi2[ob + d]      = hqa;
        g_qhi2[ob + d + 40] = hqb;
        g_qlo2[ob + d]      = __float2half_rn(qa - __half2float(hqa));
        g_qlo2[ob + d + 40] = __float2half_rn(qb - __half2float(hqb));
        g_khi2[ob + d]      = hka;
        g_khi2[ob + d + 40] = hkb;
        g_klo2[ob + d]      = __float2half_rn(ka - __half2float(hka));
        g_klo2[ob + d + 40] = __float2half_rn(kb - __half2float(hkb));
        return;
    }

    int b2 = bx - RVT_ROPE_BLKS;
    int p0 = (b2 & 63) * 32;
    int d0 = ((b2 >> 6) % 3) * 32;
    int vh = b2 / 192;
    int v = vh >> 4, h = vh & 15;
    int tx = tid & 31, ty = tid >> 5;
    #pragma unroll
    for (int r = ty; r < 32; r += 8) {
        int d = d0 + tx;
        if (d < HD)
            t[r][tx] = qkv[((size_t)v * PP + p0 + r) * N_QKV + 2 * DD + h * HD + d];
    }
    __syncthreads();
    #pragma unroll
    for (int r = ty; r < 32; r += 8) {
        int d = d0 + r;
        if (d < HD)
            g_vt[((size_t)vh * HD + d) * PP + p0 + tx] = __float2half_rn(t[tx][r]);
    }
}

// ---------------------------------------------------------------------------
// Tensor-core flash attention. QK 3-product, PV fp16, exp2-domain softmax.
// All K/V fragment loads use ldsm_x4 (half the LDSM instruction count).
// ---------------------------------------------------------------------------
#define SQ 88
#define SV 72
#define ATTN_SMEM 113152

__global__ __launch_bounds__(256, 2) void attn_mma(const int* __restrict__ valid_lens)
{
    extern __shared__ char smem[];
    uint32_t sb = smem_u32(smem);
    const int tid = threadIdx.x;
    const int lane = tid & 31;
    const int wq = tid >> 5;
    const int q0 = blockIdx.x * 128;
    const int h = blockIdx.y;
    const int v = blockIdx.z;
    int L = valid_lens[v];
    if (L < 1) L = 1;

    const size_t hb = ((size_t)(v * HH + h)) * PP * HD;
    const __half* qhi = g_qhi2 + hb + (size_t)q0 * HD;
    const __half* qlo = g_qlo2 + hb + (size_t)q0 * HD;
    const __half* khi = g_khi2 + hb;
    const __half* klo = g_klo2 + hb;
    const __half* vtp = g_vt + hb;   // [80][2048]

    const uint32_t bQHI = sb;
    const uint32_t bQLO = sb + 22528u;
    const uint32_t bKHI = sb + 45056u;
    const uint32_t bKLO = sb + 67584u;
    const uint32_t bVT  = sb + 90112u;

    for (int i = tid; i < 1280; i += 256) {
        int r = i / 10, g = i % 10;
        uint32_t off = (uint32_t)(r * SQ + g * 8) * 2;
        CP_ASYNC16(bQHI + off, qhi + (size_t)r * HD + g * 8);
        CP_ASYNC16(bQLO + off, qlo + (size_t)r * HD + g * 8);
    }
    {
        for (int i = tid; i < 640; i += 256) {
            int r = i / 10, g = i % 10;
            uint32_t off = (uint32_t)(r * SQ + g * 8) * 2;
            CP_ASYNC16(bKHI + off, khi + (size_t)r * HD + g * 8);
            CP_ASYNC16(bKLO + off, klo + (size_t)r * HD + g * 8);
        }
        for (int i = tid; i < 640; i += 256) {
            int d = i / 8, g = i % 8;
            CP_ASYNC16(bVT + (uint32_t)(d * SV + g * 8) * 2, vtp + (size_t)d * PP + g * 8);
        }
    }
    CP_COMMIT();

    float m_lo = -1e30f, m_hi = -1e30f, l_lo = 0.f, l_hi = 0.f;
    float o[10][4];
    #pragma unroll
    for (int i = 0; i < 10; i++)
        #pragma unroll
        for (int j = 0; j < 4; j++) o[i][j] = 0.f;

    // Q fragment addressing (x4, A-operand)
    const int a_row = wq * 16 + (lane & 7) + ((lane >> 3) & 1) * 8;
    const int a_c16 = (lane >> 4);
    // K fragment addressing (x4 over nt-pairs): lanes 0-7 -> nt even c16 0,
    // 8-15 -> nt even c16 1, 16-23 -> nt odd c16 0, 24-31 -> nt odd c16 1
    const int k_row_x4 = ((lane >> 4) << 3) + (lane & 7);
    const int k_c16_x4 = (lane >> 3) & 1;
    // V fragment addressing (x4 over kc-pairs): lanes 0-15 -> kc, 16-31 -> kc+1
    const int v_kc_sel = (lane >> 4);
    const int b_row = (lane & 7);
    const int gc = lane & 3;

    const int nkt = (L + 63) >> 6;
    for (int kt = 0; kt < nkt; kt++) {
        const int b = kt & 1;
        if (kt + 1 < nkt) {
            const int kn = (kt + 1) * 64;
            const uint32_t kh = bKHI + (uint32_t)(b ^ 1) * 11264u;
            const uint32_t kl = bKLO + (uint32_t)(b ^ 1) * 11264u;
            const uint32_t vb = bVT + (uint32_t)(b ^ 1) * 11520u;
            for (int i = tid; i < 640; i += 256) {
                int r = i / 10, g = i % 10;
                uint32_t off = (uint32_t)(r * SQ + g * 8) * 2;
                CP_ASYNC16(kh + off, khi + (size_t)(kn + r) * HD + g * 8);
                CP_ASYNC16(kl + off, klo + (size_t)(kn + r) * HD + g * 8);
            }
            for (int i = tid; i < 640; i += 256) {
                int d = i / 8, g = i % 8;
                CP_ASYNC16(vb + (uint32_t)(d * SV + g * 8) * 2,
                           vtp + (size_t)d * PP + kn + g * 8);
            }
            CP_COMMIT();
            CP_WAIT(1);
        } else {
            CP_WAIT(0);
        }
        __syncthreads();

        const uint32_t khb = bKHI + (uint32_t)b * 11264u;
        const uint32_t klb = bKLO + (uint32_t)b * 11264u;
        const uint32_t vtb = bVT + (uint32_t)b * 11520u;

        float s[8][4];
        #pragma unroll
        for (int nt = 0; nt < 8; nt++)
            #pragma unroll
            for (int j = 0; j < 4; j++) s[nt][j] = 0.f;

        #pragma unroll
        for (int kc = 0; kc < 5; kc++) {
            uint32_t qh[4], ql[4];
            uint32_t qoff = (uint32_t)(a_row * SQ + kc * 16 + a_c16 * 8) * 2;
            ldsm_x4(qh[0], qh[1], qh[2], qh[3], bQHI + qoff);
            ldsm_x4(ql[0], ql[1], ql[2], ql[3], bQLO + qoff);
            #pragma unroll
            for (int ntp = 0; ntp < 4; ntp++) {
                uint32_t koff = (uint32_t)((ntp * 16 + k_row_x4) * SQ +
                                           kc * 16 + k_c16_x4 * 8) * 2;
                uint32_t kh[4], kl[4];
                ldsm_x4(kh[0], kh[1], kh[2], kh[3], khb + koff);
                ldsm_x4(kl[0], kl[1], kl[2], kl[3], klb + koff);
                mma16816h(s[2 * ntp],     qh, kh);
                mma16816h(s[2 * ntp],     qh, kl);
                mma16816h(s[2 * ntp],     ql, kh);
                mma16816h(s[2 * ntp + 1], qh, kh + 2);
                mma16816h(s[2 * ntp + 1], qh, kl + 2);
                mma16816h(s[2 * ntp + 1], ql, kh + 2);
            }
        }

        const int k0 = kt * 64;
        if (k0 + 64 > L) {
            #pragma unroll
            for (int nt = 0; nt < 8; nt++) {
                int kb0 = k0 + nt * 8 + gc * 2;
                if (kb0 >= L)     { s[nt][0] = -1e30f; s[nt][2] = -1e30f; }
                if (kb0 + 1 >= L) { s[nt][1] = -1e30f; s[nt][3] = -1e30f; }
            }
        }

        float mt_lo = -1e30f, mt_hi = -1e30f;
        #pragma unroll
        for (int nt = 0; nt < 8; nt++) {
            mt_lo = fmaxf(mt_lo, fmaxf(s[nt][0], s[nt][1]));
            mt_hi = fmaxf(mt_hi, fmaxf(s[nt][2], s[nt][3]));
        }
        mt_lo = fmaxf(mt_lo, __shfl_xor_sync(0xffffffffu, mt_lo, 1));
        mt_lo = fmaxf(mt_lo, __shfl_xor_sync(0xffffffffu, mt_lo, 2));
        mt_hi = fmaxf(mt_hi, __shfl_xor_sync(0xffffffffu, mt_hi, 1));
        mt_hi = fmaxf(mt_hi, __shfl_xor_sync(0xffffffffu, mt_hi, 2));

        float mn_lo = fmaxf(m_lo, mt_lo), mn_hi = fmaxf(m_hi, mt_hi);
        float al = exp2f(m_lo - mn_lo), ah = exp2f(m_hi - mn_hi);
        m_lo = mn_lo; m_hi = mn_hi;

        float sum_lo = 0.f, sum_hi = 0.f;
        #pragma unroll
        for (int nt = 0; nt < 8; nt++) {
            s[nt][0] = exp2f(s[nt][0] - mn_lo);
            s[nt][1] = exp2f(s[nt][1] - mn_lo);
            s[nt][2] = exp2f(s[nt][2] - mn_hi);
            s[nt][3] = exp2f(s[nt][3] - mn_hi);
            sum_lo += s[nt][0] + s[nt][1];
            sum_hi += s[nt][2] + s[nt][3];
        }
        sum_lo += __shfl_xor_sync(0xffffffffu, sum_lo, 1);
        sum_lo += __shfl_xor_sync(0xffffffffu, sum_lo, 2);
        sum_hi += __shfl_xor_sync(0xffffffffu, sum_hi, 1);
        sum_hi += __shfl_xor_sync(0xffffffffu, sum_hi, 2);
        l_lo = l_lo * al + sum_lo;
        l_hi = l_hi * ah + sum_hi;

        #pragma unroll
        for (int nt = 0; nt < 10; nt++) {
            o[nt][0] *= al; o[nt][1] *= al;
            o[nt][2] *= ah; o[nt][3] *= ah;
        }

        uint32_t pa[4][4];
        #pragma unroll
        for (int kc = 0; kc < 4; kc++) {
            __half2 t0 = __floats2half2_rn(s[2 * kc][0], s[2 * kc][1]);
            __half2 t1 = __floats2half2_rn(s[2 * kc][2], s[2 * kc][3]);
            __half2 t2 = __floats2half2_rn(s[2 * kc + 1][0], s[2 * kc + 1][1]);
            __half2 t3 = __floats2half2_rn(s[2 * kc + 1][2], s[2 * kc + 1][3]);
            pa[kc][0] = *(uint32_t*)&t0;
            pa[kc][1] = *(uint32_t*)&t1;
            pa[kc][2] = *(uint32_t*)&t2;
            pa[kc][3] = *(uint32_t*)&t3;
        }

        #pragma unroll
        for (int nt = 0; nt < 10; nt++) {
            #pragma unroll
            for (int kc = 0; kc < 4; kc += 2) {
                uint32_t voff = (uint32_t)((nt * 8 + b_row) * SV +
                                           (kc + v_kc_sel) * 16 + k_c16_x4 * 8) * 2;
                uint32_t vv[4];
                ldsm_x4(vv[0], vv[1], vv[2], vv[3], vtb + voff);
                mma16816h(o[nt], pa[kc], vv);
                mma16816h(o[nt], pa[kc + 1], vv + 2);
            }
        }
        __syncthreads();
    }

    // Epilogue: write split fp16 hi/lo directly (fused split for proj GEMM)
    float inv_lo = 1.f / l_lo, inv_hi = 1.f / l_hi;
    int row_lo = q0 + wq * 16 + (lane >> 2);
    #pragma unroll
    for (int nt = 0; nt < 10; nt++) {
        int col = h * HD + nt * 8 + gc * 2;
        size_t off0 = ((size_t)v * PP + row_lo) * DD + col;
        size_t off1 = ((size_t)v * PP + row_lo + 8) * DD + col;
        float v00 = o[nt][0] * inv_lo, v01 = o[nt][1] * inv_lo;
        float v10 = o[nt][2] * inv_hi, v11 = o[nt][3] * inv_hi;
        __half h00 = __float2half_rn(v00);
        __half h01 = __float2half_rn(v01);
        __half h10 = __float2half_rn(v10);
        __half h11 = __float2half_rn(v11);
        *(__half2*)(g_ahi + off0) = __half2(h00, h01);
        *(__half2*)(g_ahi + off1) = __half2(h10, h11);
        *(__half2*)(g_alo + off0) = __half2(
            __float2half_rn(v00 - __half2float(h00)),
            __float2half_rn(v01 - __half2float(h01)));
        *(__half2*)(g_alo + off1) = __half2(
            __float2half_rn(v10 - __half2float(h10)),
            __float2half_rn(v11 - __half2float(h11)));
    }
}

// ---------------------------------------------------------------------------
// Launch — 5 launches, attention in the 4th slot (ncu capture)
// ---------------------------------------------------------------------------
extern "C" void kernel_launch(void* const* d_in, const int* in_sizes, int n_in,
                              void* d_out, int out_size)
{
    const float* hs    = (const float*)d_in[0];
    const float* rope  = (const float*)d_in[1];
    const int*   vlens = (const int*)d_in[2];
    const float* wqkv  = (const float*)d_in[3];
    const float* bqkv  = (const float*)d_in[4];
    const float* wproj = (const float*)d_in[5];
    const float* bproj = (const float*)d_in[6];
    float* out = (float*)d_out;

    float* p_qkv;
    __half *p_ahi, *p_alo, *p_bh, *p_ph;
    cudaGetSymbolAddress((void**)&p_qkv, g_qkv);
    cudaGetSymbolAddress((void**)&p_ahi, g_ahi);
    cudaGetSymbolAddress((void**)&p_alo, g_alo);
    cudaGetSymbolAddress((void**)&p_bh,  g_bh);
    cudaGetSymbolAddress((void**)&p_ph,  g_ph);

    cudaFuncSetAttribute(gemm_qkv_hybrid,
                         cudaFuncAttributeMaxDynamicSharedMemorySize, GEMM_SMEM);
    cudaFuncSetAttribute(attn_mma,
                         cudaFuncAttributeMaxDynamicSharedMemorySize, ATTN_SMEM);

    // 1) Fused prep: split hs + transpose W_qkv + transpose W_proj
    prep_fused<<<PREP_BLOCKS, 256>>>(hs, wqkv, wproj);

    // 2) Hybrid QKV GEMM: QK cols 2-product, V cols 1-product
    gemm_qkv_hybrid<<<dim3(N_QKV / GTN, M_ROWS / GTM), 256, GEMM_SMEM>>>(
        p_ahi, p_alo, p_bh, bqkv, p_qkv, DD, N_QKV);

    // 3) Fused RoPE + V transpose
    rope_vt<<<RVT_BLOCKS, 256>>>(p_qkv, rope);

    // 4) Tensor-core flash attention  <-- ncu capture slot
    attn_mma<<<dim3(PP / 128, HH, VB), 256, ATTN_SMEM>>>(vlens);

    // 5) Output projection (all tiles take the 2-product path: n0 < 2560)
    gemm_qkv_hybrid<<<dim3(DD / GTN, M_ROWS / GTM), 256, GEMM_SMEM>>>(
        p_ahi, p_alo, p_ph, bproj, out, DD, DD);
}